// round 1
// baseline (speedup 1.0000x reference)
#include <cuda_runtime.h>
#include <math.h>

// ---------------- problem constants ----------------
#define S_LEN   2048
#define BATCH   2
#define HIDDEN  2048
#define NH      16
#define QLORA   1536
#define KVLORA  512
#define DNOPE   128
#define DROPE   64
#define DV      128
#define DQ      192           // DNOPE + DROPE
#define NROWS   (BATCH*S_LEN) // 4096
#define CKV_LD  (KVLORA + DROPE) // 576
#define KV_LD   (NH*(DNOPE+DV))  // 4096
#define Q_LD    (NH*DQ)          // 3072
#define ATTN_LD (NH*DV)          // 2048

// ---------------- scratch (device globals; no runtime alloc) ----------------
__device__ float g_qa  [(size_t)NROWS*QLORA];   // 25 MB
__device__ float g_q   [(size_t)NROWS*Q_LD];    // 50 MB
__device__ float g_ckv [(size_t)NROWS*CKV_LD];  // 9.4 MB
__device__ float g_kv  [(size_t)NROWS*KV_LD];   // 67 MB
__device__ float g_attn[(size_t)NROWS*ATTN_LD]; // 33 MB

// ---------------- generic tiled SGEMM: C[M,N] = A[M,K] * B[K,N] ----------------
// 128x128 block tile, BK=8, 256 threads, 8x8 per thread.
__global__ __launch_bounds__(256) void sgemm_kernel(
    const float* __restrict__ A, const float* __restrict__ B, float* __restrict__ C,
    int M, int N, int K, int lda, int ldb, int ldc)
{
    __shared__ float As[8][128];
    __shared__ float Bs[8][132];  // +4 pad

    const int tid = threadIdx.x;
    const int bm = blockIdx.y, bn = blockIdx.x;
    const int ty = tid >> 4, tx = tid & 15;

    float acc[8][8];
#pragma unroll
    for (int i = 0; i < 8; i++)
#pragma unroll
        for (int j = 0; j < 8; j++) acc[i][j] = 0.0f;

    const int arow  = bm*128 + (tid >> 1);
    const int acol0 = (tid & 1) * 4;
    const int brow0 = tid >> 5;
    const int bcol  = bn*128 + (tid & 31) * 4;
    const bool aok = arow < M;
    const bool bok = bcol < N;
    const float* Aptr = A + (size_t)arow*lda + acol0;
    const float* Bptr = B + (size_t)brow0*ldb + bcol;

    for (int kt = 0; kt < K; kt += 8) {
        float4 av = aok ? *(const float4*)(Aptr + kt) : make_float4(0.f,0.f,0.f,0.f);
        float4 bv = bok ? *(const float4*)(Bptr + (size_t)kt*ldb) : make_float4(0.f,0.f,0.f,0.f);
        __syncthreads();
        As[acol0+0][tid>>1] = av.x;
        As[acol0+1][tid>>1] = av.y;
        As[acol0+2][tid>>1] = av.z;
        As[acol0+3][tid>>1] = av.w;
        *(float4*)&Bs[brow0][(tid & 31)*4] = bv;
        __syncthreads();
#pragma unroll
        for (int k = 0; k < 8; k++) {
            float4 a0 = *(float4*)&As[k][ty*8];
            float4 a1 = *(float4*)&As[k][ty*8+4];
            float4 b0 = *(float4*)&Bs[k][tx*8];
            float4 b1 = *(float4*)&Bs[k][tx*8+4];
            float ar[8] = {a0.x,a0.y,a0.z,a0.w,a1.x,a1.y,a1.z,a1.w};
            float br[8] = {b0.x,b0.y,b0.z,b0.w,b1.x,b1.y,b1.z,b1.w};
#pragma unroll
            for (int i = 0; i < 8; i++)
#pragma unroll
                for (int j = 0; j < 8; j++)
                    acc[i][j] = fmaf(ar[i], br[j], acc[i][j]);
        }
    }

    const int crow0 = bm*128 + ty*8;
    const int ccol0 = bn*128 + tx*8;
#pragma unroll
    for (int i = 0; i < 8; i++) {
        int r = crow0 + i;
        if (r >= M) continue;
        float* cp = C + (size_t)r*ldc;
        if (ccol0 < N)
            *(float4*)&cp[ccol0]   = make_float4(acc[i][0],acc[i][1],acc[i][2],acc[i][3]);
        if (ccol0 + 4 < N)
            *(float4*)&cp[ccol0+4] = make_float4(acc[i][4],acc[i][5],acc[i][6],acc[i][7]);
    }
}

// ---------------- row-wise RMSNorm (in place) ----------------
__global__ void rmsnorm_kernel(float* __restrict__ x, const float* __restrict__ w,
                               int W, int ld)
{
    __shared__ float red[256];
    const int row = blockIdx.x;
    float* p = x + (size_t)row*ld;
    float ss = 0.f;
    for (int c = threadIdx.x; c < W; c += 256) { float v = p[c]; ss += v*v; }
    red[threadIdx.x] = ss;
    __syncthreads();
    for (int s = 128; s; s >>= 1) {
        if (threadIdx.x < s) red[threadIdx.x] += red[threadIdx.x + s];
        __syncthreads();
    }
    const float scale = rsqrtf(red[0] / (float)W + 1e-6f);
    for (int c = threadIdx.x; c < W; c += 256) p[c] = p[c] * scale * w[c];
}

// ---------------- RoPE (DeepSeek interleaved permute + rotate-half), in place ----------------
// x'[i]=x[2i], x'[32+i]=x[2i+1];  out[i]=x'[i]*c - x'[32+i]*s ; out[32+i]=x'[32+i]*c + x'[i]*s
__device__ __forceinline__ void rope_pair(float* base, int t, int lane)
{
    float xe = base[2*lane], xo = base[2*lane + 1];
    float inv = 1.0f / powf(10000.0f, (2.0f * (float)lane) / 64.0f);
    float ph = (float)t * inv;
    float sn, cs;
    sincosf(ph, &sn, &cs);
    __syncwarp();
    base[lane]      = xe*cs - xo*sn;
    base[lane + 32] = xo*cs + xe*sn;
}

__global__ void rope_k_kernel(float* __restrict__ ckv)
{
    const int row = blockIdx.x;
    rope_pair(ckv + (size_t)row*CKV_LD + KVLORA, row % S_LEN, threadIdx.x & 31);
}

__global__ void rope_q_kernel(float* __restrict__ q)
{
    const int row = blockIdx.x;
    const int h = threadIdx.x >> 5, lane = threadIdx.x & 31;
    rope_pair(q + (size_t)row*Q_LD + h*DQ + DNOPE, row % S_LEN, lane);
}

// ---------------- causal flash attention ----------------
// Br=Bc=64, 256 threads. Q: [NROWS, NH*192] (rope applied). K = [kv nope | ckv pe].
// V = kv cols 128..255. Output attn: [NROWS, NH*128].
#define QPAD 196
#define KPAD 196
#define VPAD 132
#define PPAD 68
#define FLASH_SMEM ((64*(QPAD+KPAD+VPAD+PPAD))*4)

__global__ __launch_bounds__(256) void flash_kernel(
    const float* __restrict__ q, const float* __restrict__ kv,
    const float* __restrict__ ckv, float* __restrict__ attn)
{
    extern __shared__ float smf[];
    float* Qs = smf;
    float* Ks = Qs + 64*QPAD;
    float* Vs = Ks + 64*KPAD;
    float* Ps = Vs + 64*VPAD;

    const int tid = threadIdx.x;
    const int qt = blockIdx.x;
    const int b  = blockIdx.y >> 4;
    const int h  = blockIdx.y & 15;
    const int ty = tid >> 4, tx = tid & 15;
    const float scale = 0.07216878364870323f; // 1/sqrt(192)

    const int qrow0 = b*S_LEN + qt*64;
    // load Q tile (64 x 192)
#pragma unroll
    for (int t = 0; t < 12; t++) {
        int idx = tid + t*256;
        int r = idx / 48, c4 = idx % 48;
        float4 v = *(const float4*)(q + (size_t)(qrow0 + r)*Q_LD + h*DQ + c4*4);
        *(float4*)&Qs[r*QPAD + c4*4] = v;
    }

    float m_i[4], l_i[4], o[4][8];
#pragma unroll
    for (int i = 0; i < 4; i++) {
        m_i[i] = -INFINITY; l_i[i] = 0.f;
#pragma unroll
        for (int j = 0; j < 8; j++) o[i][j] = 0.f;
    }

    for (int j = 0; j <= qt; j++) {
        __syncthreads(); // protect previous iteration's smem reads
        const int krow0 = b*S_LEN + j*64;
        // K tile: cols 0..127 from kv (nope), 128..191 from ckv (roped pe)
#pragma unroll
        for (int t = 0; t < 12; t++) {
            int idx = tid + t*256;
            int r = idx / 48, col = (idx % 48) * 4;
            float4 v;
            if (col < DNOPE)
                v = *(const float4*)(kv + (size_t)(krow0 + r)*KV_LD + h*256 + col);
            else
                v = *(const float4*)(ckv + (size_t)(krow0 + r)*CKV_LD + KVLORA + (col - DNOPE));
            *(float4*)&Ks[r*KPAD + col] = v;
        }
        // V tile
#pragma unroll
        for (int t = 0; t < 8; t++) {
            int idx = tid + t*256;
            int r = idx >> 5, col = (idx & 31) * 4;
            float4 v = *(const float4*)(kv + (size_t)(krow0 + r)*KV_LD + h*256 + DNOPE + col);
            *(float4*)&Vs[r*VPAD + col] = v;
        }
        __syncthreads();

        // scores S = Q K^T  (4x4 per thread)
        float sc[4][4];
#pragma unroll
        for (int i = 0; i < 4; i++)
#pragma unroll
            for (int jj = 0; jj < 4; jj++) sc[i][jj] = 0.f;

        for (int c4 = 0; c4 < 48; c4++) {
            float4 qv[4], kf[4];
#pragma unroll
            for (int i = 0; i < 4; i++) qv[i] = *(float4*)&Qs[(ty*4+i)*QPAD + c4*4];
#pragma unroll
            for (int jj = 0; jj < 4; jj++) kf[jj] = *(float4*)&Ks[(tx*4+jj)*KPAD + c4*4];
#pragma unroll
            for (int i = 0; i < 4; i++)
#pragma unroll
                for (int jj = 0; jj < 4; jj++) {
                    sc[i][jj] = fmaf(qv[i].x, kf[jj].x, sc[i][jj]);
                    sc[i][jj] = fmaf(qv[i].y, kf[jj].y, sc[i][jj]);
                    sc[i][jj] = fmaf(qv[i].z, kf[jj].z, sc[i][jj]);
                    sc[i][jj] = fmaf(qv[i].w, kf[jj].w, sc[i][jj]);
                }
        }

        // scale + causal mask (sequence positions)
        const int qs0 = qt*64 + ty*4, ks0 = j*64 + tx*4;
#pragma unroll
        for (int i = 0; i < 4; i++)
#pragma unroll
            for (int jj = 0; jj < 4; jj++) {
                float v = sc[i][jj] * scale;
                if (ks0 + jj > qs0 + i) v = -INFINITY;
                sc[i][jj] = v;
            }

        // online softmax update
#pragma unroll
        for (int i = 0; i < 4; i++) {
            float rmax = fmaxf(fmaxf(sc[i][0], sc[i][1]), fmaxf(sc[i][2], sc[i][3]));
#pragma unroll
            for (int off = 8; off >= 1; off >>= 1)
                rmax = fmaxf(rmax, __shfl_xor_sync(0xffffffffu, rmax, off, 16));
            float m_new = fmaxf(m_i[i], rmax);
            float alpha = __expf(m_i[i] - m_new);
            float rsum = 0.f;
#pragma unroll
            for (int jj = 0; jj < 4; jj++) {
                float p = __expf(sc[i][jj] - m_new);
                sc[i][jj] = p;
                rsum += p;
            }
#pragma unroll
            for (int off = 8; off >= 1; off >>= 1)
                rsum += __shfl_xor_sync(0xffffffffu, rsum, off, 16);
            l_i[i] = l_i[i]*alpha + rsum;
            m_i[i] = m_new;
#pragma unroll
            for (int jj = 0; jj < 8; jj++) o[i][jj] *= alpha;
        }

        // stage P and do O += P * V
#pragma unroll
        for (int i = 0; i < 4; i++)
#pragma unroll
            for (int jj = 0; jj < 4; jj++)
                Ps[(ty*4+i)*PPAD + tx*4 + jj] = sc[i][jj];
        __syncthreads();

        for (int k = 0; k < 64; k++) {
            float p[4];
#pragma unroll
            for (int i = 0; i < 4; i++) p[i] = Ps[(ty*4+i)*PPAD + k];
            float4 v0 = *(float4*)&Vs[k*VPAD + tx*8];
            float4 v1 = *(float4*)&Vs[k*VPAD + tx*8 + 4];
#pragma unroll
            for (int i = 0; i < 4; i++) {
                o[i][0] = fmaf(p[i], v0.x, o[i][0]);
                o[i][1] = fmaf(p[i], v0.y, o[i][1]);
                o[i][2] = fmaf(p[i], v0.z, o[i][2]);
                o[i][3] = fmaf(p[i], v0.w, o[i][3]);
                o[i][4] = fmaf(p[i], v1.x, o[i][4]);
                o[i][5] = fmaf(p[i], v1.y, o[i][5]);
                o[i][6] = fmaf(p[i], v1.z, o[i][6]);
                o[i][7] = fmaf(p[i], v1.w, o[i][7]);
            }
        }
    }

    // epilogue
#pragma unroll
    for (int i = 0; i < 4; i++) {
        float invl = 1.0f / l_i[i];
        int rg = qrow0 + ty*4 + i;
        float* op = attn + (size_t)rg*ATTN_LD + h*DV + tx*8;
        float4 a = make_float4(o[i][0]*invl, o[i][1]*invl, o[i][2]*invl, o[i][3]*invl);
        float4 bq = make_float4(o[i][4]*invl, o[i][5]*invl, o[i][6]*invl, o[i][7]*invl);
        *(float4*)&op[0] = a;
        *(float4*)&op[4] = bq;
    }
}

// ---------------- launch ----------------
extern "C" void kernel_launch(void* const* d_in, const int* in_sizes, int n_in,
                              void* d_out, int out_size)
{
    const float* hid    = (const float*)d_in[0];
    const float* w_dq   = (const float*)d_in[1];
    const float* q_ln   = (const float*)d_in[2];
    const float* w_uq   = (const float*)d_in[3];
    const float* kv_a_w = (const float*)d_in[4];
    const float* kv_ln  = (const float*)d_in[5];
    const float* kv_b_w = (const float*)d_in[6];
    const float* o_w    = (const float*)d_in[7];
    float* out = (float*)d_out;

    float *qa, *qbuf, *ckv, *kvbuf, *attn;
    cudaGetSymbolAddress((void**)&qa,   g_qa);
    cudaGetSymbolAddress((void**)&qbuf, g_q);
    cudaGetSymbolAddress((void**)&ckv,  g_ckv);
    cudaGetSymbolAddress((void**)&kvbuf,g_kv);
    cudaGetSymbolAddress((void**)&attn, g_attn);

    cudaFuncSetAttribute(flash_kernel, cudaFuncAttributeMaxDynamicSharedMemorySize, FLASH_SMEM);

    // q_a = hidden @ w_dq                       [4096,1536] k=2048
    sgemm_kernel<<<dim3(QLORA/128, NROWS/128), 256>>>(hid, w_dq, qa,
        NROWS, QLORA, HIDDEN, HIDDEN, QLORA, QLORA);
    // ckv_pe = hidden @ kv_a_w                  [4096,576]  k=2048
    sgemm_kernel<<<dim3((CKV_LD+127)/128, NROWS/128), 256>>>(hid, kv_a_w, ckv,
        NROWS, CKV_LD, HIDDEN, HIDDEN, CKV_LD, CKV_LD);
    // RMSNorms (in place)
    rmsnorm_kernel<<<NROWS, 256>>>(qa,  q_ln,  QLORA,  QLORA);
    rmsnorm_kernel<<<NROWS, 256>>>(ckv, kv_ln, KVLORA, CKV_LD);
    // RoPE k_pe (in place on ckv cols 512..575)
    rope_k_kernel<<<NROWS, 32>>>(ckv);
    // q = q_a_ln @ w_uq                         [4096,3072] k=1536
    sgemm_kernel<<<dim3(Q_LD/128, NROWS/128), 256>>>(qa, w_uq, qbuf,
        NROWS, Q_LD, QLORA, QLORA, Q_LD, Q_LD);
    // RoPE q_pe per head (in place)
    rope_q_kernel<<<NROWS, 512>>>(qbuf);
    // kv = ckv_ln @ kv_b_w                      [4096,4096] k=512
    sgemm_kernel<<<dim3(KV_LD/128, NROWS/128), 256>>>(ckv, kv_b_w, kvbuf,
        NROWS, KV_LD, KVLORA, CKV_LD, KV_LD, KV_LD);
    // causal flash attention -> attn [4096, 2048]
    flash_kernel<<<dim3(S_LEN/64, BATCH*NH), 256, FLASH_SMEM>>>(qbuf, kvbuf, ckv, attn);
    // out = attn @ o_w                          [4096,2048] k=2048
    sgemm_kernel<<<dim3(HIDDEN/128, NROWS/128), 256>>>(attn, o_w, out,
        NROWS, HIDDEN, ATTN_LD, ATTN_LD, HIDDEN, HIDDEN);
}

// round 2
// speedup vs baseline: 1.5919x; 1.5919x over previous
#include <cuda_runtime.h>
#include <math.h>
#include <stdint.h>

// ---------------- problem constants ----------------
#define S_LEN   2048
#define BATCH   2
#define HIDDEN  2048
#define NH      16
#define QLORA   1536
#define KVLORA  512
#define DNOPE   128
#define DROPE   64
#define DV      128
#define DQ      192           // DNOPE + DROPE
#define NROWS   (BATCH*S_LEN) // 4096
#define CKV_LD  (KVLORA + DROPE) // 576
#define KV_LD   (NH*(DNOPE+DV))  // 4096
#define Q_LD    (NH*DQ)          // 3072
#define ATTN_LD (NH*DV)          // 2048

// ---------------- scratch (device globals; no runtime alloc) ----------------
__device__ float g_qa  [(size_t)NROWS*QLORA];
__device__ float g_q   [(size_t)NROWS*Q_LD];
__device__ float g_ckv [(size_t)NROWS*CKV_LD];
__device__ float g_kv  [(size_t)NROWS*KV_LD];
__device__ float g_attn[(size_t)NROWS*ATTN_LD];

// ---------------- TF32 tensor-core GEMM: C[M,N] = A[M,K] * B[K,N] ----------------
// 128x128x16 CTA tile, 256 threads (8 warps of 64x32), mma.m16n8k8.tf32.
// A smem: m-major stride 20 (conflict-free frag loads); B smem: k-major stride 136.
__device__ __forceinline__ float to_tf32(float x) {
    uint32_t u;
    asm("cvt.rna.tf32.f32 %0, %1;" : "=r"(u) : "f"(x));
    return __uint_as_float(u);
}

__device__ __forceinline__ float4 cvt4(float4 v) {
    return make_float4(to_tf32(v.x), to_tf32(v.y), to_tf32(v.z), to_tf32(v.w));
}

__global__ __launch_bounds__(256) void tf32_gemm(
    const float* __restrict__ A, const float* __restrict__ B, float* __restrict__ C,
    int M, int N, int K, int lda, int ldb, int ldc)
{
    __shared__ float As[2][128][20];
    __shared__ float Bs[2][16][136];

    const int tid  = threadIdx.x;
    const int lane = tid & 31;
    const int warp = tid >> 5;
    const int wm0  = (warp >> 2) * 64;   // warp m origin in tile
    const int wn0  = (warp & 3) * 32;    // warp n origin in tile
    const int gr   = lane >> 2;          // group id 0..7
    const int tc   = lane & 3;           // thread-in-group 0..3

    const int bm = blockIdx.y * 128;
    const int bn = blockIdx.x * 128;

    float acc[4][4][4];
#pragma unroll
    for (int mt = 0; mt < 4; mt++)
#pragma unroll
        for (int nt = 0; nt < 4; nt++)
#pragma unroll
            for (int r = 0; r < 4; r++) acc[mt][nt][r] = 0.0f;

    // staging assignments
    const int am     = tid >> 1;          // A row 0..127
    const int ak     = (tid & 1) * 8;     // A k offset 0 or 8
    const int bkr    = tid >> 4;          // B row 0..15
    const int bnoff  = (tid & 15) * 8;    // B col offset 0..120

    const float* Ap = A + (size_t)(bm + am) * lda + ak;
    const bool bok0 = (bn + bnoff)     < N;
    const bool bok1 = (bn + bnoff + 4) < N;

    const int ntiles = K >> 4;
    float4 ra0, ra1, rb0, rb1;
    const float4 fz = make_float4(0.f, 0.f, 0.f, 0.f);

    // prologue: load + store tile 0
    {
        ra0 = *(const float4*)(Ap);
        ra1 = *(const float4*)(Ap + 4);
        const float* bp = B + (size_t)bkr * ldb + bn + bnoff;
        rb0 = bok0 ? *(const float4*)(bp)     : fz;
        rb1 = bok1 ? *(const float4*)(bp + 4) : fz;
        *(float4*)&As[0][am][ak]        = cvt4(ra0);
        *(float4*)&As[0][am][ak + 4]    = cvt4(ra1);
        *(float4*)&Bs[0][bkr][bnoff]     = cvt4(rb0);
        *(float4*)&Bs[0][bkr][bnoff + 4] = cvt4(rb1);
    }
    __syncthreads();

    for (int kt = 0; kt < ntiles; kt++) {
        const int buf = kt & 1;
        // prefetch next tile into registers
        if (kt + 1 < ntiles) {
            const int kg = (kt + 1) * 16;
            ra0 = *(const float4*)(Ap + kg);
            ra1 = *(const float4*)(Ap + kg + 4);
            const float* bp = B + (size_t)(kg + bkr) * ldb + bn + bnoff;
            rb0 = bok0 ? *(const float4*)(bp)     : fz;
            rb1 = bok1 ? *(const float4*)(bp + 4) : fz;
        }

        // compute on current buffer: 2 ksteps of 8
#pragma unroll
        for (int ks = 0; ks < 2; ks++) {
            const int k0 = ks * 8;
            uint32_t af[4][4], bfr[4][2];
#pragma unroll
            for (int mt = 0; mt < 4; mt++) {
                const int r = wm0 + mt * 16 + gr;
                af[mt][0] = __float_as_uint(As[buf][r][k0 + tc]);
                af[mt][1] = __float_as_uint(As[buf][r + 8][k0 + tc]);
                af[mt][2] = __float_as_uint(As[buf][r][k0 + tc + 4]);
                af[mt][3] = __float_as_uint(As[buf][r + 8][k0 + tc + 4]);
            }
#pragma unroll
            for (int nt = 0; nt < 4; nt++) {
                const int c = wn0 + nt * 8 + gr;
                bfr[nt][0] = __float_as_uint(Bs[buf][k0 + tc][c]);
                bfr[nt][1] = __float_as_uint(Bs[buf][k0 + tc + 4][c]);
            }
#pragma unroll
            for (int mt = 0; mt < 4; mt++)
#pragma unroll
                for (int nt = 0; nt < 4; nt++) {
                    asm volatile(
                        "mma.sync.aligned.m16n8k8.row.col.f32.tf32.tf32.f32 "
                        "{%0,%1,%2,%3}, {%4,%5,%6,%7}, {%8,%9}, {%0,%1,%2,%3};"
                        : "+f"(acc[mt][nt][0]), "+f"(acc[mt][nt][1]),
                          "+f"(acc[mt][nt][2]), "+f"(acc[mt][nt][3])
                        : "r"(af[mt][0]), "r"(af[mt][1]), "r"(af[mt][2]), "r"(af[mt][3]),
                          "r"(bfr[nt][0]), "r"(bfr[nt][1]));
                }
        }

        // store prefetched tile into the other buffer
        if (kt + 1 < ntiles) {
            const int nb = buf ^ 1;
            *(float4*)&As[nb][am][ak]        = cvt4(ra0);
            *(float4*)&As[nb][am][ak + 4]    = cvt4(ra1);
            *(float4*)&Bs[nb][bkr][bnoff]     = cvt4(rb0);
            *(float4*)&Bs[nb][bkr][bnoff + 4] = cvt4(rb1);
        }
        __syncthreads();
    }

    // epilogue: write C (c0,c1 contiguous -> float2)
#pragma unroll
    for (int mt = 0; mt < 4; mt++) {
        const int row0 = bm + wm0 + mt * 16 + gr;
#pragma unroll
        for (int nt = 0; nt < 4; nt++) {
            const int col = bn + wn0 + nt * 8 + tc * 2;
            if (col < N) {
                *(float2*)&C[(size_t)row0 * ldc + col] =
                    make_float2(acc[mt][nt][0], acc[mt][nt][1]);
                *(float2*)&C[(size_t)(row0 + 8) * ldc + col] =
                    make_float2(acc[mt][nt][2], acc[mt][nt][3]);
            }
        }
    }
}

// ---------------- row-wise RMSNorm (in place) ----------------
__global__ void rmsnorm_kernel(float* __restrict__ x, const float* __restrict__ w,
                               int W, int ld)
{
    __shared__ float red[256];
    const int row = blockIdx.x;
    float* p = x + (size_t)row*ld;
    float ss = 0.f;
    for (int c = threadIdx.x; c < W; c += 256) { float v = p[c]; ss += v*v; }
    red[threadIdx.x] = ss;
    __syncthreads();
    for (int s = 128; s; s >>= 1) {
        if (threadIdx.x < s) red[threadIdx.x] += red[threadIdx.x + s];
        __syncthreads();
    }
    const float scale = rsqrtf(red[0] / (float)W + 1e-6f);
    for (int c = threadIdx.x; c < W; c += 256) p[c] = p[c] * scale * w[c];
}

// ---------------- RoPE (DeepSeek interleaved permute + rotate-half), in place ----------------
__device__ __forceinline__ void rope_pair(float* base, int t, int lane)
{
    float xe = base[2*lane], xo = base[2*lane + 1];
    float inv = 1.0f / powf(10000.0f, (2.0f * (float)lane) / 64.0f);
    float ph = (float)t * inv;
    float sn, cs;
    sincosf(ph, &sn, &cs);
    __syncwarp();
    base[lane]      = xe*cs - xo*sn;
    base[lane + 32] = xo*cs + xe*sn;
}

__global__ void rope_k_kernel(float* __restrict__ ckv)
{
    const int row = blockIdx.x;
    rope_pair(ckv + (size_t)row*CKV_LD + KVLORA, row % S_LEN, threadIdx.x & 31);
}

__global__ void rope_q_kernel(float* __restrict__ q)
{
    const int row = blockIdx.x;
    const int h = threadIdx.x >> 5, lane = threadIdx.x & 31;
    rope_pair(q + (size_t)row*Q_LD + h*DQ + DNOPE, row % S_LEN, lane);
}

// ---------------- causal flash attention (fp32, unchanged) ----------------
#define QPAD 196
#define KPAD 196
#define VPAD 132
#define PPAD 68
#define FLASH_SMEM ((64*(QPAD+KPAD+VPAD+PPAD))*4)

__global__ __launch_bounds__(256) void flash_kernel(
    const float* __restrict__ q, const float* __restrict__ kv,
    const float* __restrict__ ckv, float* __restrict__ attn)
{
    extern __shared__ float smf[];
    float* Qs = smf;
    float* Ks = Qs + 64*QPAD;
    float* Vs = Ks + 64*KPAD;
    float* Ps = Vs + 64*VPAD;

    const int tid = threadIdx.x;
    const int qt = blockIdx.x;
    const int b  = blockIdx.y >> 4;
    const int h  = blockIdx.y & 15;
    const int ty = tid >> 4, tx = tid & 15;
    const float scale = 0.07216878364870323f; // 1/sqrt(192)

    const int qrow0 = b*S_LEN + qt*64;
#pragma unroll
    for (int t = 0; t < 12; t++) {
        int idx = tid + t*256;
        int r = idx / 48, c4 = idx % 48;
        float4 v = *(const float4*)(q + (size_t)(qrow0 + r)*Q_LD + h*DQ + c4*4);
        *(float4*)&Qs[r*QPAD + c4*4] = v;
    }

    float m_i[4], l_i[4], o[4][8];
#pragma unroll
    for (int i = 0; i < 4; i++) {
        m_i[i] = -INFINITY; l_i[i] = 0.f;
#pragma unroll
        for (int j = 0; j < 8; j++) o[i][j] = 0.f;
    }

    for (int j = 0; j <= qt; j++) {
        __syncthreads();
        const int krow0 = b*S_LEN + j*64;
#pragma unroll
        for (int t = 0; t < 12; t++) {
            int idx = tid + t*256;
            int r = idx / 48, col = (idx % 48) * 4;
            float4 v;
            if (col < DNOPE)
                v = *(const float4*)(kv + (size_t)(krow0 + r)*KV_LD + h*256 + col);
            else
                v = *(const float4*)(ckv + (size_t)(krow0 + r)*CKV_LD + KVLORA + (col - DNOPE));
            *(float4*)&Ks[r*KPAD + col] = v;
        }
#pragma unroll
        for (int t = 0; t < 8; t++) {
            int idx = tid + t*256;
            int r = idx >> 5, col = (idx & 31) * 4;
            float4 v = *(const float4*)(kv + (size_t)(krow0 + r)*KV_LD + h*256 + DNOPE + col);
            *(float4*)&Vs[r*VPAD + col] = v;
        }
        __syncthreads();

        float sc[4][4];
#pragma unroll
        for (int i = 0; i < 4; i++)
#pragma unroll
            for (int jj = 0; jj < 4; jj++) sc[i][jj] = 0.f;

        for (int c4 = 0; c4 < 48; c4++) {
            float4 qv[4], kf[4];
#pragma unroll
            for (int i = 0; i < 4; i++) qv[i] = *(float4*)&Qs[(ty*4+i)*QPAD + c4*4];
#pragma unroll
            for (int jj = 0; jj < 4; jj++) kf[jj] = *(float4*)&Ks[(tx*4+jj)*KPAD + c4*4];
#pragma unroll
            for (int i = 0; i < 4; i++)
#pragma unroll
                for (int jj = 0; jj < 4; jj++) {
                    sc[i][jj] = fmaf(qv[i].x, kf[jj].x, sc[i][jj]);
                    sc[i][jj] = fmaf(qv[i].y, kf[jj].y, sc[i][jj]);
                    sc[i][jj] = fmaf(qv[i].z, kf[jj].z, sc[i][jj]);
                    sc[i][jj] = fmaf(qv[i].w, kf[jj].w, sc[i][jj]);
                }
        }

        const int qs0 = qt*64 + ty*4, ks0 = j*64 + tx*4;
#pragma unroll
        for (int i = 0; i < 4; i++)
#pragma unroll
            for (int jj = 0; jj < 4; jj++) {
                float v = sc[i][jj] * scale;
                if (ks0 + jj > qs0 + i) v = -INFINITY;
                sc[i][jj] = v;
            }

#pragma unroll
        for (int i = 0; i < 4; i++) {
            float rmax = fmaxf(fmaxf(sc[i][0], sc[i][1]), fmaxf(sc[i][2], sc[i][3]));
#pragma unroll
            for (int off = 8; off >= 1; off >>= 1)
                rmax = fmaxf(rmax, __shfl_xor_sync(0xffffffffu, rmax, off, 16));
            float m_new = fmaxf(m_i[i], rmax);
            float alpha = __expf(m_i[i] - m_new);
            float rsum = 0.f;
#pragma unroll
            for (int jj = 0; jj < 4; jj++) {
                float p = __expf(sc[i][jj] - m_new);
                sc[i][jj] = p;
                rsum += p;
            }
#pragma unroll
            for (int off = 8; off >= 1; off >>= 1)
                rsum += __shfl_xor_sync(0xffffffffu, rsum, off, 16);
            l_i[i] = l_i[i]*alpha + rsum;
            m_i[i] = m_new;
#pragma unroll
            for (int jj = 0; jj < 8; jj++) o[i][jj] *= alpha;
        }

#pragma unroll
        for (int i = 0; i < 4; i++)
#pragma unroll
            for (int jj = 0; jj < 4; jj++)
                Ps[(ty*4+i)*PPAD + tx*4 + jj] = sc[i][jj];
        __syncthreads();

        for (int k = 0; k < 64; k++) {
            float p[4];
#pragma unroll
            for (int i = 0; i < 4; i++) p[i] = Ps[(ty*4+i)*PPAD + k];
            float4 v0 = *(float4*)&Vs[k*VPAD + tx*8];
            float4 v1 = *(float4*)&Vs[k*VPAD + tx*8 + 4];
#pragma unroll
            for (int i = 0; i < 4; i++) {
                o[i][0] = fmaf(p[i], v0.x, o[i][0]);
                o[i][1] = fmaf(p[i], v0.y, o[i][1]);
                o[i][2] = fmaf(p[i], v0.z, o[i][2]);
                o[i][3] = fmaf(p[i], v0.w, o[i][3]);
                o[i][4] = fmaf(p[i], v1.x, o[i][4]);
                o[i][5] = fmaf(p[i], v1.y, o[i][5]);
                o[i][6] = fmaf(p[i], v1.z, o[i][6]);
                o[i][7] = fmaf(p[i], v1.w, o[i][7]);
            }
        }
    }

#pragma unroll
    for (int i = 0; i < 4; i++) {
        float invl = 1.0f / l_i[i];
        int rg = qrow0 + ty*4 + i;
        float* op = attn + (size_t)rg*ATTN_LD + h*DV + tx*8;
        float4 a = make_float4(o[i][0]*invl, o[i][1]*invl, o[i][2]*invl, o[i][3]*invl);
        float4 bq = make_float4(o[i][4]*invl, o[i][5]*invl, o[i][6]*invl, o[i][7]*invl);
        *(float4*)&op[0] = a;
        *(float4*)&op[4] = bq;
    }
}

// ---------------- launch ----------------
extern "C" void kernel_launch(void* const* d_in, const int* in_sizes, int n_in,
                              void* d_out, int out_size)
{
    const float* hid    = (const float*)d_in[0];
    const float* w_dq   = (const float*)d_in[1];
    const float* q_ln   = (const float*)d_in[2];
    const float* w_uq   = (const float*)d_in[3];
    const float* kv_a_w = (const float*)d_in[4];
    const float* kv_ln  = (const float*)d_in[5];
    const float* kv_b_w = (const float*)d_in[6];
    const float* o_w    = (const float*)d_in[7];
    float* out = (float*)d_out;

    float *qa, *qbuf, *ckv, *kvbuf, *attn;
    cudaGetSymbolAddress((void**)&qa,   g_qa);
    cudaGetSymbolAddress((void**)&qbuf, g_q);
    cudaGetSymbolAddress((void**)&ckv,  g_ckv);
    cudaGetSymbolAddress((void**)&kvbuf,g_kv);
    cudaGetSymbolAddress((void**)&attn, g_attn);

    cudaFuncSetAttribute(flash_kernel, cudaFuncAttributeMaxDynamicSharedMemorySize, FLASH_SMEM);

    // q_a = hidden @ w_dq                       [4096,1536] k=2048
    tf32_gemm<<<dim3(QLORA/128, NROWS/128), 256>>>(hid, w_dq, qa,
        NROWS, QLORA, HIDDEN, HIDDEN, QLORA, QLORA);
    // ckv_pe = hidden @ kv_a_w                  [4096,576]  k=2048
    tf32_gemm<<<dim3((CKV_LD+127)/128, NROWS/128), 256>>>(hid, kv_a_w, ckv,
        NROWS, CKV_LD, HIDDEN, HIDDEN, CKV_LD, CKV_LD);
    // RMSNorms (in place)
    rmsnorm_kernel<<<NROWS, 256>>>(qa,  q_ln,  QLORA,  QLORA);
    rmsnorm_kernel<<<NROWS, 256>>>(ckv, kv_ln, KVLORA, CKV_LD);
    // RoPE k_pe (in place on ckv cols 512..575)
    rope_k_kernel<<<NROWS, 32>>>(ckv);
    // q = q_a_ln @ w_uq                         [4096,3072] k=1536
    tf32_gemm<<<dim3(Q_LD/128, NROWS/128), 256>>>(qa, w_uq, qbuf,
        NROWS, Q_LD, QLORA, QLORA, Q_LD, Q_LD);
    // RoPE q_pe per head (in place)
    rope_q_kernel<<<NROWS, 512>>>(qbuf);
    // kv = ckv_ln @ kv_b_w                      [4096,4096] k=512
    tf32_gemm<<<dim3(KV_LD/128, NROWS/128), 256>>>(ckv, kv_b_w, kvbuf,
        NROWS, KV_LD, KVLORA, CKV_LD, KV_LD, KV_LD);
    // causal flash attention -> attn [4096, 2048]
    flash_kernel<<<dim3(S_LEN/64, BATCH*NH), 256, FLASH_SMEM>>>(qbuf, kvbuf, ckv, attn);
    // out = attn @ o_w                          [4096,2048] k=2048
    tf32_gemm<<<dim3(HIDDEN/128, NROWS/128), 256>>>(attn, o_w, out,
        NROWS, HIDDEN, ATTN_LD, ATTN_LD, HIDDEN, HIDDEN);
}

// round 3
// speedup vs baseline: 1.8161x; 1.1408x over previous
#include <cuda_runtime.h>
#include <math.h>
#include <stdint.h>

// ---------------- problem constants ----------------
#define S_LEN   2048
#define BATCH   2
#define HIDDEN  2048
#define NH      16
#define QLORA   1536
#define KVLORA  512
#define DNOPE   128
#define DROPE   64
#define DV      128
#define DQ      192           // DNOPE + DROPE
#define NROWS   (BATCH*S_LEN) // 4096
#define CKV_LD  (KVLORA + DROPE) // 576
#define KV_LD   (NH*(DNOPE+DV))  // 4096
#define Q_LD    (NH*DQ)          // 3072
#define ATTN_LD (NH*DV)          // 2048

// ---------------- scratch (device globals; no runtime alloc) ----------------
__device__ float g_qa  [(size_t)NROWS*QLORA];
__device__ float g_q   [(size_t)NROWS*Q_LD];
__device__ float g_ckv [(size_t)NROWS*CKV_LD];
__device__ float g_kv  [(size_t)NROWS*KV_LD];
__device__ float g_attn[(size_t)NROWS*ATTN_LD];

// ---------------- tf32 helpers ----------------
__device__ __forceinline__ float to_tf32(float x) {
    uint32_t u;
    asm("cvt.rna.tf32.f32 %0, %1;" : "=r"(u) : "f"(x));
    return __uint_as_float(u);
}
__device__ __forceinline__ float4 cvt4(float4 v) {
    return make_float4(to_tf32(v.x), to_tf32(v.y), to_tf32(v.z), to_tf32(v.w));
}

#define MMA_TF32(acc, a0,a1,a2,a3, b0,b1)                                       \
    asm volatile(                                                               \
        "mma.sync.aligned.m16n8k8.row.col.f32.tf32.tf32.f32 "                   \
        "{%0,%1,%2,%3}, {%4,%5,%6,%7}, {%8,%9}, {%0,%1,%2,%3};"                 \
        : "+f"(acc[0]), "+f"(acc[1]), "+f"(acc[2]), "+f"(acc[3])                \
        : "r"(a0), "r"(a1), "r"(a2), "r"(a3), "r"(b0), "r"(b1))

// ---------------- TF32 tensor-core GEMM: C[M,N] = A[M,K] * B[K,N] ----------------
__global__ __launch_bounds__(256) void tf32_gemm(
    const float* __restrict__ A, const float* __restrict__ B, float* __restrict__ C,
    int M, int N, int K, int lda, int ldb, int ldc)
{
    __shared__ float As[2][128][20];
    __shared__ float Bs[2][16][136];

    const int tid  = threadIdx.x;
    const int lane = tid & 31;
    const int warp = tid >> 5;
    const int wm0  = (warp >> 2) * 64;
    const int wn0  = (warp & 3) * 32;
    const int gr   = lane >> 2;
    const int tc   = lane & 3;

    const int bm = blockIdx.y * 128;
    const int bn = blockIdx.x * 128;

    float acc[4][4][4];
#pragma unroll
    for (int mt = 0; mt < 4; mt++)
#pragma unroll
        for (int nt = 0; nt < 4; nt++)
#pragma unroll
            for (int r = 0; r < 4; r++) acc[mt][nt][r] = 0.0f;

    const int am     = tid >> 1;
    const int ak     = (tid & 1) * 8;
    const int bkr    = tid >> 4;
    const int bnoff  = (tid & 15) * 8;

    const float* Ap = A + (size_t)(bm + am) * lda + ak;
    const bool bok0 = (bn + bnoff)     < N;
    const bool bok1 = (bn + bnoff + 4) < N;

    const int ntiles = K >> 4;
    float4 ra0, ra1, rb0, rb1;
    const float4 fz = make_float4(0.f, 0.f, 0.f, 0.f);

    {
        ra0 = *(const float4*)(Ap);
        ra1 = *(const float4*)(Ap + 4);
        const float* bp = B + (size_t)bkr * ldb + bn + bnoff;
        rb0 = bok0 ? *(const float4*)(bp)     : fz;
        rb1 = bok1 ? *(const float4*)(bp + 4) : fz;
        *(float4*)&As[0][am][ak]        = cvt4(ra0);
        *(float4*)&As[0][am][ak + 4]    = cvt4(ra1);
        *(float4*)&Bs[0][bkr][bnoff]     = cvt4(rb0);
        *(float4*)&Bs[0][bkr][bnoff + 4] = cvt4(rb1);
    }
    __syncthreads();

    for (int kt = 0; kt < ntiles; kt++) {
        const int buf = kt & 1;
        if (kt + 1 < ntiles) {
            const int kg = (kt + 1) * 16;
            ra0 = *(const float4*)(Ap + kg);
            ra1 = *(const float4*)(Ap + kg + 4);
            const float* bp = B + (size_t)(kg + bkr) * ldb + bn + bnoff;
            rb0 = bok0 ? *(const float4*)(bp)     : fz;
            rb1 = bok1 ? *(const float4*)(bp + 4) : fz;
        }

#pragma unroll
        for (int ks = 0; ks < 2; ks++) {
            const int k0 = ks * 8;
            uint32_t af[4][4], bfr[4][2];
#pragma unroll
            for (int mt = 0; mt < 4; mt++) {
                const int r = wm0 + mt * 16 + gr;
                af[mt][0] = __float_as_uint(As[buf][r][k0 + tc]);
                af[mt][1] = __float_as_uint(As[buf][r + 8][k0 + tc]);
                af[mt][2] = __float_as_uint(As[buf][r][k0 + tc + 4]);
                af[mt][3] = __float_as_uint(As[buf][r + 8][k0 + tc + 4]);
            }
#pragma unroll
            for (int nt = 0; nt < 4; nt++) {
                const int c = wn0 + nt * 8 + gr;
                bfr[nt][0] = __float_as_uint(Bs[buf][k0 + tc][c]);
                bfr[nt][1] = __float_as_uint(Bs[buf][k0 + tc + 4][c]);
            }
#pragma unroll
            for (int mt = 0; mt < 4; mt++)
#pragma unroll
                for (int nt = 0; nt < 4; nt++)
                    MMA_TF32(acc[mt][nt], af[mt][0], af[mt][1], af[mt][2], af[mt][3],
                             bfr[nt][0], bfr[nt][1]);
        }

        if (kt + 1 < ntiles) {
            const int nb = buf ^ 1;
            *(float4*)&As[nb][am][ak]        = cvt4(ra0);
            *(float4*)&As[nb][am][ak + 4]    = cvt4(ra1);
            *(float4*)&Bs[nb][bkr][bnoff]     = cvt4(rb0);
            *(float4*)&Bs[nb][bkr][bnoff + 4] = cvt4(rb1);
        }
        __syncthreads();
    }

#pragma unroll
    for (int mt = 0; mt < 4; mt++) {
        const int row0 = bm + wm0 + mt * 16 + gr;
#pragma unroll
        for (int nt = 0; nt < 4; nt++) {
            const int col = bn + wn0 + nt * 8 + tc * 2;
            if (col < N) {
                *(float2*)&C[(size_t)row0 * ldc + col] =
                    make_float2(acc[mt][nt][0], acc[mt][nt][1]);
                *(float2*)&C[(size_t)(row0 + 8) * ldc + col] =
                    make_float2(acc[mt][nt][2], acc[mt][nt][3]);
            }
        }
    }
}

// ---------------- row-wise RMSNorm (in place) ----------------
__global__ void rmsnorm_kernel(float* __restrict__ x, const float* __restrict__ w,
                               int W, int ld)
{
    __shared__ float red[256];
    const int row = blockIdx.x;
    float* p = x + (size_t)row*ld;
    float ss = 0.f;
    for (int c = threadIdx.x; c < W; c += 256) { float v = p[c]; ss += v*v; }
    red[threadIdx.x] = ss;
    __syncthreads();
    for (int s = 128; s; s >>= 1) {
        if (threadIdx.x < s) red[threadIdx.x] += red[threadIdx.x + s];
        __syncthreads();
    }
    const float scale = rsqrtf(red[0] / (float)W + 1e-6f);
    for (int c = threadIdx.x; c < W; c += 256) p[c] = p[c] * scale * w[c];
}

// ---------------- RoPE ----------------
__device__ __forceinline__ void rope_pair(float* base, int t, int lane)
{
    float xe = base[2*lane], xo = base[2*lane + 1];
    float inv = 1.0f / powf(10000.0f, (2.0f * (float)lane) / 64.0f);
    float ph = (float)t * inv;
    float sn, cs;
    sincosf(ph, &sn, &cs);
    __syncwarp();
    base[lane]      = xe*cs - xo*sn;
    base[lane + 32] = xo*cs + xe*sn;
}

__global__ void rope_k_kernel(float* __restrict__ ckv)
{
    const int row = blockIdx.x;
    rope_pair(ckv + (size_t)row*CKV_LD + KVLORA, row % S_LEN, threadIdx.x & 31);
}

__global__ void rope_q_kernel(float* __restrict__ q)
{
    const int row = blockIdx.x;
    const int h = threadIdx.x >> 5, lane = threadIdx.x & 31;
    rope_pair(q + (size_t)row*Q_LD + h*DQ + DNOPE, row % S_LEN, lane);
}

// ---------------- tensor-core causal flash attention ----------------
// 4 warps (128 thr); warp w owns q rows [16w,16w+16). Br=Bc=64.
// Strides: [gr][tc]-indexed => stride%32==4 ; [tc][gr]-indexed => stride%32==8.
#define FQ 196
#define FK 196
#define FV 136
#define FP 68
#define FLASH_SMEM ((64*(FQ+FK+FV+FP))*4)

__global__ __launch_bounds__(128) void flash_tc_kernel(
    const float* __restrict__ q, const float* __restrict__ kv,
    const float* __restrict__ ckv, float* __restrict__ attn)
{
    extern __shared__ float smf[];
    float* Qs = smf;               // 64 x FQ
    float* Ks = Qs + 64*FQ;        // 64 x FK
    float* Vs = Ks + 64*FK;        // 64 x FV
    float* Ps = Vs + 64*FV;        // 64 x FP

    const int tid  = threadIdx.x;
    const int lane = tid & 31;
    const int warp = tid >> 5;
    const int gr   = lane >> 2;   // 0..7
    const int tc   = lane & 3;    // 0..3
    const int qt = blockIdx.x;
    const int b  = blockIdx.y >> 4;
    const int h  = blockIdx.y & 15;
    const float scale = 0.07216878364870323f; // 1/sqrt(192)

    const int qrow0 = b*S_LEN + qt*64;
    const int wr0   = warp * 16;  // warp's row origin in tile

    // load Q tile (64 x 192), tf32-converted
#pragma unroll
    for (int t = 0; t < 24; t++) {
        int idx = tid + t*128;
        int r = idx / 48, c4 = (idx % 48) * 4;
        float4 v = *(const float4*)(q + (size_t)(qrow0 + r)*Q_LD + h*DQ + c4);
        *(float4*)&Qs[r*FQ + c4] = cvt4(v);
    }

    float m0 = -INFINITY, m1 = -INFINITY, l0 = 0.f, l1 = 0.f;
    float o[16][4];
#pragma unroll
    for (int nt = 0; nt < 16; nt++)
#pragma unroll
        for (int r = 0; r < 4; r++) o[nt][r] = 0.f;

    for (int j = 0; j <= qt; j++) {
        __syncthreads();
        const int krow0 = b*S_LEN + j*64;
        // K tile: cols 0..127 from kv nope, 128..191 from roped ckv pe
#pragma unroll
        for (int t = 0; t < 24; t++) {
            int idx = tid + t*128;
            int r = idx / 48, col = (idx % 48) * 4;
            float4 v;
            if (col < DNOPE)
                v = *(const float4*)(kv + (size_t)(krow0 + r)*KV_LD + h*256 + col);
            else
                v = *(const float4*)(ckv + (size_t)(krow0 + r)*CKV_LD + KVLORA + (col - DNOPE));
            *(float4*)&Ks[r*FK + col] = cvt4(v);
        }
        // V tile (64 x 128)
#pragma unroll
        for (int t = 0; t < 16; t++) {
            int idx = tid + t*128;
            int r = idx >> 5, col = (idx & 31) * 4;
            float4 v = *(const float4*)(kv + (size_t)(krow0 + r)*KV_LD + h*256 + DNOPE + col);
            *(float4*)&Vs[r*FV + col] = cvt4(v);
        }
        __syncthreads();

        // ---- S = Q K^T (warp: 16 x 64) ----
        float accS[8][4];
#pragma unroll
        for (int nt = 0; nt < 8; nt++)
#pragma unroll
            for (int r = 0; r < 4; r++) accS[nt][r] = 0.f;

#pragma unroll
        for (int k = 0; k < 24; k++) {
            const int k0 = k * 8;
            uint32_t a0 = __float_as_uint(Qs[(wr0 + gr)*FQ     + k0 + tc]);
            uint32_t a1 = __float_as_uint(Qs[(wr0 + gr + 8)*FQ + k0 + tc]);
            uint32_t a2 = __float_as_uint(Qs[(wr0 + gr)*FQ     + k0 + tc + 4]);
            uint32_t a3 = __float_as_uint(Qs[(wr0 + gr + 8)*FQ + k0 + tc + 4]);
#pragma unroll
            for (int nt = 0; nt < 8; nt++) {
                uint32_t b0 = __float_as_uint(Ks[(nt*8 + gr)*FK + k0 + tc]);
                uint32_t b1 = __float_as_uint(Ks[(nt*8 + gr)*FK + k0 + tc + 4]);
                MMA_TF32(accS[nt], a0, a1, a2, a3, b0, b1);
            }
        }

        // ---- scale + (diag-only) causal mask ----
        if (j == qt) {
            const int r0 = wr0 + gr, r1 = r0 + 8;
#pragma unroll
            for (int nt = 0; nt < 8; nt++) {
                const int c0 = nt*8 + 2*tc;
                accS[nt][0] = (c0     <= r0) ? accS[nt][0]*scale : -INFINITY;
                accS[nt][1] = (c0 + 1 <= r0) ? accS[nt][1]*scale : -INFINITY;
                accS[nt][2] = (c0     <= r1) ? accS[nt][2]*scale : -INFINITY;
                accS[nt][3] = (c0 + 1 <= r1) ? accS[nt][3]*scale : -INFINITY;
            }
        } else {
#pragma unroll
            for (int nt = 0; nt < 8; nt++)
#pragma unroll
                for (int r = 0; r < 4; r++) accS[nt][r] *= scale;
        }

        // ---- online softmax (rows r0, r1 per thread) ----
        float rm0 = -INFINITY, rm1 = -INFINITY;
#pragma unroll
        for (int nt = 0; nt < 8; nt++) {
            rm0 = fmaxf(rm0, fmaxf(accS[nt][0], accS[nt][1]));
            rm1 = fmaxf(rm1, fmaxf(accS[nt][2], accS[nt][3]));
        }
        rm0 = fmaxf(rm0, __shfl_xor_sync(0xffffffffu, rm0, 1));
        rm0 = fmaxf(rm0, __shfl_xor_sync(0xffffffffu, rm0, 2));
        rm1 = fmaxf(rm1, __shfl_xor_sync(0xffffffffu, rm1, 1));
        rm1 = fmaxf(rm1, __shfl_xor_sync(0xffffffffu, rm1, 2));

        const float mn0 = fmaxf(m0, rm0), mn1 = fmaxf(m1, rm1);
        const float al0 = __expf(m0 - mn0), al1 = __expf(m1 - mn1);
        m0 = mn0; m1 = mn1;

        float rs0 = 0.f, rs1 = 0.f;
#pragma unroll
        for (int nt = 0; nt < 8; nt++) {
            float p0 = __expf(accS[nt][0] - mn0);
            float p1 = __expf(accS[nt][1] - mn0);
            float p2 = __expf(accS[nt][2] - mn1);
            float p3 = __expf(accS[nt][3] - mn1);
            rs0 += p0 + p1; rs1 += p2 + p3;
            // stage P (tf32) into warp-private rows of Ps
            const int c0 = nt*8 + 2*tc;
            Ps[(wr0 + gr)*FP + c0]     = to_tf32(p0);
            Ps[(wr0 + gr)*FP + c0 + 1] = to_tf32(p1);
            Ps[(wr0 + gr + 8)*FP + c0]     = to_tf32(p2);
            Ps[(wr0 + gr + 8)*FP + c0 + 1] = to_tf32(p3);
        }
        rs0 += __shfl_xor_sync(0xffffffffu, rs0, 1);
        rs0 += __shfl_xor_sync(0xffffffffu, rs0, 2);
        rs1 += __shfl_xor_sync(0xffffffffu, rs1, 1);
        rs1 += __shfl_xor_sync(0xffffffffu, rs1, 2);
        l0 = l0*al0 + rs0;
        l1 = l1*al1 + rs1;

#pragma unroll
        for (int nt = 0; nt < 16; nt++) {
            o[nt][0] *= al0; o[nt][1] *= al0;
            o[nt][2] *= al1; o[nt][3] *= al1;
        }
        __syncwarp();

        // ---- O += P V (warp: 16 x 128) ----
#pragma unroll
        for (int k = 0; k < 8; k++) {
            const int k0 = k * 8;
            uint32_t a0 = __float_as_uint(Ps[(wr0 + gr)*FP     + k0 + tc]);
            uint32_t a1 = __float_as_uint(Ps[(wr0 + gr + 8)*FP + k0 + tc]);
            uint32_t a2 = __float_as_uint(Ps[(wr0 + gr)*FP     + k0 + tc + 4]);
            uint32_t a3 = __float_as_uint(Ps[(wr0 + gr + 8)*FP + k0 + tc + 4]);
#pragma unroll
            for (int nt = 0; nt < 16; nt++) {
                uint32_t b0 = __float_as_uint(Vs[(k0 + tc)*FV     + nt*8 + gr]);
                uint32_t b1 = __float_as_uint(Vs[(k0 + tc + 4)*FV + nt*8 + gr]);
                MMA_TF32(o[nt], a0, a1, a2, a3, b0, b1);
            }
        }
    }

    // ---- epilogue ----
    const float il0 = 1.0f / l0, il1 = 1.0f / l1;
    const int row0 = qrow0 + wr0 + gr;
#pragma unroll
    for (int nt = 0; nt < 16; nt++) {
        const int col = h*DV + nt*8 + 2*tc;
        *(float2*)&attn[(size_t)row0*ATTN_LD + col] =
            make_float2(o[nt][0]*il0, o[nt][1]*il0);
        *(float2*)&attn[(size_t)(row0 + 8)*ATTN_LD + col] =
            make_float2(o[nt][2]*il1, o[nt][3]*il1);
    }
}

// ---------------- launch ----------------
extern "C" void kernel_launch(void* const* d_in, const int* in_sizes, int n_in,
                              void* d_out, int out_size)
{
    const float* hid    = (const float*)d_in[0];
    const float* w_dq   = (const float*)d_in[1];
    const float* q_ln   = (const float*)d_in[2];
    const float* w_uq   = (const float*)d_in[3];
    const float* kv_a_w = (const float*)d_in[4];
    const float* kv_ln  = (const float*)d_in[5];
    const float* kv_b_w = (const float*)d_in[6];
    const float* o_w    = (const float*)d_in[7];
    float* out = (float*)d_out;

    float *qa, *qbuf, *ckv, *kvbuf, *attn;
    cudaGetSymbolAddress((void**)&qa,   g_qa);
    cudaGetSymbolAddress((void**)&qbuf, g_q);
    cudaGetSymbolAddress((void**)&ckv,  g_ckv);
    cudaGetSymbolAddress((void**)&kvbuf,g_kv);
    cudaGetSymbolAddress((void**)&attn, g_attn);

    cudaFuncSetAttribute(flash_tc_kernel, cudaFuncAttributeMaxDynamicSharedMemorySize, FLASH_SMEM);

    // q_a = hidden @ w_dq                       [4096,1536] k=2048
    tf32_gemm<<<dim3(QLORA/128, NROWS/128), 256>>>(hid, w_dq, qa,
        NROWS, QLORA, HIDDEN, HIDDEN, QLORA, QLORA);
    // ckv_pe = hidden @ kv_a_w                  [4096,576]  k=2048
    tf32_gemm<<<dim3((CKV_LD+127)/128, NROWS/128), 256>>>(hid, kv_a_w, ckv,
        NROWS, CKV_LD, HIDDEN, HIDDEN, CKV_LD, CKV_LD);
    // RMSNorms (in place)
    rmsnorm_kernel<<<NROWS, 256>>>(qa,  q_ln,  QLORA,  QLORA);
    rmsnorm_kernel<<<NROWS, 256>>>(ckv, kv_ln, KVLORA, CKV_LD);
    // RoPE k_pe (in place on ckv cols 512..575)
    rope_k_kernel<<<NROWS, 32>>>(ckv);
    // q = q_a_ln @ w_uq                         [4096,3072] k=1536
    tf32_gemm<<<dim3(Q_LD/128, NROWS/128), 256>>>(qa, w_uq, qbuf,
        NROWS, Q_LD, QLORA, QLORA, Q_LD, Q_LD);
    // RoPE q_pe per head (in place)
    rope_q_kernel<<<NROWS, 512>>>(qbuf);
    // kv = ckv_ln @ kv_b_w                      [4096,4096] k=512
    tf32_gemm<<<dim3(KV_LD/128, NROWS/128), 256>>>(ckv, kv_b_w, kvbuf,
        NROWS, KV_LD, KVLORA, CKV_LD, KV_LD, KV_LD);
    // tensor-core causal flash attention -> attn [4096, 2048]
    flash_tc_kernel<<<dim3(S_LEN/64, BATCH*NH), 128, FLASH_SMEM>>>(qbuf, kvbuf, ckv, attn);
    // out = attn @ o_w                          [4096,2048] k=2048
    tf32_gemm<<<dim3(HIDDEN/128, NROWS/128), 256>>>(attn, o_w, out,
        NROWS, HIDDEN, ATTN_LD, ATTN_LD, HIDDEN, HIDDEN);
}

// round 4
// speedup vs baseline: 2.1487x; 1.1832x over previous
#include <cuda_runtime.h>
#include <math.h>
#include <stdint.h>

// ---------------- problem constants ----------------
#define S_LEN   2048
#define BATCH   2
#define HIDDEN  2048
#define NH      16
#define QLORA   1536
#define KVLORA  512
#define DNOPE   128
#define DROPE   64
#define DV      128
#define DQ      192           // DNOPE + DROPE
#define NROWS   (BATCH*S_LEN) // 4096
#define CKV_LD  (KVLORA + DROPE) // 576
#define KV_LD   (NH*(DNOPE+DV))  // 4096
#define Q_LD    (NH*DQ)          // 3072
#define ATTN_LD (NH*DV)          // 2048

// ---------------- scratch (device globals; no runtime alloc) ----------------
__device__ float g_qa  [(size_t)NROWS*QLORA];
__device__ float g_q   [(size_t)NROWS*Q_LD];
__device__ float g_ckv [(size_t)NROWS*CKV_LD];
__device__ float g_kv  [(size_t)NROWS*KV_LD];
__device__ float g_attn[(size_t)NROWS*ATTN_LD];

// ---------------- tf32 helpers ----------------
__device__ __forceinline__ float to_tf32(float x) {
    uint32_t u;
    asm("cvt.rna.tf32.f32 %0, %1;" : "=r"(u) : "f"(x));
    return __uint_as_float(u);
}
__device__ __forceinline__ float4 cvt4(float4 v) {
    return make_float4(to_tf32(v.x), to_tf32(v.y), to_tf32(v.z), to_tf32(v.w));
}

#define MMA_TF32(acc, a0,a1,a2,a3, b0,b1)                                       \
    asm volatile(                                                               \
        "mma.sync.aligned.m16n8k8.row.col.f32.tf32.tf32.f32 "                   \
        "{%0,%1,%2,%3}, {%4,%5,%6,%7}, {%8,%9}, {%0,%1,%2,%3};"                 \
        : "+f"(acc[0]), "+f"(acc[1]), "+f"(acc[2]), "+f"(acc[3])                \
        : "r"(a0), "r"(a1), "r"(a2), "r"(a3), "r"(b0), "r"(b1))

// ---------------- TF32 tensor-core GEMM: C[M,N] = A[M,K] * B[K,N] ----------------
__global__ __launch_bounds__(256) void tf32_gemm(
    const float* __restrict__ A, const float* __restrict__ B, float* __restrict__ C,
    int M, int N, int K, int lda, int ldb, int ldc)
{
    __shared__ float As[2][128][20];
    __shared__ float Bs[2][16][136];

    const int tid  = threadIdx.x;
    const int lane = tid & 31;
    const int warp = tid >> 5;
    const int wm0  = (warp >> 2) * 64;
    const int wn0  = (warp & 3) * 32;
    const int gr   = lane >> 2;
    const int tc   = lane & 3;

    const int bm = blockIdx.y * 128;
    const int bn = blockIdx.x * 128;

    float acc[4][4][4];
#pragma unroll
    for (int mt = 0; mt < 4; mt++)
#pragma unroll
        for (int nt = 0; nt < 4; nt++)
#pragma unroll
            for (int r = 0; r < 4; r++) acc[mt][nt][r] = 0.0f;

    const int am     = tid >> 1;
    const int ak     = (tid & 1) * 8;
    const int bkr    = tid >> 4;
    const int bnoff  = (tid & 15) * 8;

    const float* Ap = A + (size_t)(bm + am) * lda + ak;
    const bool bok0 = (bn + bnoff)     < N;
    const bool bok1 = (bn + bnoff + 4) < N;

    const int ntiles = K >> 4;
    float4 ra0, ra1, rb0, rb1;
    const float4 fz = make_float4(0.f, 0.f, 0.f, 0.f);

    {
        ra0 = *(const float4*)(Ap);
        ra1 = *(const float4*)(Ap + 4);
        const float* bp = B + (size_t)bkr * ldb + bn + bnoff;
        rb0 = bok0 ? *(const float4*)(bp)     : fz;
        rb1 = bok1 ? *(const float4*)(bp + 4) : fz;
        *(float4*)&As[0][am][ak]        = cvt4(ra0);
        *(float4*)&As[0][am][ak + 4]    = cvt4(ra1);
        *(float4*)&Bs[0][bkr][bnoff]     = cvt4(rb0);
        *(float4*)&Bs[0][bkr][bnoff + 4] = cvt4(rb1);
    }
    __syncthreads();

    for (int kt = 0; kt < ntiles; kt++) {
        const int buf = kt & 1;
        if (kt + 1 < ntiles) {
            const int kg = (kt + 1) * 16;
            ra0 = *(const float4*)(Ap + kg);
            ra1 = *(const float4*)(Ap + kg + 4);
            const float* bp = B + (size_t)(kg + bkr) * ldb + bn + bnoff;
            rb0 = bok0 ? *(const float4*)(bp)     : fz;
            rb1 = bok1 ? *(const float4*)(bp + 4) : fz;
        }

#pragma unroll
        for (int ks = 0; ks < 2; ks++) {
            const int k0 = ks * 8;
            uint32_t af[4][4], bfr[4][2];
#pragma unroll
            for (int mt = 0; mt < 4; mt++) {
                const int r = wm0 + mt * 16 + gr;
                af[mt][0] = __float_as_uint(As[buf][r][k0 + tc]);
                af[mt][1] = __float_as_uint(As[buf][r + 8][k0 + tc]);
                af[mt][2] = __float_as_uint(As[buf][r][k0 + tc + 4]);
                af[mt][3] = __float_as_uint(As[buf][r + 8][k0 + tc + 4]);
            }
#pragma unroll
            for (int nt = 0; nt < 4; nt++) {
                const int c = wn0 + nt * 8 + gr;
                bfr[nt][0] = __float_as_uint(Bs[buf][k0 + tc][c]);
                bfr[nt][1] = __float_as_uint(Bs[buf][k0 + tc + 4][c]);
            }
#pragma unroll
            for (int mt = 0; mt < 4; mt++)
#pragma unroll
                for (int nt = 0; nt < 4; nt++)
                    MMA_TF32(acc[mt][nt], af[mt][0], af[mt][1], af[mt][2], af[mt][3],
                             bfr[nt][0], bfr[nt][1]);
        }

        if (kt + 1 < ntiles) {
            const int nb = buf ^ 1;
            *(float4*)&As[nb][am][ak]        = cvt4(ra0);
            *(float4*)&As[nb][am][ak + 4]    = cvt4(ra1);
            *(float4*)&Bs[nb][bkr][bnoff]     = cvt4(rb0);
            *(float4*)&Bs[nb][bkr][bnoff + 4] = cvt4(rb1);
        }
        __syncthreads();
    }

#pragma unroll
    for (int mt = 0; mt < 4; mt++) {
        const int row0 = bm + wm0 + mt * 16 + gr;
#pragma unroll
        for (int nt = 0; nt < 4; nt++) {
            const int col = bn + wn0 + nt * 8 + tc * 2;
            if (col < N) {
                *(float2*)&C[(size_t)row0 * ldc + col] =
                    make_float2(acc[mt][nt][0], acc[mt][nt][1]);
                *(float2*)&C[(size_t)(row0 + 8) * ldc + col] =
                    make_float2(acc[mt][nt][2], acc[mt][nt][3]);
            }
        }
    }
}

// ---------------- row-wise RMSNorm (in place) ----------------
__global__ void rmsnorm_kernel(float* __restrict__ x, const float* __restrict__ w,
                               int W, int ld)
{
    __shared__ float red[256];
    const int row = blockIdx.x;
    float* p = x + (size_t)row*ld;
    float ss = 0.f;
    for (int c = threadIdx.x; c < W; c += 256) { float v = p[c]; ss += v*v; }
    red[threadIdx.x] = ss;
    __syncthreads();
    for (int s = 128; s; s >>= 1) {
        if (threadIdx.x < s) red[threadIdx.x] += red[threadIdx.x + s];
        __syncthreads();
    }
    const float scale = rsqrtf(red[0] / (float)W + 1e-6f);
    for (int c = threadIdx.x; c < W; c += 256) p[c] = p[c] * scale * w[c];
}

// ---------------- RoPE ----------------
__device__ __forceinline__ void rope_pair(float* base, int t, int lane)
{
    float xe = base[2*lane], xo = base[2*lane + 1];
    float inv = 1.0f / powf(10000.0f, (2.0f * (float)lane) / 64.0f);
    float ph = (float)t * inv;
    float sn, cs;
    sincosf(ph, &sn, &cs);
    __syncwarp();
    base[lane]      = xe*cs - xo*sn;
    base[lane + 32] = xo*cs + xe*sn;
}

__global__ void rope_k_kernel(float* __restrict__ ckv)
{
    const int row = blockIdx.x;
    rope_pair(ckv + (size_t)row*CKV_LD + KVLORA, row % S_LEN, threadIdx.x & 31);
}

__global__ void rope_q_kernel(float* __restrict__ q)
{
    const int row = blockIdx.x;
    const int h = threadIdx.x >> 5, lane = threadIdx.x & 31;
    rope_pair(q + (size_t)row*Q_LD + h*DQ + DNOPE, row % S_LEN, lane);
}

// ---------------- tensor-core causal flash attention (Br=128, 8 warps) ----------------
// Warp w owns q rows [16w, 16w+16). Bc=64.
// Strides: [gr][tc]-indexed => stride%32==4 ; [tc][gr]-indexed => stride%32==8.
#define FQ 196
#define FK 196
#define FV 136
#define FP 68
#define BR 128
#define FLASH_SMEM ((BR*FQ + 64*FK + 64*FV + BR*FP)*4)

__global__ __launch_bounds__(256) void flash_tc_kernel(
    const float* __restrict__ q, const float* __restrict__ kv,
    const float* __restrict__ ckv, float* __restrict__ attn)
{
    extern __shared__ float smf[];
    float* Qs = smf;                 // BR x FQ
    float* Ks = Qs + BR*FQ;          // 64 x FK
    float* Vs = Ks + 64*FK;          // 64 x FV
    float* Ps = Vs + 64*FV;          // BR x FP

    const int tid  = threadIdx.x;
    const int lane = tid & 31;
    const int warp = tid >> 5;
    const int gr   = lane >> 2;   // 0..7
    const int tc   = lane & 3;    // 0..3
    const int qt = blockIdx.x;
    const int b  = blockIdx.y >> 4;
    const int h  = blockIdx.y & 15;
    const float scale = 0.07216878364870323f; // 1/sqrt(192)

    const int qrow0 = b*S_LEN + qt*BR;
    const int wr0   = warp * 16;  // warp's row origin in tile

    // load Q tile (128 x 192), tf32-converted
#pragma unroll
    for (int t = 0; t < 24; t++) {
        int idx = tid + t*256;
        int r = idx / 48, c4 = (idx % 48) * 4;
        float4 v = *(const float4*)(q + (size_t)(qrow0 + r)*Q_LD + h*DQ + c4);
        *(float4*)&Qs[r*FQ + c4] = cvt4(v);
    }

    float m0 = -INFINITY, m1 = -INFINITY, l0 = 0.f, l1 = 0.f;
    float o[16][4];
#pragma unroll
    for (int nt = 0; nt < 16; nt++)
#pragma unroll
        for (int r = 0; r < 4; r++) o[nt][r] = 0.f;

    const int jmax = 2*qt + 1;
    for (int j = 0; j <= jmax; j++) {
        __syncthreads();
        const int krow0 = b*S_LEN + j*64;
        // K tile: cols 0..127 from kv nope, 128..191 from roped ckv pe
#pragma unroll
        for (int t = 0; t < 12; t++) {
            int idx = tid + t*256;
            int r = idx / 48, col = (idx % 48) * 4;
            float4 v;
            if (col < DNOPE)
                v = *(const float4*)(kv + (size_t)(krow0 + r)*KV_LD + h*256 + col);
            else
                v = *(const float4*)(ckv + (size_t)(krow0 + r)*CKV_LD + KVLORA + (col - DNOPE));
            *(float4*)&Ks[r*FK + col] = cvt4(v);
        }
        // V tile (64 x 128)
#pragma unroll
        for (int t = 0; t < 8; t++) {
            int idx = tid + t*256;
            int r = idx >> 5, col = (idx & 31) * 4;
            float4 v = *(const float4*)(kv + (size_t)(krow0 + r)*KV_LD + h*256 + DNOPE + col);
            *(float4*)&Vs[r*FV + col] = cvt4(v);
        }
        __syncthreads();

        // causal block classification for this warp
        const int off = j*64 - qt*BR;           // col_local - row_local offset
        if (off > wr0 + 15) continue;           // block fully above diagonal: skip
        const bool needMask = (off + 63 > wr0); // diagonal block

        // ---- S = Q K^T (warp: 16 x 64) ----
        float accS[8][4];
#pragma unroll
        for (int nt = 0; nt < 8; nt++)
#pragma unroll
            for (int r = 0; r < 4; r++) accS[nt][r] = 0.f;

#pragma unroll
        for (int k = 0; k < 24; k++) {
            const int k0 = k * 8;
            uint32_t a0 = __float_as_uint(Qs[(wr0 + gr)*FQ     + k0 + tc]);
            uint32_t a1 = __float_as_uint(Qs[(wr0 + gr + 8)*FQ + k0 + tc]);
            uint32_t a2 = __float_as_uint(Qs[(wr0 + gr)*FQ     + k0 + tc + 4]);
            uint32_t a3 = __float_as_uint(Qs[(wr0 + gr + 8)*FQ + k0 + tc + 4]);
#pragma unroll
            for (int nt = 0; nt < 8; nt++) {
                uint32_t b0 = __float_as_uint(Ks[(nt*8 + gr)*FK + k0 + tc]);
                uint32_t b1 = __float_as_uint(Ks[(nt*8 + gr)*FK + k0 + tc + 4]);
                MMA_TF32(accS[nt], a0, a1, a2, a3, b0, b1);
            }
        }

        // ---- scale + (diag-only) causal mask ----
        if (needMask) {
            const int r0 = wr0 + gr, r1 = r0 + 8;
#pragma unroll
            for (int nt = 0; nt < 8; nt++) {
                const int c0 = nt*8 + 2*tc + off;
                accS[nt][0] = (c0     <= r0) ? accS[nt][0]*scale : -INFINITY;
                accS[nt][1] = (c0 + 1 <= r0) ? accS[nt][1]*scale : -INFINITY;
                accS[nt][2] = (c0     <= r1) ? accS[nt][2]*scale : -INFINITY;
                accS[nt][3] = (c0 + 1 <= r1) ? accS[nt][3]*scale : -INFINITY;
            }
        } else {
#pragma unroll
            for (int nt = 0; nt < 8; nt++)
#pragma unroll
                for (int r = 0; r < 4; r++) accS[nt][r] *= scale;
        }

        // ---- online softmax (rows r0, r1 per thread) ----
        float rm0 = -INFINITY, rm1 = -INFINITY;
#pragma unroll
        for (int nt = 0; nt < 8; nt++) {
            rm0 = fmaxf(rm0, fmaxf(accS[nt][0], accS[nt][1]));
            rm1 = fmaxf(rm1, fmaxf(accS[nt][2], accS[nt][3]));
        }
        rm0 = fmaxf(rm0, __shfl_xor_sync(0xffffffffu, rm0, 1));
        rm0 = fmaxf(rm0, __shfl_xor_sync(0xffffffffu, rm0, 2));
        rm1 = fmaxf(rm1, __shfl_xor_sync(0xffffffffu, rm1, 1));
        rm1 = fmaxf(rm1, __shfl_xor_sync(0xffffffffu, rm1, 2));

        const float mn0 = fmaxf(m0, rm0), mn1 = fmaxf(m1, rm1);
        const float al0 = __expf(m0 - mn0), al1 = __expf(m1 - mn1);
        m0 = mn0; m1 = mn1;

        float rs0 = 0.f, rs1 = 0.f;
#pragma unroll
        for (int nt = 0; nt < 8; nt++) {
            float p0 = __expf(accS[nt][0] - mn0);
            float p1 = __expf(accS[nt][1] - mn0);
            float p2 = __expf(accS[nt][2] - mn1);
            float p3 = __expf(accS[nt][3] - mn1);
            rs0 += p0 + p1; rs1 += p2 + p3;
            const int c0 = nt*8 + 2*tc;
            Ps[(wr0 + gr)*FP + c0]     = to_tf32(p0);
            Ps[(wr0 + gr)*FP + c0 + 1] = to_tf32(p1);
            Ps[(wr0 + gr + 8)*FP + c0]     = to_tf32(p2);
            Ps[(wr0 + gr + 8)*FP + c0 + 1] = to_tf32(p3);
        }
        rs0 += __shfl_xor_sync(0xffffffffu, rs0, 1);
        rs0 += __shfl_xor_sync(0xffffffffu, rs0, 2);
        rs1 += __shfl_xor_sync(0xffffffffu, rs1, 1);
        rs1 += __shfl_xor_sync(0xffffffffu, rs1, 2);
        l0 = l0*al0 + rs0;
        l1 = l1*al1 + rs1;

#pragma unroll
        for (int nt = 0; nt < 16; nt++) {
            o[nt][0] *= al0; o[nt][1] *= al0;
            o[nt][2] *= al1; o[nt][3] *= al1;
        }
        __syncwarp();

        // ---- O += P V (warp: 16 x 128) ----
#pragma unroll
        for (int k = 0; k < 8; k++) {
            const int k0 = k * 8;
            uint32_t a0 = __float_as_uint(Ps[(wr0 + gr)*FP     + k0 + tc]);
            uint32_t a1 = __float_as_uint(Ps[(wr0 + gr + 8)*FP + k0 + tc]);
            uint32_t a2 = __float_as_uint(Ps[(wr0 + gr)*FP     + k0 + tc + 4]);
            uint32_t a3 = __float_as_uint(Ps[(wr0 + gr + 8)*FP + k0 + tc + 4]);
#pragma unroll
            for (int nt = 0; nt < 16; nt++) {
                uint32_t b0 = __float_as_uint(Vs[(k0 + tc)*FV     + nt*8 + gr]);
                uint32_t b1 = __float_as_uint(Vs[(k0 + tc + 4)*FV + nt*8 + gr]);
                MMA_TF32(o[nt], a0, a1, a2, a3, b0, b1);
            }
        }
    }

    // ---- epilogue ----
    const float il0 = 1.0f / l0, il1 = 1.0f / l1;
    const int row0 = qrow0 + wr0 + gr;
#pragma unroll
    for (int nt = 0; nt < 16; nt++) {
        const int col = h*DV + nt*8 + 2*tc;
        *(float2*)&attn[(size_t)row0*ATTN_LD + col] =
            make_float2(o[nt][0]*il0, o[nt][1]*il0);
        *(float2*)&attn[(size_t)(row0 + 8)*ATTN_LD + col] =
            make_float2(o[nt][2]*il1, o[nt][3]*il1);
    }
}

// ---------------- launch ----------------
extern "C" void kernel_launch(void* const* d_in, const int* in_sizes, int n_in,
                              void* d_out, int out_size)
{
    const float* hid    = (const float*)d_in[0];
    const float* w_dq   = (const float*)d_in[1];
    const float* q_ln   = (const float*)d_in[2];
    const float* w_uq   = (const float*)d_in[3];
    const float* kv_a_w = (const float*)d_in[4];
    const float* kv_ln  = (const float*)d_in[5];
    const float* kv_b_w = (const float*)d_in[6];
    const float* o_w    = (const float*)d_in[7];
    float* out = (float*)d_out;

    float *qa, *qbuf, *ckv, *kvbuf, *attn;
    cudaGetSymbolAddress((void**)&qa,   g_qa);
    cudaGetSymbolAddress((void**)&qbuf, g_q);
    cudaGetSymbolAddress((void**)&ckv,  g_ckv);
    cudaGetSymbolAddress((void**)&kvbuf,g_kv);
    cudaGetSymbolAddress((void**)&attn, g_attn);

    cudaFuncSetAttribute(flash_tc_kernel, cudaFuncAttributeMaxDynamicSharedMemorySize, FLASH_SMEM);

    // q_a = hidden @ w_dq                       [4096,1536] k=2048
    tf32_gemm<<<dim3(QLORA/128, NROWS/128), 256>>>(hid, w_dq, qa,
        NROWS, QLORA, HIDDEN, HIDDEN, QLORA, QLORA);
    // ckv_pe = hidden @ kv_a_w                  [4096,576]  k=2048
    tf32_gemm<<<dim3((CKV_LD+127)/128, NROWS/128), 256>>>(hid, kv_a_w, ckv,
        NROWS, CKV_LD, HIDDEN, HIDDEN, CKV_LD, CKV_LD);
    // RMSNorms (in place)
    rmsnorm_kernel<<<NROWS, 256>>>(qa,  q_ln,  QLORA,  QLORA);
    rmsnorm_kernel<<<NROWS, 256>>>(ckv, kv_ln, KVLORA, CKV_LD);
    // RoPE k_pe (in place on ckv cols 512..575)
    rope_k_kernel<<<NROWS, 32>>>(ckv);
    // q = q_a_ln @ w_uq                         [4096,3072] k=1536
    tf32_gemm<<<dim3(Q_LD/128, NROWS/128), 256>>>(qa, w_uq, qbuf,
        NROWS, Q_LD, QLORA, QLORA, Q_LD, Q_LD);
    // RoPE q_pe per head (in place)
    rope_q_kernel<<<NROWS, 512>>>(qbuf);
    // kv = ckv_ln @ kv_b_w                      [4096,4096] k=512
    tf32_gemm<<<dim3(KV_LD/128, NROWS/128), 256>>>(ckv, kv_b_w, kvbuf,
        NROWS, KV_LD, KVLORA, CKV_LD, KV_LD, KV_LD);
    // tensor-core causal flash attention -> attn [4096, 2048]
    flash_tc_kernel<<<dim3(S_LEN/BR, BATCH*NH), 256, FLASH_SMEM>>>(qbuf, kvbuf, ckv, attn);
    // out = attn @ o_w                          [4096,2048] k=2048
    tf32_gemm<<<dim3(HIDDEN/128, NROWS/128), 256>>>(attn, o_w, out,
        NROWS, HIDDEN, ATTN_LD, ATTN_LD, HIDDEN, HIDDEN);
}

// round 5
// speedup vs baseline: 3.7503x; 1.7453x over previous
#include <cuda_runtime.h>
#include <math.h>
#include <stdint.h>

// ---------------- problem constants ----------------
#define S_LEN   2048
#define BATCH   2
#define HIDDEN  2048
#define NH      16
#define QLORA   1536
#define KVLORA  512
#define DNOPE   128
#define DROPE   64
#define DV      128
#define DQ      192           // DNOPE + DROPE
#define NROWS   (BATCH*S_LEN) // 4096
#define CKV_LD  (KVLORA + DROPE) // 576
#define KV_LD   (NH*(DNOPE+DV))  // 4096
#define Q_LD    (NH*DQ)          // 3072
#define ATTN_LD (NH*DV)          // 2048

// ---------------- scratch (device globals; no runtime alloc) ----------------
__device__ float g_qa  [(size_t)NROWS*QLORA];
__device__ float g_q   [(size_t)NROWS*Q_LD];
__device__ float g_ckv [(size_t)NROWS*CKV_LD];
__device__ float g_kv  [(size_t)NROWS*KV_LD];
__device__ float g_attn[(size_t)NROWS*ATTN_LD];

// ---------------- tf32 helpers ----------------
__device__ __forceinline__ float to_tf32(float x) {
    uint32_t u;
    asm("cvt.rna.tf32.f32 %0, %1;" : "=r"(u) : "f"(x));
    return __uint_as_float(u);
}
__device__ __forceinline__ uint32_t to_tf32u(float x) {
    uint32_t u;
    asm("cvt.rna.tf32.f32 %0, %1;" : "=r"(u) : "f"(x));
    return u;
}
__device__ __forceinline__ float4 cvt4(float4 v) {
    return make_float4(to_tf32(v.x), to_tf32(v.y), to_tf32(v.z), to_tf32(v.w));
}

#define MMA_TF32(acc, a0,a1,a2,a3, b0,b1)                                       \
    asm volatile(                                                               \
        "mma.sync.aligned.m16n8k8.row.col.f32.tf32.tf32.f32 "                   \
        "{%0,%1,%2,%3}, {%4,%5,%6,%7}, {%8,%9}, {%0,%1,%2,%3};"                 \
        : "+f"(acc[0]), "+f"(acc[1]), "+f"(acc[2]), "+f"(acc[3])                \
        : "r"(a0), "r"(a1), "r"(a2), "r"(a3), "r"(b0), "r"(b1))

#define CP_ASYNC16(dst_u32, src_ptr)                                            \
    asm volatile("cp.async.cg.shared.global [%0], [%1], 16;"                    \
                 :: "r"(dst_u32), "l"(src_ptr))
#define CP_COMMIT() asm volatile("cp.async.commit_group;")
#define CP_WAIT1()  asm volatile("cp.async.wait_group 1;")

// ---------------- TF32 GEMM with 3-stage cp.async pipeline ----------------
// C[M,N] = A[M,K]*B[K,N]. 128x128x16 tile, 256 thr, 8 warps of 64x32.
// A smem stride 36 (144B: 16B-mult, ==4 mod 32); B stride 136 (544B, ==8 mod 32).
#define GSTAGES 3
#define ASTRIDE 36
#define BSTRIDE 136

__global__ __launch_bounds__(256) void tf32_gemm(
    const float* __restrict__ A, const float* __restrict__ B, float* __restrict__ C,
    int M, int N, int K, int lda, int ldb, int ldc)
{
    __shared__ float As[GSTAGES][128][ASTRIDE];
    __shared__ float Bs[GSTAGES][16][BSTRIDE];

    const int tid  = threadIdx.x;
    const int lane = tid & 31;
    const int warp = tid >> 5;
    const int wm0  = (warp >> 2) * 64;
    const int wn0  = (warp & 3) * 32;
    const int gr   = lane >> 2;
    const int tc   = lane & 3;

    const int bm = blockIdx.y * 128;
    const int bn = blockIdx.x * 128;

    float acc[4][4][4];
#pragma unroll
    for (int mt = 0; mt < 4; mt++)
#pragma unroll
        for (int nt = 0; nt < 4; nt++)
#pragma unroll
            for (int r = 0; r < 4; r++) acc[mt][nt][r] = 0.0f;

    // staging: A tile = 512 float4 chunks (row = c>>2, sub = c&3); thread does c=tid, tid+256
    // B tile = 512 chunks (row = c>>5, col4 = c&31); thread does c=tid, tid+256
    const int a_r0 = tid >> 2,        a_s0 = (tid & 3) * 4;
    const int a_r1 = (tid + 256) >> 2, a_s1 = a_s0;
    const int b_r0 = tid >> 5,        b_c0 = (tid & 31) * 4;
    const int b_r1 = (tid + 256) >> 5, b_c1 = b_c0;

    const float* Ap0 = A + (size_t)(bm + a_r0) * lda + a_s0;
    const float* Ap1 = A + (size_t)(bm + a_r1) * lda + a_s1;
    const bool bok = (bn + b_c0) < N;   // same col for both B chunks

    const int ntiles = K >> 4;

    uint32_t sa0[GSTAGES], sa1[GSTAGES], sb0[GSTAGES], sb1[GSTAGES];
#pragma unroll
    for (int s = 0; s < GSTAGES; s++) {
        sa0[s] = (uint32_t)__cvta_generic_to_shared(&As[s][a_r0][a_s0]);
        sa1[s] = (uint32_t)__cvta_generic_to_shared(&As[s][a_r1][a_s1]);
        sb0[s] = (uint32_t)__cvta_generic_to_shared(&Bs[s][b_r0][b_c0]);
        sb1[s] = (uint32_t)__cvta_generic_to_shared(&Bs[s][b_r1][b_c1]);
    }

    // prologue: issue stages 0 and 1
#pragma unroll
    for (int s = 0; s < 2; s++) {
        const int kg = s * 16;
        CP_ASYNC16(sa0[s], Ap0 + kg);
        CP_ASYNC16(sa1[s], Ap1 + kg);
        if (bok) {
            CP_ASYNC16(sb0[s], B + (size_t)(kg + b_r0) * ldb + bn + b_c0);
            CP_ASYNC16(sb1[s], B + (size_t)(kg + b_r1) * ldb + bn + b_c1);
        }
        CP_COMMIT();
    }

    for (int kt = 0; kt < ntiles; kt++) {
        CP_WAIT1();
        __syncthreads();

        // issue stage kt+2
        if (kt + 2 < ntiles) {
            const int s = (kt + 2) % GSTAGES;
            const int kg = (kt + 2) * 16;
            CP_ASYNC16(sa0[s], Ap0 + kg);
            CP_ASYNC16(sa1[s], Ap1 + kg);
            if (bok) {
                CP_ASYNC16(sb0[s], B + (size_t)(kg + b_r0) * ldb + bn + b_c0);
                CP_ASYNC16(sb1[s], B + (size_t)(kg + b_r1) * ldb + bn + b_c1);
            }
        }
        CP_COMMIT();   // keep group count in lockstep even when nothing issued

        const int buf = kt % GSTAGES;
#pragma unroll
        for (int ks = 0; ks < 2; ks++) {
            const int k0 = ks * 8;
            uint32_t af[4][4], bfr[4][2];
#pragma unroll
            for (int mt = 0; mt < 4; mt++) {
                const int r = wm0 + mt * 16 + gr;
                af[mt][0] = to_tf32u(As[buf][r][k0 + tc]);
                af[mt][1] = to_tf32u(As[buf][r + 8][k0 + tc]);
                af[mt][2] = to_tf32u(As[buf][r][k0 + tc + 4]);
                af[mt][3] = to_tf32u(As[buf][r + 8][k0 + tc + 4]);
            }
#pragma unroll
            for (int nt = 0; nt < 4; nt++) {
                const int c = wn0 + nt * 8 + gr;
                bfr[nt][0] = to_tf32u(Bs[buf][k0 + tc][c]);
                bfr[nt][1] = to_tf32u(Bs[buf][k0 + tc + 4][c]);
            }
#pragma unroll
            for (int mt = 0; mt < 4; mt++)
#pragma unroll
                for (int nt = 0; nt < 4; nt++)
                    MMA_TF32(acc[mt][nt], af[mt][0], af[mt][1], af[mt][2], af[mt][3],
                             bfr[nt][0], bfr[nt][1]);
        }
    }

#pragma unroll
    for (int mt = 0; mt < 4; mt++) {
        const int row0 = bm + wm0 + mt * 16 + gr;
#pragma unroll
        for (int nt = 0; nt < 4; nt++) {
            const int col = bn + wn0 + nt * 8 + tc * 2;
            if (col < N) {
                *(float2*)&C[(size_t)row0 * ldc + col] =
                    make_float2(acc[mt][nt][0], acc[mt][nt][1]);
                *(float2*)&C[(size_t)(row0 + 8) * ldc + col] =
                    make_float2(acc[mt][nt][2], acc[mt][nt][3]);
            }
        }
    }
}

// ---------------- row-wise RMSNorm (in place) ----------------
__global__ void rmsnorm_kernel(float* __restrict__ x, const float* __restrict__ w,
                               int W, int ld)
{
    __shared__ float red[256];
    const int row = blockIdx.x;
    float* p = x + (size_t)row*ld;
    float ss = 0.f;
    for (int c = threadIdx.x; c < W; c += 256) { float v = p[c]; ss += v*v; }
    red[threadIdx.x] = ss;
    __syncthreads();
    for (int s = 128; s; s >>= 1) {
        if (threadIdx.x < s) red[threadIdx.x] += red[threadIdx.x + s];
        __syncthreads();
    }
    const float scale = rsqrtf(red[0] / (float)W + 1e-6f);
    for (int c = threadIdx.x; c < W; c += 256) p[c] = p[c] * scale * w[c];
}

// ---------------- RoPE ----------------
__device__ __forceinline__ void rope_pair(float* base, int t, int lane)
{
    float xe = base[2*lane], xo = base[2*lane + 1];
    float inv = 1.0f / powf(10000.0f, (2.0f * (float)lane) / 64.0f);
    float ph = (float)t * inv;
    float sn, cs;
    sincosf(ph, &sn, &cs);
    __syncwarp();
    base[lane]      = xe*cs - xo*sn;
    base[lane + 32] = xo*cs + xe*sn;
}

__global__ void rope_k_kernel(float* __restrict__ ckv)
{
    const int row = blockIdx.x;
    rope_pair(ckv + (size_t)row*CKV_LD + KVLORA, row % S_LEN, threadIdx.x & 31);
}

__global__ void rope_q_kernel(float* __restrict__ q)
{
    const int row = blockIdx.x;
    const int h = threadIdx.x >> 5, lane = threadIdx.x & 31;
    rope_pair(q + (size_t)row*Q_LD + h*DQ + DNOPE, row % S_LEN, lane);
}

// ---------------- tensor-core causal flash attention (Br=128, 8 warps) ----------------
#define FQ 196
#define FK 196
#define FV 136
#define FP 68
#define BR 128
#define FLASH_SMEM ((BR*FQ + 64*FK + 64*FV + BR*FP)*4)

__global__ __launch_bounds__(256) void flash_tc_kernel(
    const float* __restrict__ q, const float* __restrict__ kv,
    const float* __restrict__ ckv, float* __restrict__ attn)
{
    extern __shared__ float smf[];
    float* Qs = smf;                 // BR x FQ
    float* Ks = Qs + BR*FQ;          // 64 x FK
    float* Vs = Ks + 64*FK;          // 64 x FV
    float* Ps = Vs + 64*FV;          // BR x FP

    const int tid  = threadIdx.x;
    const int lane = tid & 31;
    const int warp = tid >> 5;
    const int gr   = lane >> 2;
    const int tc   = lane & 3;
    const int qt = blockIdx.x;
    const int b  = blockIdx.y >> 4;
    const int h  = blockIdx.y & 15;
    const float scale = 0.07216878364870323f; // 1/sqrt(192)

    const int qrow0 = b*S_LEN + qt*BR;
    const int wr0   = warp * 16;

#pragma unroll
    for (int t = 0; t < 24; t++) {
        int idx = tid + t*256;
        int r = idx / 48, c4 = (idx % 48) * 4;
        float4 v = *(const float4*)(q + (size_t)(qrow0 + r)*Q_LD + h*DQ + c4);
        *(float4*)&Qs[r*FQ + c4] = cvt4(v);
    }

    float m0 = -INFINITY, m1 = -INFINITY, l0 = 0.f, l1 = 0.f;
    float o[16][4];
#pragma unroll
    for (int nt = 0; nt < 16; nt++)
#pragma unroll
        for (int r = 0; r < 4; r++) o[nt][r] = 0.f;

    const int jmax = 2*qt + 1;
    for (int j = 0; j <= jmax; j++) {
        __syncthreads();
        const int krow0 = b*S_LEN + j*64;
#pragma unroll
        for (int t = 0; t < 12; t++) {
            int idx = tid + t*256;
            int r = idx / 48, col = (idx % 48) * 4;
            float4 v;
            if (col < DNOPE)
                v = *(const float4*)(kv + (size_t)(krow0 + r)*KV_LD + h*256 + col);
            else
                v = *(const float4*)(ckv + (size_t)(krow0 + r)*CKV_LD + KVLORA + (col - DNOPE));
            *(float4*)&Ks[r*FK + col] = cvt4(v);
        }
#pragma unroll
        for (int t = 0; t < 8; t++) {
            int idx = tid + t*256;
            int r = idx >> 5, col = (idx & 31) * 4;
            float4 v = *(const float4*)(kv + (size_t)(krow0 + r)*KV_LD + h*256 + DNOPE + col);
            *(float4*)&Vs[r*FV + col] = cvt4(v);
        }
        __syncthreads();

        const int off = j*64 - qt*BR;
        if (off > wr0 + 15) continue;
        const bool needMask = (off + 63 > wr0);

        float accS[8][4];
#pragma unroll
        for (int nt = 0; nt < 8; nt++)
#pragma unroll
            for (int r = 0; r < 4; r++) accS[nt][r] = 0.f;

#pragma unroll
        for (int k = 0; k < 24; k++) {
            const int k0 = k * 8;
            uint32_t a0 = __float_as_uint(Qs[(wr0 + gr)*FQ     + k0 + tc]);
            uint32_t a1 = __float_as_uint(Qs[(wr0 + gr + 8)*FQ + k0 + tc]);
            uint32_t a2 = __float_as_uint(Qs[(wr0 + gr)*FQ     + k0 + tc + 4]);
            uint32_t a3 = __float_as_uint(Qs[(wr0 + gr + 8)*FQ + k0 + tc + 4]);
#pragma unroll
            for (int nt = 0; nt < 8; nt++) {
                uint32_t b0 = __float_as_uint(Ks[(nt*8 + gr)*FK + k0 + tc]);
                uint32_t b1 = __float_as_uint(Ks[(nt*8 + gr)*FK + k0 + tc + 4]);
                MMA_TF32(accS[nt], a0, a1, a2, a3, b0, b1);
            }
        }

        if (needMask) {
            const int r0 = wr0 + gr, r1 = r0 + 8;
#pragma unroll
            for (int nt = 0; nt < 8; nt++) {
                const int c0 = nt*8 + 2*tc + off;
                accS[nt][0] = (c0     <= r0) ? accS[nt][0]*scale : -INFINITY;
                accS[nt][1] = (c0 + 1 <= r0) ? accS[nt][1]*scale : -INFINITY;
                accS[nt][2] = (c0     <= r1) ? accS[nt][2]*scale : -INFINITY;
                accS[nt][3] = (c0 + 1 <= r1) ? accS[nt][3]*scale : -INFINITY;
            }
        } else {
#pragma unroll
            for (int nt = 0; nt < 8; nt++)
#pragma unroll
                for (int r = 0; r < 4; r++) accS[nt][r] *= scale;
        }

        float rm0 = -INFINITY, rm1 = -INFINITY;
#pragma unroll
        for (int nt = 0; nt < 8; nt++) {
            rm0 = fmaxf(rm0, fmaxf(accS[nt][0], accS[nt][1]));
            rm1 = fmaxf(rm1, fmaxf(accS[nt][2], accS[nt][3]));
        }
        rm0 = fmaxf(rm0, __shfl_xor_sync(0xffffffffu, rm0, 1));
        rm0 = fmaxf(rm0, __shfl_xor_sync(0xffffffffu, rm0, 2));
        rm1 = fmaxf(rm1, __shfl_xor_sync(0xffffffffu, rm1, 1));
        rm1 = fmaxf(rm1, __shfl_xor_sync(0xffffffffu, rm1, 2));

        const float mn0 = fmaxf(m0, rm0), mn1 = fmaxf(m1, rm1);
        const float al0 = __expf(m0 - mn0), al1 = __expf(m1 - mn1);
        m0 = mn0; m1 = mn1;

        float rs0 = 0.f, rs1 = 0.f;
#pragma unroll
        for (int nt = 0; nt < 8; nt++) {
            float p0 = __expf(accS[nt][0] - mn0);
            float p1 = __expf(accS[nt][1] - mn0);
            float p2 = __expf(accS[nt][2] - mn1);
            float p3 = __expf(accS[nt][3] - mn1);
            rs0 += p0 + p1; rs1 += p2 + p3;
            const int c0 = nt*8 + 2*tc;
            Ps[(wr0 + gr)*FP + c0]     = to_tf32(p0);
            Ps[(wr0 + gr)*FP + c0 + 1] = to_tf32(p1);
            Ps[(wr0 + gr + 8)*FP + c0]     = to_tf32(p2);
            Ps[(wr0 + gr + 8)*FP + c0 + 1] = to_tf32(p3);
        }
        rs0 += __shfl_xor_sync(0xffffffffu, rs0, 1);
        rs0 += __shfl_xor_sync(0xffffffffu, rs0, 2);
        rs1 += __shfl_xor_sync(0xffffffffu, rs1, 1);
        rs1 += __shfl_xor_sync(0xffffffffu, rs1, 2);
        l0 = l0*al0 + rs0;
        l1 = l1*al1 + rs1;

#pragma unroll
        for (int nt = 0; nt < 16; nt++) {
            o[nt][0] *= al0; o[nt][1] *= al0;
            o[nt][2] *= al1; o[nt][3] *= al1;
        }
        __syncwarp();

#pragma unroll
        for (int k = 0; k < 8; k++) {
            const int k0 = k * 8;
            uint32_t a0 = __float_as_uint(Ps[(wr0 + gr)*FP     + k0 + tc]);
            uint32_t a1 = __float_as_uint(Ps[(wr0 + gr + 8)*FP + k0 + tc]);
            uint32_t a2 = __float_as_uint(Ps[(wr0 + gr)*FP     + k0 + tc + 4]);
            uint32_t a3 = __float_as_uint(Ps[(wr0 + gr + 8)*FP + k0 + tc + 4]);
#pragma unroll
            for (int nt = 0; nt < 16; nt++) {
                uint32_t b0 = __float_as_uint(Vs[(k0 + tc)*FV     + nt*8 + gr]);
                uint32_t b1 = __float_as_uint(Vs[(k0 + tc + 4)*FV + nt*8 + gr]);
                MMA_TF32(o[nt], a0, a1, a2, a3, b0, b1);
            }
        }
    }

    const float il0 = 1.0f / l0, il1 = 1.0f / l1;
    const int row0 = qrow0 + wr0 + gr;
#pragma unroll
    for (int nt = 0; nt < 16; nt++) {
        const int col = h*DV + nt*8 + 2*tc;
        *(float2*)&attn[(size_t)row0*ATTN_LD + col] =
            make_float2(o[nt][0]*il0, o[nt][1]*il0);
        *(float2*)&attn[(size_t)(row0 + 8)*ATTN_LD + col] =
            make_float2(o[nt][2]*il1, o[nt][3]*il1);
    }
}

// ---------------- launch ----------------
extern "C" void kernel_launch(void* const* d_in, const int* in_sizes, int n_in,
                              void* d_out, int out_size)
{
    const float* hid    = (const float*)d_in[0];
    const float* w_dq   = (const float*)d_in[1];
    const float* q_ln   = (const float*)d_in[2];
    const float* w_uq   = (const float*)d_in[3];
    const float* kv_a_w = (const float*)d_in[4];
    const float* kv_ln  = (const float*)d_in[5];
    const float* kv_b_w = (const float*)d_in[6];
    const float* o_w    = (const float*)d_in[7];
    float* out = (float*)d_out;

    float *qa, *qbuf, *ckv, *kvbuf, *attn;
    cudaGetSymbolAddress((void**)&qa,   g_qa);
    cudaGetSymbolAddress((void**)&qbuf, g_q);
    cudaGetSymbolAddress((void**)&ckv,  g_ckv);
    cudaGetSymbolAddress((void**)&kvbuf,g_kv);
    cudaGetSymbolAddress((void**)&attn, g_attn);

    cudaFuncSetAttribute(flash_tc_kernel, cudaFuncAttributeMaxDynamicSharedMemorySize, FLASH_SMEM);

    // q_a = hidden @ w_dq                       [4096,1536] k=2048
    tf32_gemm<<<dim3(QLORA/128, NROWS/128), 256>>>(hid, w_dq, qa,
        NROWS, QLORA, HIDDEN, HIDDEN, QLORA, QLORA);
    // ckv_pe = hidden @ kv_a_w                  [4096,576]  k=2048
    tf32_gemm<<<dim3((CKV_LD+127)/128, NROWS/128), 256>>>(hid, kv_a_w, ckv,
        NROWS, CKV_LD, HIDDEN, HIDDEN, CKV_LD, CKV_LD);
    // RMSNorms (in place)
    rmsnorm_kernel<<<NROWS, 256>>>(qa,  q_ln,  QLORA,  QLORA);
    rmsnorm_kernel<<<NROWS, 256>>>(ckv, kv_ln, KVLORA, CKV_LD);
    // RoPE k_pe (in place on ckv cols 512..575)
    rope_k_kernel<<<NROWS, 32>>>(ckv);
    // q = q_a_ln @ w_uq                         [4096,3072] k=1536
    tf32_gemm<<<dim3(Q_LD/128, NROWS/128), 256>>>(qa, w_uq, qbuf,
        NROWS, Q_LD, QLORA, QLORA, Q_LD, Q_LD);
    // RoPE q_pe per head (in place)
    rope_q_kernel<<<NROWS, 512>>>(qbuf);
    // kv = ckv_ln @ kv_b_w                      [4096,4096] k=512
    tf32_gemm<<<dim3(KV_LD/128, NROWS/128), 256>>>(ckv, kv_b_w, kvbuf,
        NROWS, KV_LD, KVLORA, CKV_LD, KV_LD, KV_LD);
    // tensor-core causal flash attention -> attn [4096, 2048]
    flash_tc_kernel<<<dim3(S_LEN/BR, BATCH*NH), 256, FLASH_SMEM>>>(qbuf, kvbuf, ckv, attn);
    // out = attn @ o_w                          [4096,2048] k=2048
    tf32_gemm<<<dim3(HIDDEN/128, NROWS/128), 256>>>(attn, o_w, out,
        NROWS, HIDDEN, ATTN_LD, ATTN_LD, HIDDEN, HIDDEN);
}

// round 6
// speedup vs baseline: 4.2961x; 1.1456x over previous
#include <cuda_runtime.h>
#include <math.h>
#include <stdint.h>

// ---------------- problem constants ----------------
#define S_LEN   2048
#define BATCH   2
#define HIDDEN  2048
#define NH      16
#define QLORA   1536
#define KVLORA  512
#define DNOPE   128
#define DROPE   64
#define DV      128
#define DQ      192           // DNOPE + DROPE
#define NROWS   (BATCH*S_LEN) // 4096
#define CKV_LD  (KVLORA + DROPE) // 576
#define KV_LD   (NH*(DNOPE+DV))  // 4096
#define Q_LD    (NH*DQ)          // 3072
#define ATTN_LD (NH*DV)          // 2048

// ---------------- scratch (device globals; no runtime alloc) ----------------
__device__ float g_qa  [(size_t)NROWS*QLORA];
__device__ float g_q   [(size_t)NROWS*Q_LD];
__device__ float g_ckv [(size_t)NROWS*CKV_LD];
__device__ float g_kv  [(size_t)NROWS*KV_LD];
__device__ float g_attn[(size_t)NROWS*ATTN_LD];

// ---------------- tf32 helpers ----------------
__device__ __forceinline__ float to_tf32(float x) {
    uint32_t u;
    asm("cvt.rna.tf32.f32 %0, %1;" : "=r"(u) : "f"(x));
    return __uint_as_float(u);
}
__device__ __forceinline__ uint32_t to_tf32u(float x) {
    uint32_t u;
    asm("cvt.rna.tf32.f32 %0, %1;" : "=r"(u) : "f"(x));
    return u;
}
__device__ __forceinline__ float4 cvt4(float4 v) {
    return make_float4(to_tf32(v.x), to_tf32(v.y), to_tf32(v.z), to_tf32(v.w));
}

#define MMA_TF32(acc, a0,a1,a2,a3, b0,b1)                                       \
    asm volatile(                                                               \
        "mma.sync.aligned.m16n8k8.row.col.f32.tf32.tf32.f32 "                   \
        "{%0,%1,%2,%3}, {%4,%5,%6,%7}, {%8,%9}, {%0,%1,%2,%3};"                 \
        : "+f"(acc[0]), "+f"(acc[1]), "+f"(acc[2]), "+f"(acc[3])                \
        : "r"(a0), "r"(a1), "r"(a2), "r"(a3), "r"(b0), "r"(b1))

#define CP_ASYNC16(dst_u32, src_ptr)                                            \
    asm volatile("cp.async.cg.shared.global [%0], [%1], 16;"                    \
                 :: "r"(dst_u32), "l"(src_ptr))
#define CP_COMMIT() asm volatile("cp.async.commit_group;")
#define CP_WAIT1()  asm volatile("cp.async.wait_group 1;")

// ---------------- TF32 GEMM, 3-stage cp.async, BK=32 ----------------
// C[M,N] = A[M,K]*B[K,N]. 128x128x32 tile, 256 thr, 8 warps of 64x32.
// A smem stride 36 floats (144B: 16B-mult, ==4 mod 32); B stride 136 (==8 mod 32).
#define GSTAGES 3
#define BKK 32
#define ASTRIDE 36
#define BSTRIDE 136

__global__ __launch_bounds__(256, 2) void tf32_gemm(
    const float* __restrict__ A, const float* __restrict__ B, float* __restrict__ C,
    int M, int N, int K, int lda, int ldb, int ldc)
{
    __shared__ float As[GSTAGES][128][ASTRIDE];
    __shared__ float Bs[GSTAGES][BKK][BSTRIDE];

    const int tid  = threadIdx.x;
    const int lane = tid & 31;
    const int warp = tid >> 5;
    const int wm0  = (warp >> 2) * 64;
    const int wn0  = (warp & 3) * 32;
    const int gr   = lane >> 2;
    const int tc   = lane & 3;

    const int bm = blockIdx.y * 128;
    const int bn = blockIdx.x * 128;

    float acc[4][4][4];
#pragma unroll
    for (int mt = 0; mt < 4; mt++)
#pragma unroll
        for (int nt = 0; nt < 4; nt++)
#pragma unroll
            for (int r = 0; r < 4; r++) acc[mt][nt][r] = 0.0f;

    // staging: A tile 128x32 = 1024 float4 chunks; thread does 4 (rows ar+32i, col asub)
    //          B tile 32x128 = 1024 chunks; thread does 4 (rows br+8i, col bcol)
    const int asub = (tid & 7) * 4;
    const int ar   = tid >> 3;
    const int bcol = (tid & 31) * 4;
    const int br   = tid >> 5;
    const bool bok = (bn + bcol) < N;

    const float* ApBase[4];
#pragma unroll
    for (int i = 0; i < 4; i++)
        ApBase[i] = A + (size_t)(bm + ar + i * 32) * lda + asub;

    uint32_t sa[GSTAGES], sb[GSTAGES];
#pragma unroll
    for (int s = 0; s < GSTAGES; s++) {
        sa[s] = (uint32_t)__cvta_generic_to_shared(&As[s][ar][asub]);
        sb[s] = (uint32_t)__cvta_generic_to_shared(&Bs[s][br][bcol]);
    }

    const int ntiles = K >> 5;

    // prologue: stages 0,1
#pragma unroll
    for (int s = 0; s < 2; s++) {
        const int kg = s * BKK;
#pragma unroll
        for (int i = 0; i < 4; i++)
            CP_ASYNC16(sa[s] + i * (32 * ASTRIDE * 4), ApBase[i] + kg);
        if (bok) {
#pragma unroll
            for (int i = 0; i < 4; i++)
                CP_ASYNC16(sb[s] + i * (8 * BSTRIDE * 4),
                           B + (size_t)(kg + br + i * 8) * ldb + bn + bcol);
        }
        CP_COMMIT();
    }

    for (int kt = 0; kt < ntiles; kt++) {
        CP_WAIT1();
        __syncthreads();

        if (kt + 2 < ntiles) {
            const int s = (kt + 2) % GSTAGES;
            const int kg = (kt + 2) * BKK;
#pragma unroll
            for (int i = 0; i < 4; i++)
                CP_ASYNC16(sa[s] + i * (32 * ASTRIDE * 4), ApBase[i] + kg);
            if (bok) {
#pragma unroll
                for (int i = 0; i < 4; i++)
                    CP_ASYNC16(sb[s] + i * (8 * BSTRIDE * 4),
                               B + (size_t)(kg + br + i * 8) * ldb + bn + bcol);
            }
        }
        CP_COMMIT();

        const int buf = kt % GSTAGES;
#pragma unroll
        for (int ks = 0; ks < 4; ks++) {
            const int k0 = ks * 8;
            uint32_t af[4][4], bfr[4][2];
#pragma unroll
            for (int mt = 0; mt < 4; mt++) {
                const int r = wm0 + mt * 16 + gr;
                af[mt][0] = to_tf32u(As[buf][r][k0 + tc]);
                af[mt][1] = to_tf32u(As[buf][r + 8][k0 + tc]);
                af[mt][2] = to_tf32u(As[buf][r][k0 + tc + 4]);
                af[mt][3] = to_tf32u(As[buf][r + 8][k0 + tc + 4]);
            }
#pragma unroll
            for (int nt = 0; nt < 4; nt++) {
                const int c = wn0 + nt * 8 + gr;
                bfr[nt][0] = to_tf32u(Bs[buf][k0 + tc][c]);
                bfr[nt][1] = to_tf32u(Bs[buf][k0 + tc + 4][c]);
            }
#pragma unroll
            for (int mt = 0; mt < 4; mt++)
#pragma unroll
                for (int nt = 0; nt < 4; nt++)
                    MMA_TF32(acc[mt][nt], af[mt][0], af[mt][1], af[mt][2], af[mt][3],
                             bfr[nt][0], bfr[nt][1]);
        }
    }

#pragma unroll
    for (int mt = 0; mt < 4; mt++) {
        const int row0 = bm + wm0 + mt * 16 + gr;
#pragma unroll
        for (int nt = 0; nt < 4; nt++) {
            const int col = bn + wn0 + nt * 8 + tc * 2;
            if (col < N) {
                *(float2*)&C[(size_t)row0 * ldc + col] =
                    make_float2(acc[mt][nt][0], acc[mt][nt][1]);
                *(float2*)&C[(size_t)(row0 + 8) * ldc + col] =
                    make_float2(acc[mt][nt][2], acc[mt][nt][3]);
            }
        }
    }
}

// ---------------- row-wise RMSNorm (in place) ----------------
__global__ void rmsnorm_kernel(float* __restrict__ x, const float* __restrict__ w,
                               int W, int ld)
{
    __shared__ float red[256];
    const int row = blockIdx.x;
    float* p = x + (size_t)row*ld;
    float ss = 0.f;
    for (int c = threadIdx.x; c < W; c += 256) { float v = p[c]; ss += v*v; }
    red[threadIdx.x] = ss;
    __syncthreads();
    for (int s = 128; s; s >>= 1) {
        if (threadIdx.x < s) red[threadIdx.x] += red[threadIdx.x + s];
        __syncthreads();
    }
    const float scale = rsqrtf(red[0] / (float)W + 1e-6f);
    for (int c = threadIdx.x; c < W; c += 256) p[c] = p[c] * scale * w[c];
}

// ---------------- RoPE ----------------
__device__ __forceinline__ void rope_pair(float* base, int t, int lane)
{
    float xe = base[2*lane], xo = base[2*lane + 1];
    float inv = 1.0f / powf(10000.0f, (2.0f * (float)lane) / 64.0f);
    float ph = (float)t * inv;
    float sn, cs;
    sincosf(ph, &sn, &cs);
    __syncwarp();
    base[lane]      = xe*cs - xo*sn;
    base[lane + 32] = xo*cs + xe*sn;
}

__global__ void rope_k_kernel(float* __restrict__ ckv)
{
    const int row = blockIdx.x;
    rope_pair(ckv + (size_t)row*CKV_LD + KVLORA, row % S_LEN, threadIdx.x & 31);
}

__global__ void rope_q_kernel(float* __restrict__ q)
{
    const int row = blockIdx.x;
    const int h = threadIdx.x >> 5, lane = threadIdx.x & 31;
    rope_pair(q + (size_t)row*Q_LD + h*DQ + DNOPE, row % S_LEN, lane);
}

// ---------------- tensor-core causal flash attention ----------------
// Br=128 (8 warps x 16 rows), Bc=32, double-buffered cp.async K/V.
// Q: 128 x FQ (tf32-converted at stage). K/V raw fp32, cvt at fragment load.
#define FQ 196
#define FK 196
#define FV 136
#define FP 36
#define BR 128
#define BC 32
#define FLASH_SMEM ((BR*FQ + 2*BC*FK + 2*BC*FV + BR*FP)*4)

__global__ __launch_bounds__(256) void flash_tc_kernel(
    const float* __restrict__ q, const float* __restrict__ kv,
    const float* __restrict__ ckv, float* __restrict__ attn)
{
    extern __shared__ float smf[];
    float* Qs = smf;                   // BR x FQ
    float* Ks = Qs + BR*FQ;            // 2 x BC x FK
    float* Vs = Ks + 2*BC*FK;          // 2 x BC x FV
    float* Ps = Vs + 2*BC*FV;          // BR x FP

    const int tid  = threadIdx.x;
    const int lane = tid & 31;
    const int warp = tid >> 5;
    const int gr   = lane >> 2;
    const int tc   = lane & 3;
    const int qt = (gridDim.x - 1) - blockIdx.x;   // heavy tiles first
    const int b  = blockIdx.y >> 4;
    const int h  = blockIdx.y & 15;
    const float scale = 0.07216878364870323f; // 1/sqrt(192)

    const int qrow0 = b*S_LEN + qt*BR;
    const int wr0   = warp * 16;

    // K chunk assignment: 32x48 float4 = 1536 chunks, 6 per thread
    const int kcr = tid / 48;            // rows kcr + 16/3... (c=tid+i*256: r=c/48)
    // (computed per-chunk below since 256 % 48 != 0)
    // V chunk assignment: 32x32 = 1024 chunks, 4 per thread
    const int vr = tid >> 5;             // rows vr + 8i
    const int vc = (tid & 31) * 4;

    uint32_t ksm[2], vsm[2];
    ksm[0] = (uint32_t)__cvta_generic_to_shared(Ks);
    ksm[1] = (uint32_t)__cvta_generic_to_shared(Ks + BC*FK);
    vsm[0] = (uint32_t)__cvta_generic_to_shared(Vs + vr*FV + vc);
    vsm[1] = (uint32_t)__cvta_generic_to_shared(Vs + BC*FV + vr*FV + vc);

    // load Q tile (128 x 192), tf32-converted
#pragma unroll
    for (int t = 0; t < 24; t++) {
        int idx = tid + t*256;
        int r = idx / 48, c4 = (idx % 48) * 4;
        float4 v = *(const float4*)(q + (size_t)(qrow0 + r)*Q_LD + h*DQ + c4);
        *(float4*)&Qs[r*FQ + c4] = cvt4(v);
    }

    float m0 = -INFINITY, m1 = -INFINITY, l0 = 0.f, l1 = 0.f;
    float o[16][4];
#pragma unroll
    for (int nt = 0; nt < 16; nt++)
#pragma unroll
        for (int r = 0; r < 4; r++) o[nt][r] = 0.f;

    const int jmax = 4*qt + 3;

    // issue tile j into buffer buf
    auto issue_tile = [&](int j, int buf) {
        const int krow0 = b*S_LEN + j*BC;
#pragma unroll
        for (int t = 0; t < 6; t++) {
            int idx = tid + t*256;
            int r = idx / 48, col = (idx % 48) * 4;
            const float* src;
            if (col < DNOPE)
                src = kv + (size_t)(krow0 + r)*KV_LD + h*256 + col;
            else
                src = ckv + (size_t)(krow0 + r)*CKV_LD + KVLORA + (col - DNOPE);
            CP_ASYNC16(ksm[buf] + (uint32_t)(r*FK + col)*4, src);
        }
#pragma unroll
        for (int t = 0; t < 4; t++) {
            const float* src = kv + (size_t)(krow0 + vr + t*8)*KV_LD + h*256 + DNOPE + vc;
            CP_ASYNC16(vsm[buf] + (uint32_t)(t*8*FV)*4, src);
        }
    };

    // prologue: tile 0 -> buf 0
    issue_tile(0, 0);
    CP_COMMIT();

    for (int j = 0; j <= jmax; j++) {
        __syncthreads();                 // prior-iter reads of buf (j+1)&1 done
        if (j + 1 <= jmax) issue_tile(j + 1, (j + 1) & 1);
        CP_COMMIT();
        CP_WAIT1();                      // tile j landed
        __syncthreads();                 // visible to all warps

        const int off = j*BC - qt*BR;    // col_local - row_local offset
        if (off > wr0 + 15) continue;    // block fully above diagonal for this warp
        const bool needMask = (off + BC - 1 > wr0);

        const float* Ksb = Ks + (j & 1)*BC*FK;
        const float* Vsb = Vs + (j & 1)*BC*FV;

        // ---- S = Q K^T (warp: 16 x 32) ----
        float accS[4][4];
#pragma unroll
        for (int nt = 0; nt < 4; nt++)
#pragma unroll
            for (int r = 0; r < 4; r++) accS[nt][r] = 0.f;

#pragma unroll
        for (int k = 0; k < 24; k++) {
            const int k0 = k * 8;
            uint32_t a0 = __float_as_uint(Qs[(wr0 + gr)*FQ     + k0 + tc]);
            uint32_t a1 = __float_as_uint(Qs[(wr0 + gr + 8)*FQ + k0 + tc]);
            uint32_t a2 = __float_as_uint(Qs[(wr0 + gr)*FQ     + k0 + tc + 4]);
            uint32_t a3 = __float_as_uint(Qs[(wr0 + gr + 8)*FQ + k0 + tc + 4]);
#pragma unroll
            for (int nt = 0; nt < 4; nt++) {
                uint32_t b0 = to_tf32u(Ksb[(nt*8 + gr)*FK + k0 + tc]);
                uint32_t b1 = to_tf32u(Ksb[(nt*8 + gr)*FK + k0 + tc + 4]);
                MMA_TF32(accS[nt], a0, a1, a2, a3, b0, b1);
            }
        }

        // ---- scale + (diag-only) causal mask ----
        if (needMask) {
            const int r0 = wr0 + gr, r1 = r0 + 8;
#pragma unroll
            for (int nt = 0; nt < 4; nt++) {
                const int c0 = nt*8 + 2*tc + off;
                accS[nt][0] = (c0     <= r0) ? accS[nt][0]*scale : -INFINITY;
                accS[nt][1] = (c0 + 1 <= r0) ? accS[nt][1]*scale : -INFINITY;
                accS[nt][2] = (c0     <= r1) ? accS[nt][2]*scale : -INFINITY;
                accS[nt][3] = (c0 + 1 <= r1) ? accS[nt][3]*scale : -INFINITY;
            }
        } else {
#pragma unroll
            for (int nt = 0; nt < 4; nt++)
#pragma unroll
                for (int r = 0; r < 4; r++) accS[nt][r] *= scale;
        }

        // ---- online softmax ----
        float rm0 = -INFINITY, rm1 = -INFINITY;
#pragma unroll
        for (int nt = 0; nt < 4; nt++) {
            rm0 = fmaxf(rm0, fmaxf(accS[nt][0], accS[nt][1]));
            rm1 = fmaxf(rm1, fmaxf(accS[nt][2], accS[nt][3]));
        }
        rm0 = fmaxf(rm0, __shfl_xor_sync(0xffffffffu, rm0, 1));
        rm0 = fmaxf(rm0, __shfl_xor_sync(0xffffffffu, rm0, 2));
        rm1 = fmaxf(rm1, __shfl_xor_sync(0xffffffffu, rm1, 1));
        rm1 = fmaxf(rm1, __shfl_xor_sync(0xffffffffu, rm1, 2));

        const float mn0 = fmaxf(m0, rm0), mn1 = fmaxf(m1, rm1);
        const float al0 = __expf(m0 - mn0), al1 = __expf(m1 - mn1);
        m0 = mn0; m1 = mn1;

        float rs0 = 0.f, rs1 = 0.f;
#pragma unroll
        for (int nt = 0; nt < 4; nt++) {
            float p0 = __expf(accS[nt][0] - mn0);
            float p1 = __expf(accS[nt][1] - mn0);
            float p2 = __expf(accS[nt][2] - mn1);
            float p3 = __expf(accS[nt][3] - mn1);
            rs0 += p0 + p1; rs1 += p2 + p3;
            const int c0 = nt*8 + 2*tc;
            Ps[(wr0 + gr)*FP + c0]     = to_tf32(p0);
            Ps[(wr0 + gr)*FP + c0 + 1] = to_tf32(p1);
            Ps[(wr0 + gr + 8)*FP + c0]     = to_tf32(p2);
            Ps[(wr0 + gr + 8)*FP + c0 + 1] = to_tf32(p3);
        }
        rs0 += __shfl_xor_sync(0xffffffffu, rs0, 1);
        rs0 += __shfl_xor_sync(0xffffffffu, rs0, 2);
        rs1 += __shfl_xor_sync(0xffffffffu, rs1, 1);
        rs1 += __shfl_xor_sync(0xffffffffu, rs1, 2);
        l0 = l0*al0 + rs0;
        l1 = l1*al1 + rs1;

#pragma unroll
        for (int nt = 0; nt < 16; nt++) {
            o[nt][0] *= al0; o[nt][1] *= al0;
            o[nt][2] *= al1; o[nt][3] *= al1;
        }
        __syncwarp();

        // ---- O += P V (warp: 16 x 128, k=32) ----
#pragma unroll
        for (int k = 0; k < 4; k++) {
            const int k0 = k * 8;
            uint32_t a0 = __float_as_uint(Ps[(wr0 + gr)*FP     + k0 + tc]);
            uint32_t a1 = __float_as_uint(Ps[(wr0 + gr + 8)*FP + k0 + tc]);
            uint32_t a2 = __float_as_uint(Ps[(wr0 + gr)*FP     + k0 + tc + 4]);
            uint32_t a3 = __float_as_uint(Ps[(wr0 + gr + 8)*FP + k0 + tc + 4]);
#pragma unroll
            for (int nt = 0; nt < 16; nt++) {
                uint32_t b0 = to_tf32u(Vsb[(k0 + tc)*FV     + nt*8 + gr]);
                uint32_t b1 = to_tf32u(Vsb[(k0 + tc + 4)*FV + nt*8 + gr]);
                MMA_TF32(o[nt], a0, a1, a2, a3, b0, b1);
            }
        }
    }

    // ---- epilogue ----
    const float il0 = 1.0f / l0, il1 = 1.0f / l1;
    const int row0 = qrow0 + wr0 + gr;
#pragma unroll
    for (int nt = 0; nt < 16; nt++) {
        const int col = h*DV + nt*8 + 2*tc;
        *(float2*)&attn[(size_t)row0*ATTN_LD + col] =
            make_float2(o[nt][0]*il0, o[nt][1]*il0);
        *(float2*)&attn[(size_t)(row0 + 8)*ATTN_LD + col] =
            make_float2(o[nt][2]*il1, o[nt][3]*il1);
    }
}

// ---------------- launch ----------------
extern "C" void kernel_launch(void* const* d_in, const int* in_sizes, int n_in,
                              void* d_out, int out_size)
{
    const float* hid    = (const float*)d_in[0];
    const float* w_dq   = (const float*)d_in[1];
    const float* q_ln   = (const float*)d_in[2];
    const float* w_uq   = (const float*)d_in[3];
    const float* kv_a_w = (const float*)d_in[4];
    const float* kv_ln  = (const float*)d_in[5];
    const float* kv_b_w = (const float*)d_in[6];
    const float* o_w    = (const float*)d_in[7];
    float* out = (float*)d_out;

    float *qa, *qbuf, *ckv, *kvbuf, *attn;
    cudaGetSymbolAddress((void**)&qa,   g_qa);
    cudaGetSymbolAddress((void**)&qbuf, g_q);
    cudaGetSymbolAddress((void**)&ckv,  g_ckv);
    cudaGetSymbolAddress((void**)&kvbuf,g_kv);
    cudaGetSymbolAddress((void**)&attn, g_attn);

    cudaFuncSetAttribute(flash_tc_kernel, cudaFuncAttributeMaxDynamicSharedMemorySize, FLASH_SMEM);

    // q_a = hidden @ w_dq                       [4096,1536] k=2048
    tf32_gemm<<<dim3(QLORA/128, NROWS/128), 256>>>(hid, w_dq, qa,
        NROWS, QLORA, HIDDEN, HIDDEN, QLORA, QLORA);
    // ckv_pe = hidden @ kv_a_w                  [4096,576]  k=2048
    tf32_gemm<<<dim3((CKV_LD+127)/128, NROWS/128), 256>>>(hid, kv_a_w, ckv,
        NROWS, CKV_LD, HIDDEN, HIDDEN, CKV_LD, CKV_LD);
    // RMSNorms (in place)
    rmsnorm_kernel<<<NROWS, 256>>>(qa,  q_ln,  QLORA,  QLORA);
    rmsnorm_kernel<<<NROWS, 256>>>(ckv, kv_ln, KVLORA, CKV_LD);
    // RoPE k_pe (in place on ckv cols 512..575)
    rope_k_kernel<<<NROWS, 32>>>(ckv);
    // q = q_a_ln @ w_uq                         [4096,3072] k=1536
    tf32_gemm<<<dim3(Q_LD/128, NROWS/128), 256>>>(qa, w_uq, qbuf,
        NROWS, Q_LD, QLORA, QLORA, Q_LD, Q_LD);
    // RoPE q_pe per head (in place)
    rope_q_kernel<<<NROWS, 512>>>(qbuf);
    // kv = ckv_ln @ kv_b_w                      [4096,4096] k=512
    tf32_gemm<<<dim3(KV_LD/128, NROWS/128), 256>>>(ckv, kv_b_w, kvbuf,
        NROWS, KV_LD, KVLORA, CKV_LD, KV_LD, KV_LD);
    // tensor-core causal flash attention -> attn [4096, 2048]
    flash_tc_kernel<<<dim3(S_LEN/BR, BATCH*NH), 256, FLASH_SMEM>>>(qbuf, kvbuf, ckv, attn);
    // out = attn @ o_w                          [4096,2048] k=2048
    tf32_gemm<<<dim3(HIDDEN/128, NROWS/128), 256>>>(attn, o_w, out,
        NROWS, HIDDEN, ATTN_LD, ATTN_LD, HIDDEN, HIDDEN);
}

// round 8
// speedup vs baseline: 6.1912x; 1.4411x over previous
#include <cuda_runtime.h>
#include <cuda_fp16.h>
#include <math.h>
#include <stdint.h>

// ---------------- problem constants ----------------
#define S_LEN   2048
#define BATCH   2
#define HIDDEN  2048
#define NH      16
#define QLORA   1536
#define KVLORA  512
#define DNOPE   128
#define DROPE   64
#define DV      128
#define DQ      192           // DNOPE + DROPE
#define NROWS   (BATCH*S_LEN) // 4096
#define CKV_LD  (KVLORA + DROPE) // 576
#define KV_LD   (NH*(DNOPE+DV))  // 4096
#define Q_LD    (NH*DQ)          // 3072
#define ATTN_LD (NH*DV)          // 2048

// ---------------- scratch (device globals; no runtime alloc) ----------------
__device__ float  g_qa  [(size_t)NROWS*QLORA];     // fp32 GEMM outputs
__device__ float  g_q   [(size_t)NROWS*Q_LD];
__device__ float  g_ckv [(size_t)NROWS*CKV_LD];
__device__ float  g_kv  [(size_t)NROWS*KV_LD];
// half operands for fp16 GEMMs
__device__ __half g_hidh [(size_t)NROWS*HIDDEN];
__device__ __half g_qah  [(size_t)NROWS*QLORA];
__device__ __half g_ckvh [(size_t)NROWS*KVLORA];
__device__ __half g_attnh[(size_t)NROWS*ATTN_LD];
__device__ __half g_wdqT [(size_t)QLORA*HIDDEN];   // [1536][2048]
__device__ __half g_wuqT [(size_t)Q_LD*QLORA];     // [3072][1536]
__device__ __half g_kvaT [(size_t)CKV_LD*HIDDEN];  // [576][2048]
__device__ __half g_kvbT [(size_t)KV_LD*KVLORA];   // [4096][512]
__device__ __half g_owT  [(size_t)HIDDEN*ATTN_LD]; // [2048][2048]

// ---------------- helpers ----------------
__device__ __forceinline__ float to_tf32(float x) {
    uint32_t u;
    asm("cvt.rna.tf32.f32 %0, %1;" : "=r"(u) : "f"(x));
    return __uint_as_float(u);
}
__device__ __forceinline__ uint32_t to_tf32u(float x) {
    uint32_t u;
    asm("cvt.rna.tf32.f32 %0, %1;" : "=r"(u) : "f"(x));
    return u;
}
__device__ __forceinline__ float4 cvt4(float4 v) {
    return make_float4(to_tf32(v.x), to_tf32(v.y), to_tf32(v.z), to_tf32(v.w));
}

#define MMA_TF32(acc, a0,a1,a2,a3, b0,b1)                                       \
    asm volatile(                                                               \
        "mma.sync.aligned.m16n8k8.row.col.f32.tf32.tf32.f32 "                   \
        "{%0,%1,%2,%3}, {%4,%5,%6,%7}, {%8,%9}, {%0,%1,%2,%3};"                 \
        : "+f"(acc[0]), "+f"(acc[1]), "+f"(acc[2]), "+f"(acc[3])                \
        : "r"(a0), "r"(a1), "r"(a2), "r"(a3), "r"(b0), "r"(b1))

#define MMA_F16(acc, a0,a1,a2,a3, b0,b1)                                        \
    asm volatile(                                                               \
        "mma.sync.aligned.m16n8k16.row.col.f32.f16.f16.f32 "                    \
        "{%0,%1,%2,%3}, {%4,%5,%6,%7}, {%8,%9}, {%0,%1,%2,%3};"                 \
        : "+f"(acc[0]), "+f"(acc[1]), "+f"(acc[2]), "+f"(acc[3])                \
        : "r"(a0), "r"(a1), "r"(a2), "r"(a3), "r"(b0), "r"(b1))

#define CP_ASYNC16(dst_u32, src_ptr)                                            \
    asm volatile("cp.async.cg.shared.global [%0], [%1], 16;"                    \
                 :: "r"(dst_u32), "l"(src_ptr))
#define CP_COMMIT() asm volatile("cp.async.commit_group;")
#define CP_WAIT1()  asm volatile("cp.async.wait_group 1;")

__device__ __forceinline__ uint32_t smem_u32(const void* p) {
    uint32_t a;
    asm("{ .reg .u64 t; cvta.to.shared.u64 t, %1; cvt.u32.u64 %0, t; }"
        : "=r"(a) : "l"(p));
    return a;
}

// ---------------- pre-pass kernels ----------------
__global__ void f2h_kernel(const float* __restrict__ src, __half* __restrict__ dst, int n4)
{
    int i = blockIdx.x * 256 + threadIdx.x;
    if (i < n4) {
        float4 v = ((const float4*)src)[i];
        ((__half2*)dst)[2*i]     = __floats2half2_rn(v.x, v.y);
        ((__half2*)dst)[2*i + 1] = __floats2half2_rn(v.z, v.w);
    }
}

// src[R][C] fp32 row-major -> dst[C][R] half row-major
__global__ void transpose_h_kernel(const float* __restrict__ src,
                                   __half* __restrict__ dst, int R, int C)
{
    __shared__ float t[32][33];
    int c  = blockIdx.x * 32 + threadIdx.x;
    int r0 = blockIdx.y * 32 + threadIdx.y;
#pragma unroll
    for (int i = 0; i < 4; i++) {
        int r = r0 + i * 8;
        if (r < R && c < C) t[threadIdx.y + i*8][threadIdx.x] = src[(size_t)r*C + c];
    }
    __syncthreads();
    int c2 = blockIdx.y * 32 + threadIdx.x;   // index into R
    int r2 = blockIdx.x * 32 + threadIdx.y;   // index into C
#pragma unroll
    for (int i = 0; i < 4; i++) {
        int r = r2 + i * 8;
        if (r < C && c2 < R)
            dst[(size_t)r*R + c2] = __float2half_rn(t[threadIdx.x][threadIdx.y + i*8]);
    }
}

// ---------------- fp16 tensor-core GEMM ----------------
// C[M,N](fp32) = A[M,K](half) @ Bt[N,K](half)^T. 128x128 CTA tile, BK=64.
// 3-stage cp.async ring. smem row stride 72 halves (144B; ==8 mod 64 -> frag loads conflict-free).
#define HS 3
#define HBK 64
#define HSTR 72
#define H_TILE_BYTES (128*HSTR*2)
#define H_SMEM (2*HS*H_TILE_BYTES)

__global__ __launch_bounds__(256, 2) void h16_gemm(
    const __half* __restrict__ A, const __half* __restrict__ Bt,
    float* __restrict__ C, int M, int N, int K, int ldc)
{
    extern __shared__ char hsm[];
    const uint32_t smb = smem_u32(hsm);
    const __half* As_h = (const __half*)hsm;
    const __half* Bs_h = (const __half*)(hsm + HS*H_TILE_BYTES);

    const int tid  = threadIdx.x;
    const int lane = tid & 31;
    const int warp = tid >> 5;
    const int wm0  = (warp >> 2) * 64;
    const int wn0  = (warp & 3) * 32;
    const int gr   = lane >> 2;
    const int tc   = lane & 3;

    const int bm = blockIdx.y * 128;
    const int bn = blockIdx.x * 128;

    float acc[4][4][4];
#pragma unroll
    for (int mt = 0; mt < 4; mt++)
#pragma unroll
        for (int nt = 0; nt < 4; nt++)
#pragma unroll
            for (int r = 0; r < 4; r++) acc[mt][nt][r] = 0.0f;

    // staging: tile 128 rows x 128B = 1024 chunks of 16B; 4 per thread per operand
    const int r0 = tid >> 3;   // 0..31
    const int ch = tid & 7;    // 16B chunk in row
    const __half* Asrc[4]; const __half* Bsrc[4];
    uint32_t soff[4];
#pragma unroll
    for (int i = 0; i < 4; i++) {
        const int rr = r0 + 32*i;
        Asrc[i] = A + (size_t)(bm + rr)*K + ch*8;
        int nr = bn + rr; if (nr > N-1) nr = N-1;
        Bsrc[i] = Bt + (size_t)nr*K + ch*8;
        soff[i] = (uint32_t)(rr*144 + ch*16);
    }
    const uint32_t a_base = smb;
    const uint32_t b_base = smb + HS*H_TILE_BYTES;

    const int ntiles = K >> 6;

    auto issue_stage = [&](int t) {
        const int kg = t * HBK;
        const uint32_t as = a_base + (t % HS) * H_TILE_BYTES;
        const uint32_t bs = b_base + (t % HS) * H_TILE_BYTES;
#pragma unroll
        for (int i = 0; i < 4; i++) CP_ASYNC16(as + soff[i], Asrc[i] + kg);
#pragma unroll
        for (int i = 0; i < 4; i++) CP_ASYNC16(bs + soff[i], Bsrc[i] + kg);
    };

    issue_stage(0); CP_COMMIT();
    issue_stage(1); CP_COMMIT();

    for (int kt = 0; kt < ntiles; kt++) {
        CP_WAIT1();
        __syncthreads();
        if (kt + 2 < ntiles) issue_stage(kt + 2);
        CP_COMMIT();

        const __half* At  = As_h + (kt % HS) * (128*HSTR);
        const __half* Bts = Bs_h + (kt % HS) * (128*HSTR);
#pragma unroll
        for (int ks = 0; ks < 4; ks++) {
            const int k0 = ks * 16;
            uint32_t af[4][4], bf[4][2];
#pragma unroll
            for (int mt = 0; mt < 4; mt++) {
                const int row = wm0 + mt*16 + gr;
                af[mt][0] = *(const uint32_t*)(At + row*HSTR     + k0 + 2*tc);
                af[mt][1] = *(const uint32_t*)(At + (row+8)*HSTR + k0 + 2*tc);
                af[mt][2] = *(const uint32_t*)(At + row*HSTR     + k0 + 8 + 2*tc);
                af[mt][3] = *(const uint32_t*)(At + (row+8)*HSTR + k0 + 8 + 2*tc);
            }
#pragma unroll
            for (int nt = 0; nt < 4; nt++) {
                const int cr = wn0 + nt*8 + gr;
                bf[nt][0] = *(const uint32_t*)(Bts + cr*HSTR + k0 + 2*tc);
                bf[nt][1] = *(const uint32_t*)(Bts + cr*HSTR + k0 + 8 + 2*tc);
            }
#pragma unroll
            for (int mt = 0; mt < 4; mt++)
#pragma unroll
                for (int nt = 0; nt < 4; nt++)
                    MMA_F16(acc[mt][nt], af[mt][0], af[mt][1], af[mt][2], af[mt][3],
                            bf[nt][0], bf[nt][1]);
        }
    }

#pragma unroll
    for (int mt = 0; mt < 4; mt++) {
        const int row0 = bm + wm0 + mt * 16 + gr;
#pragma unroll
        for (int nt = 0; nt < 4; nt++) {
            const int col = bn + wn0 + nt * 8 + tc * 2;
            if (col < N) {
                *(float2*)&C[(size_t)row0 * ldc + col] =
                    make_float2(acc[mt][nt][0], acc[mt][nt][1]);
                *(float2*)&C[(size_t)(row0 + 8) * ldc + col] =
                    make_float2(acc[mt][nt][2], acc[mt][nt][3]);
            }
        }
    }
}

// ---------------- RMSNorm: read fp32, write half ----------------
__global__ void rmsnorm_h_kernel(const float* __restrict__ x, const float* __restrict__ w,
                                 __half* __restrict__ dst, int W, int ldin)
{
    __shared__ float red[256];
    const int row = blockIdx.x;
    const float* p = x + (size_t)row*ldin;
    float ss = 0.f;
    for (int c = threadIdx.x; c < W; c += 256) { float v = p[c]; ss += v*v; }
    red[threadIdx.x] = ss;
    __syncthreads();
    for (int s = 128; s; s >>= 1) {
        if (threadIdx.x < s) red[threadIdx.x] += red[threadIdx.x + s];
        __syncthreads();
    }
    const float scale = rsqrtf(red[0] / (float)W + 1e-6f);
    __half* d = dst + (size_t)row*W;
    for (int c = threadIdx.x; c < W; c += 256)
        d[c] = __float2half_rn(p[c] * scale * w[c]);
}

// ---------------- RoPE ----------------
__device__ __forceinline__ void rope_pair(float* base, int t, int lane)
{
    float xe = base[2*lane], xo = base[2*lane + 1];
    float inv = 1.0f / powf(10000.0f, (2.0f * (float)lane) / 64.0f);
    float ph = (float)t * inv;
    float sn, cs;
    sincosf(ph, &sn, &cs);
    __syncwarp();
    base[lane]      = xe*cs - xo*sn;
    base[lane + 32] = xo*cs + xe*sn;
}

__global__ void rope_k_kernel(float* __restrict__ ckv)
{
    const int row = blockIdx.x;
    rope_pair(ckv + (size_t)row*CKV_LD + KVLORA, row % S_LEN, threadIdx.x & 31);
}

__global__ void rope_q_kernel(float* __restrict__ q)
{
    const int row = blockIdx.x;
    const int h = threadIdx.x >> 5, lane = threadIdx.x & 31;
    rope_pair(q + (size_t)row*Q_LD + h*DQ + DNOPE, row % S_LEN, lane);
}

// ---------------- tensor-core causal flash attention (unchanged math) ----------------
// Br=128 (8 warps x 16 rows), Bc=32, double-buffered cp.async K/V. Output -> half attn.
#define FQ 196
#define FK 196
#define FV 136
#define FP 36
#define BR 128
#define BC 32
#define FLASH_SMEM ((BR*FQ + 2*BC*FK + 2*BC*FV + BR*FP)*4)

__global__ __launch_bounds__(256) void flash_tc_kernel(
    const float* __restrict__ q, const float* __restrict__ kv,
    const float* __restrict__ ckv, __half* __restrict__ attn)
{
    extern __shared__ float smf[];
    float* Qs = smf;                   // BR x FQ
    float* Ks = Qs + BR*FQ;            // 2 x BC x FK
    float* Vs = Ks + 2*BC*FK;          // 2 x BC x FV
    float* Ps = Vs + 2*BC*FV;          // BR x FP

    const int tid  = threadIdx.x;
    const int lane = tid & 31;
    const int warp = tid >> 5;
    const int gr   = lane >> 2;
    const int tc   = lane & 3;
    const int qt = (gridDim.x - 1) - blockIdx.x;   // heavy tiles first
    const int b  = blockIdx.y >> 4;
    const int h  = blockIdx.y & 15;
    const float scale = 0.07216878364870323f; // 1/sqrt(192)

    const int qrow0 = b*S_LEN + qt*BR;
    const int wr0   = warp * 16;

    const int vr = tid >> 5;
    const int vc = (tid & 31) * 4;

    uint32_t ksm[2], vsm[2];
    ksm[0] = (uint32_t)__cvta_generic_to_shared(Ks);
    ksm[1] = (uint32_t)__cvta_generic_to_shared(Ks + BC*FK);
    vsm[0] = (uint32_t)__cvta_generic_to_shared(Vs + vr*FV + vc);
    vsm[1] = (uint32_t)__cvta_generic_to_shared(Vs + BC*FV + vr*FV + vc);

#pragma unroll
    for (int t = 0; t < 24; t++) {
        int idx = tid + t*256;
        int r = idx / 48, c4 = (idx % 48) * 4;
        float4 v = *(const float4*)(q + (size_t)(qrow0 + r)*Q_LD + h*DQ + c4);
        *(float4*)&Qs[r*FQ + c4] = cvt4(v);
    }

    float m0 = -INFINITY, m1 = -INFINITY, l0 = 0.f, l1 = 0.f;
    float o[16][4];
#pragma unroll
    for (int nt = 0; nt < 16; nt++)
#pragma unroll
        for (int r = 0; r < 4; r++) o[nt][r] = 0.f;

    const int jmax = 4*qt + 3;

    auto issue_tile = [&](int j, int buf) {
        const int krow0 = b*S_LEN + j*BC;
#pragma unroll
        for (int t = 0; t < 6; t++) {
            int idx = tid + t*256;
            int r = idx / 48, col = (idx % 48) * 4;
            const float* src;
            if (col < DNOPE)
                src = kv + (size_t)(krow0 + r)*KV_LD + h*256 + col;
            else
                src = ckv + (size_t)(krow0 + r)*CKV_LD + KVLORA + (col - DNOPE);
            CP_ASYNC16(ksm[buf] + (uint32_t)(r*FK + col)*4, src);
        }
#pragma unroll
        for (int t = 0; t < 4; t++) {
            const float* src = kv + (size_t)(krow0 + vr + t*8)*KV_LD + h*256 + DNOPE + vc;
            CP_ASYNC16(vsm[buf] + (uint32_t)(t*8*FV)*4, src);
        }
    };

    issue_tile(0, 0);
    CP_COMMIT();

    for (int j = 0; j <= jmax; j++) {
        __syncthreads();
        if (j + 1 <= jmax) issue_tile(j + 1, (j + 1) & 1);
        CP_COMMIT();
        CP_WAIT1();
        __syncthreads();

        const int off = j*BC - qt*BR;
        if (off > wr0 + 15) continue;
        const bool needMask = (off + BC - 1 > wr0);

        const float* Ksb = Ks + (j & 1)*BC*FK;
        const float* Vsb = Vs + (j & 1)*BC*FV;

        float accS[4][4];
#pragma unroll
        for (int nt = 0; nt < 4; nt++)
#pragma unroll
            for (int r = 0; r < 4; r++) accS[nt][r] = 0.f;

#pragma unroll
        for (int k = 0; k < 24; k++) {
            const int k0 = k * 8;
            uint32_t a0 = __float_as_uint(Qs[(wr0 + gr)*FQ     + k0 + tc]);
            uint32_t a1 = __float_as_uint(Qs[(wr0 + gr + 8)*FQ + k0 + tc]);
            uint32_t a2 = __float_as_uint(Qs[(wr0 + gr)*FQ     + k0 + tc + 4]);
            uint32_t a3 = __float_as_uint(Qs[(wr0 + gr + 8)*FQ + k0 + tc + 4]);
#pragma unroll
            for (int nt = 0; nt < 4; nt++) {
                uint32_t b0 = to_tf32u(Ksb[(nt*8 + gr)*FK + k0 + tc]);
                uint32_t b1 = to_tf32u(Ksb[(nt*8 + gr)*FK + k0 + tc + 4]);
                MMA_TF32(accS[nt], a0, a1, a2, a3, b0, b1);
            }
        }

        if (needMask) {
            const int r0 = wr0 + gr, r1 = r0 + 8;
#pragma unroll
            for (int nt = 0; nt < 4; nt++) {
                const int c0 = nt*8 + 2*tc + off;
                accS[nt][0] = (c0     <= r0) ? accS[nt][0]*scale : -INFINITY;
                accS[nt][1] = (c0 + 1 <= r0) ? accS[nt][1]*scale : -INFINITY;
                accS[nt][2] = (c0     <= r1) ? accS[nt][2]*scale : -INFINITY;
                accS[nt][3] = (c0 + 1 <= r1) ? accS[nt][3]*scale : -INFINITY;
            }
        } else {
#pragma unroll
            for (int nt = 0; nt < 4; nt++)
#pragma unroll
                for (int r = 0; r < 4; r++) accS[nt][r] *= scale;
        }

        float rm0 = -INFINITY, rm1 = -INFINITY;
#pragma unroll
        for (int nt = 0; nt < 4; nt++) {
            rm0 = fmaxf(rm0, fmaxf(accS[nt][0], accS[nt][1]));
            rm1 = fmaxf(rm1, fmaxf(accS[nt][2], accS[nt][3]));
        }
        rm0 = fmaxf(rm0, __shfl_xor_sync(0xffffffffu, rm0, 1));
        rm0 = fmaxf(rm0, __shfl_xor_sync(0xffffffffu, rm0, 2));
        rm1 = fmaxf(rm1, __shfl_xor_sync(0xffffffffu, rm1, 1));
        rm1 = fmaxf(rm1, __shfl_xor_sync(0xffffffffu, rm1, 2));

        const float mn0 = fmaxf(m0, rm0), mn1 = fmaxf(m1, rm1);
        const float al0 = __expf(m0 - mn0), al1 = __expf(m1 - mn1);
        m0 = mn0; m1 = mn1;

        float rs0 = 0.f, rs1 = 0.f;
#pragma unroll
        for (int nt = 0; nt < 4; nt++) {
            float p0 = __expf(accS[nt][0] - mn0);
            float p1 = __expf(accS[nt][1] - mn0);
            float p2 = __expf(accS[nt][2] - mn1);
            float p3 = __expf(accS[nt][3] - mn1);
            rs0 += p0 + p1; rs1 += p2 + p3;
            const int c0 = nt*8 + 2*tc;
            Ps[(wr0 + gr)*FP + c0]     = to_tf32(p0);
            Ps[(wr0 + gr)*FP + c0 + 1] = to_tf32(p1);
            Ps[(wr0 + gr + 8)*FP + c0]     = to_tf32(p2);
            Ps[(wr0 + gr + 8)*FP + c0 + 1] = to_tf32(p3);
        }
        rs0 += __shfl_xor_sync(0xffffffffu, rs0, 1);
        rs0 += __shfl_xor_sync(0xffffffffu, rs0, 2);
        rs1 += __shfl_xor_sync(0xffffffffu, rs1, 1);
        rs1 += __shfl_xor_sync(0xffffffffu, rs1, 2);
        l0 = l0*al0 + rs0;
        l1 = l1*al1 + rs1;

#pragma unroll
        for (int nt = 0; nt < 16; nt++) {
            o[nt][0] *= al0; o[nt][1] *= al0;
            o[nt][2] *= al1; o[nt][3] *= al1;
        }
        __syncwarp();

#pragma unroll
        for (int k = 0; k < 4; k++) {
            const int k0 = k * 8;
            uint32_t a0 = __float_as_uint(Ps[(wr0 + gr)*FP     + k0 + tc]);
            uint32_t a1 = __float_as_uint(Ps[(wr0 + gr + 8)*FP + k0 + tc]);
            uint32_t a2 = __float_as_uint(Ps[(wr0 + gr)*FP     + k0 + tc + 4]);
            uint32_t a3 = __float_as_uint(Ps[(wr0 + gr + 8)*FP + k0 + tc + 4]);
#pragma unroll
            for (int nt = 0; nt < 16; nt++) {
                uint32_t b0 = to_tf32u(Vsb[(k0 + tc)*FV     + nt*8 + gr]);
                uint32_t b1 = to_tf32u(Vsb[(k0 + tc + 4)*FV + nt*8 + gr]);
                MMA_TF32(o[nt], a0, a1, a2, a3, b0, b1);
            }
        }
    }

    // epilogue: half output feeds the fp16 output GEMM
    const float il0 = 1.0f / l0, il1 = 1.0f / l1;
    const int row0 = qrow0 + wr0 + gr;
#pragma unroll
    for (int nt = 0; nt < 16; nt++) {
        const int col = h*DV + nt*8 + 2*tc;
        *(__half2*)&attn[(size_t)row0*ATTN_LD + col] =
            __floats2half2_rn(o[nt][0]*il0, o[nt][1]*il0);
        *(__half2*)&attn[(size_t)(row0 + 8)*ATTN_LD + col] =
            __floats2half2_rn(o[nt][2]*il1, o[nt][3]*il1);
    }
}

// ---------------- launch ----------------
extern "C" void kernel_launch(void* const* d_in, const int* in_sizes, int n_in,
                              void* d_out, int out_size)
{
    const float* hid    = (const float*)d_in[0];
    const float* w_dq   = (const float*)d_in[1];
    const float* q_ln   = (const float*)d_in[2];
    const float* w_uq   = (const float*)d_in[3];
    const float* kv_a_w = (const float*)d_in[4];
    const float* kv_ln  = (const float*)d_in[5];
    const float* kv_b_w = (const float*)d_in[6];
    const float* o_w    = (const float*)d_in[7];
    float* out = (float*)d_out;

    float *qa, *qbuf, *ckv, *kvbuf;
    __half *hidh, *qah, *ckvh, *attnh, *wdqT, *wuqT, *kvaT, *kvbT, *owT;
    cudaGetSymbolAddress((void**)&qa,   g_qa);
    cudaGetSymbolAddress((void**)&qbuf, g_q);
    cudaGetSymbolAddress((void**)&ckv,  g_ckv);
    cudaGetSymbolAddress((void**)&kvbuf,g_kv);
    cudaGetSymbolAddress((void**)&hidh, g_hidh);
    cudaGetSymbolAddress((void**)&qah,  g_qah);
    cudaGetSymbolAddress((void**)&ckvh, g_ckvh);
    cudaGetSymbolAddress((void**)&attnh,g_attnh);
    cudaGetSymbolAddress((void**)&wdqT, g_wdqT);
    cudaGetSymbolAddress((void**)&wuqT, g_wuqT);
    cudaGetSymbolAddress((void**)&kvaT, g_kvaT);
    cudaGetSymbolAddress((void**)&kvbT, g_kvbT);
    cudaGetSymbolAddress((void**)&owT,  g_owT);

    cudaFuncSetAttribute(flash_tc_kernel, cudaFuncAttributeMaxDynamicSharedMemorySize, FLASH_SMEM);
    cudaFuncSetAttribute(h16_gemm, cudaFuncAttributeMaxDynamicSharedMemorySize, H_SMEM);

    // pre-pass: hidden -> half; weights -> transposed half [N][K]
    f2h_kernel<<<(NROWS*HIDDEN/4 + 255)/256, 256>>>(hid, hidh, NROWS*HIDDEN/4);
    dim3 tb(32, 8);
    transpose_h_kernel<<<dim3(QLORA/32,  HIDDEN/32), tb>>>(w_dq,   wdqT, HIDDEN, QLORA);
    transpose_h_kernel<<<dim3(CKV_LD/32, HIDDEN/32), tb>>>(kv_a_w, kvaT, HIDDEN, CKV_LD);
    transpose_h_kernel<<<dim3(Q_LD/32,   QLORA/32),  tb>>>(w_uq,   wuqT, QLORA,  Q_LD);
    transpose_h_kernel<<<dim3(KV_LD/32,  KVLORA/32), tb>>>(kv_b_w, kvbT, KVLORA, KV_LD);
    transpose_h_kernel<<<dim3(HIDDEN/32, ATTN_LD/32),tb>>>(o_w,    owT,  ATTN_LD, HIDDEN);

    // q_a = hidden @ w_dq        [4096,1536] k=2048
    h16_gemm<<<dim3(QLORA/128, NROWS/128), 256, H_SMEM>>>(hidh, wdqT, qa,
        NROWS, QLORA, HIDDEN, QLORA);
    // ckv_pe = hidden @ kv_a_w   [4096,576]  k=2048
    h16_gemm<<<dim3((CKV_LD+127)/128, NROWS/128), 256, H_SMEM>>>(hidh, kvaT, ckv,
        NROWS, CKV_LD, HIDDEN, CKV_LD);
    // RMSNorms -> half operands
    rmsnorm_h_kernel<<<NROWS, 256>>>(qa,  q_ln,  qah,  QLORA,  QLORA);
    rmsnorm_h_kernel<<<NROWS, 256>>>(ckv, kv_ln, ckvh, KVLORA, CKV_LD);
    // RoPE k_pe (fp32 ckv cols 512..575, in place)
    rope_k_kernel<<<NROWS, 32>>>(ckv);
    // q = q_a_ln @ w_uq          [4096,3072] k=1536
    h16_gemm<<<dim3(Q_LD/128, NROWS/128), 256, H_SMEM>>>(qah, wuqT, qbuf,
        NROWS, Q_LD, QLORA, Q_LD);
    // RoPE q_pe (fp32, in place)
    rope_q_kernel<<<NROWS, 512>>>(qbuf);
    // kv = ckv_ln @ kv_b_w       [4096,4096] k=512
    h16_gemm<<<dim3(KV_LD/128, NROWS/128), 256, H_SMEM>>>(ckvh, kvbT, kvbuf,
        NROWS, KV_LD, KVLORA, KV_LD);
    // causal flash attention -> attnh (half) [4096, 2048]
    flash_tc_kernel<<<dim3(S_LEN/BR, BATCH*NH), 256, FLASH_SMEM>>>(qbuf, kvbuf, ckv, attnh);
    // out = attn @ o_w           [4096,2048] k=2048
    h16_gemm<<<dim3(HIDDEN/128, NROWS/128), 256, H_SMEM>>>(attnh, owT, out,
        NROWS, HIDDEN, ATTN_LD, HIDDEN);
}

// round 9
// speedup vs baseline: 7.7458x; 1.2511x over previous
#include <cuda_runtime.h>
#include <cuda_fp16.h>
#include <math.h>
#include <stdint.h>

// ---------------- problem constants ----------------
#define S_LEN   2048
#define BATCH   2
#define HIDDEN  2048
#define NH      16
#define QLORA   1536
#define KVLORA  512
#define DNOPE   128
#define DROPE   64
#define DV      128
#define DQ      192           // DNOPE + DROPE
#define NROWS   (BATCH*S_LEN) // 4096
#define CKV_LD  (KVLORA + DROPE) // 576
#define KV_LD   (NH*(DNOPE+DV))  // 4096
#define Q_LD    (NH*DQ)          // 3072
#define ATTN_LD (NH*DV)          // 2048

// ---------------- scratch (device globals; no runtime alloc) ----------------
__device__ float  g_qa  [(size_t)NROWS*QLORA];     // fp32 GEMM outputs
__device__ float  g_ckv [(size_t)NROWS*CKV_LD];
// half operands
__device__ __half g_hidh [(size_t)NROWS*HIDDEN];
__device__ __half g_qah  [(size_t)NROWS*QLORA];
__device__ __half g_ckvh [(size_t)NROWS*KVLORA];
__device__ __half g_qh   [(size_t)NROWS*Q_LD];     // q (half, rope in place)
__device__ __half g_kvh  [(size_t)NROWS*KV_LD];    // kv (half, GEMM output)
__device__ __half g_vTh  [(size_t)NH*DV*NROWS];    // V transposed [h][dv][row]
__device__ __half g_kpeh [(size_t)NROWS*DROPE];    // roped k_pe (half)
__device__ __half g_attnh[(size_t)NROWS*ATTN_LD];
__device__ __half g_wdqT [(size_t)QLORA*HIDDEN];
__device__ __half g_wuqT [(size_t)Q_LD*QLORA];
__device__ __half g_kvaT [(size_t)CKV_LD*HIDDEN];
__device__ __half g_kvbT [(size_t)KV_LD*KVLORA];
__device__ __half g_owT  [(size_t)HIDDEN*ATTN_LD];

// ---------------- helpers ----------------
#define MMA_F16(acc, a0,a1,a2,a3, b0,b1)                                        \
    asm volatile(                                                               \
        "mma.sync.aligned.m16n8k16.row.col.f32.f16.f16.f32 "                    \
        "{%0,%1,%2,%3}, {%4,%5,%6,%7}, {%8,%9}, {%0,%1,%2,%3};"                 \
        : "+f"(acc[0]), "+f"(acc[1]), "+f"(acc[2]), "+f"(acc[3])                \
        : "r"(a0), "r"(a1), "r"(a2), "r"(a3), "r"(b0), "r"(b1))

#define CP_ASYNC16(dst_u32, src_ptr)                                            \
    asm volatile("cp.async.cg.shared.global [%0], [%1], 16;"                    \
                 :: "r"(dst_u32), "l"(src_ptr))
#define CP_COMMIT() asm volatile("cp.async.commit_group;")
#define CP_WAIT1()  asm volatile("cp.async.wait_group 1;")

__device__ __forceinline__ uint32_t smem_u32(const void* p) {
    uint32_t a;
    asm("{ .reg .u64 t; cvta.to.shared.u64 t, %1; cvt.u32.u64 %0, t; }"
        : "=r"(a) : "l"(p));
    return a;
}

// ---------------- pre-pass kernels ----------------
__global__ void f2h_kernel(const float* __restrict__ src, __half* __restrict__ dst, int n4)
{
    int i = blockIdx.x * 256 + threadIdx.x;
    if (i < n4) {
        float4 v = ((const float4*)src)[i];
        ((__half2*)dst)[2*i]     = __floats2half2_rn(v.x, v.y);
        ((__half2*)dst)[2*i + 1] = __floats2half2_rn(v.z, v.w);
    }
}

// src[R][C] fp32 row-major -> dst[C][R] half row-major
__global__ void transpose_h_kernel(const float* __restrict__ src,
                                   __half* __restrict__ dst, int R, int C)
{
    __shared__ float t[32][33];
    int c  = blockIdx.x * 32 + threadIdx.x;
    int r0 = blockIdx.y * 32 + threadIdx.y;
#pragma unroll
    for (int i = 0; i < 4; i++) {
        int r = r0 + i * 8;
        if (r < R && c < C) t[threadIdx.y + i*8][threadIdx.x] = src[(size_t)r*C + c];
    }
    __syncthreads();
    int c2 = blockIdx.y * 32 + threadIdx.x;
    int r2 = blockIdx.x * 32 + threadIdx.y;
#pragma unroll
    for (int i = 0; i < 4; i++) {
        int r = r2 + i * 8;
        if (r < C && c2 < R)
            dst[(size_t)r*R + c2] = __float2half_rn(t[threadIdx.x][threadIdx.y + i*8]);
    }
}

// V slice of kvh -> vT[h][dv][row]  (half -> half transpose)
__global__ void vtrans_kernel(const __half* __restrict__ kvh, __half* __restrict__ vT)
{
    __shared__ __half t[32][33];
    const int h   = blockIdx.y >> 2;
    const int dvb = blockIdx.y & 3;
    const int row0 = blockIdx.x * 32;
#pragma unroll
    for (int i = 0; i < 4; i++) {
        int r = row0 + threadIdx.y + i*8;
        t[threadIdx.y + i*8][threadIdx.x] =
            kvh[(size_t)r*KV_LD + h*256 + DNOPE + dvb*32 + threadIdx.x];
    }
    __syncthreads();
#pragma unroll
    for (int i = 0; i < 4; i++) {
        int dv = dvb*32 + threadIdx.y + i*8;
        vT[(size_t)(h*DV + dv)*NROWS + row0 + threadIdx.x] = t[threadIdx.x][threadIdx.y + i*8];
    }
}

// ---------------- fp16 tensor-core GEMM (templated output) ----------------
#define HS 3
#define HBK 64
#define HSTR 72
#define H_TILE_BYTES (128*HSTR*2)
#define H_SMEM (2*HS*H_TILE_BYTES)

template <typename TOut>
__global__ __launch_bounds__(256, 2) void h16_gemm(
    const __half* __restrict__ A, const __half* __restrict__ Bt,
    TOut* __restrict__ C, int M, int N, int K, int ldc)
{
    extern __shared__ char hsm[];
    const uint32_t smb = smem_u32(hsm);
    const __half* As_h = (const __half*)hsm;
    const __half* Bs_h = (const __half*)(hsm + HS*H_TILE_BYTES);

    const int tid  = threadIdx.x;
    const int lane = tid & 31;
    const int warp = tid >> 5;
    const int wm0  = (warp >> 2) * 64;
    const int wn0  = (warp & 3) * 32;
    const int gr   = lane >> 2;
    const int tc   = lane & 3;

    const int bm = blockIdx.y * 128;
    const int bn = blockIdx.x * 128;

    float acc[4][4][4];
#pragma unroll
    for (int mt = 0; mt < 4; mt++)
#pragma unroll
        for (int nt = 0; nt < 4; nt++)
#pragma unroll
            for (int r = 0; r < 4; r++) acc[mt][nt][r] = 0.0f;

    const int r0 = tid >> 3;
    const int ch = tid & 7;
    const __half* Asrc[4]; const __half* Bsrc[4];
    uint32_t soff[4];
#pragma unroll
    for (int i = 0; i < 4; i++) {
        const int rr = r0 + 32*i;
        Asrc[i] = A + (size_t)(bm + rr)*K + ch*8;
        int nr = bn + rr; if (nr > N-1) nr = N-1;
        Bsrc[i] = Bt + (size_t)nr*K + ch*8;
        soff[i] = (uint32_t)(rr*144 + ch*16);
    }
    const uint32_t a_base = smb;
    const uint32_t b_base = smb + HS*H_TILE_BYTES;

    const int ntiles = K >> 6;

    auto issue_stage = [&](int t) {
        const int kg = t * HBK;
        const uint32_t as = a_base + (t % HS) * H_TILE_BYTES;
        const uint32_t bs = b_base + (t % HS) * H_TILE_BYTES;
#pragma unroll
        for (int i = 0; i < 4; i++) CP_ASYNC16(as + soff[i], Asrc[i] + kg);
#pragma unroll
        for (int i = 0; i < 4; i++) CP_ASYNC16(bs + soff[i], Bsrc[i] + kg);
    };

    issue_stage(0); CP_COMMIT();
    issue_stage(1); CP_COMMIT();

    for (int kt = 0; kt < ntiles; kt++) {
        CP_WAIT1();
        __syncthreads();
        if (kt + 2 < ntiles) issue_stage(kt + 2);
        CP_COMMIT();

        const __half* At  = As_h + (kt % HS) * (128*HSTR);
        const __half* Bts = Bs_h + (kt % HS) * (128*HSTR);
#pragma unroll
        for (int ks = 0; ks < 4; ks++) {
            const int k0 = ks * 16;
            uint32_t af[4][4], bf[4][2];
#pragma unroll
            for (int mt = 0; mt < 4; mt++) {
                const int row = wm0 + mt*16 + gr;
                af[mt][0] = *(const uint32_t*)(At + row*HSTR     + k0 + 2*tc);
                af[mt][1] = *(const uint32_t*)(At + (row+8)*HSTR + k0 + 2*tc);
                af[mt][2] = *(const uint32_t*)(At + row*HSTR     + k0 + 8 + 2*tc);
                af[mt][3] = *(const uint32_t*)(At + (row+8)*HSTR + k0 + 8 + 2*tc);
            }
#pragma unroll
            for (int nt = 0; nt < 4; nt++) {
                const int cr = wn0 + nt*8 + gr;
                bf[nt][0] = *(const uint32_t*)(Bts + cr*HSTR + k0 + 2*tc);
                bf[nt][1] = *(const uint32_t*)(Bts + cr*HSTR + k0 + 8 + 2*tc);
            }
#pragma unroll
            for (int mt = 0; mt < 4; mt++)
#pragma unroll
                for (int nt = 0; nt < 4; nt++)
                    MMA_F16(acc[mt][nt], af[mt][0], af[mt][1], af[mt][2], af[mt][3],
                            bf[nt][0], bf[nt][1]);
        }
    }

#pragma unroll
    for (int mt = 0; mt < 4; mt++) {
        const int row0 = bm + wm0 + mt * 16 + gr;
#pragma unroll
        for (int nt = 0; nt < 4; nt++) {
            const int col = bn + wn0 + nt * 8 + tc * 2;
            if (col < N) {
                if constexpr (sizeof(TOut) == 4) {
                    *(float2*)&((float*)C)[(size_t)row0 * ldc + col] =
                        make_float2(acc[mt][nt][0], acc[mt][nt][1]);
                    *(float2*)&((float*)C)[(size_t)(row0 + 8) * ldc + col] =
                        make_float2(acc[mt][nt][2], acc[mt][nt][3]);
                } else {
                    *(__half2*)&((__half*)C)[(size_t)row0 * ldc + col] =
                        __floats2half2_rn(acc[mt][nt][0], acc[mt][nt][1]);
                    *(__half2*)&((__half*)C)[(size_t)(row0 + 8) * ldc + col] =
                        __floats2half2_rn(acc[mt][nt][2], acc[mt][nt][3]);
                }
            }
        }
    }
}

// ---------------- RMSNorm: read fp32, write half ----------------
__global__ void rmsnorm_h_kernel(const float* __restrict__ x, const float* __restrict__ w,
                                 __half* __restrict__ dst, int W, int ldin)
{
    __shared__ float red[256];
    const int row = blockIdx.x;
    const float* p = x + (size_t)row*ldin;
    float ss = 0.f;
    for (int c = threadIdx.x; c < W; c += 256) { float v = p[c]; ss += v*v; }
    red[threadIdx.x] = ss;
    __syncthreads();
    for (int s = 128; s; s >>= 1) {
        if (threadIdx.x < s) red[threadIdx.x] += red[threadIdx.x + s];
        __syncthreads();
    }
    const float scale = rsqrtf(red[0] / (float)W + 1e-6f);
    __half* d = dst + (size_t)row*W;
    for (int c = threadIdx.x; c < W; c += 256)
        d[c] = __float2half_rn(p[c] * scale * w[c]);
}

// ---------------- RoPE ----------------
__global__ void rope_k_h_kernel(const float* __restrict__ ckv, __half* __restrict__ kpeh)
{
    const int row = blockIdx.x;
    const int lane = threadIdx.x & 31;
    const float* base = ckv + (size_t)row*CKV_LD + KVLORA;
    float xe = base[2*lane], xo = base[2*lane + 1];
    float inv = 1.0f / powf(10000.0f, (2.0f * (float)lane) / 64.0f);
    float ph = (float)(row % S_LEN) * inv;
    float sn, cs;
    sincosf(ph, &sn, &cs);
    kpeh[(size_t)row*DROPE + lane]      = __float2half_rn(xe*cs - xo*sn);
    kpeh[(size_t)row*DROPE + lane + 32] = __float2half_rn(xo*cs + xe*sn);
}

__global__ void rope_q_h_kernel(__half* __restrict__ q)
{
    const int row = blockIdx.x;
    const int h = threadIdx.x >> 5, lane = threadIdx.x & 31;
    __half* base = q + (size_t)row*Q_LD + h*DQ + DNOPE;
    float xe = __half2float(base[2*lane]), xo = __half2float(base[2*lane + 1]);
    float inv = 1.0f / powf(10000.0f, (2.0f * (float)lane) / 64.0f);
    float ph = (float)(row % S_LEN) * inv;
    float sn, cs;
    sincosf(ph, &sn, &cs);
    __syncwarp();
    base[lane]      = __float2half_rn(xe*cs - xo*sn);
    base[lane + 32] = __float2half_rn(xo*cs + xe*sn);
}

// ---------------- all-fp16 tensor-core causal flash attention ----------------
// Br=128 (8 warps x 16 rows), Bc=32, double-buffered cp.async K/Vt.
// Strides (halves): Q/K 200 (b32 stride 100 == 4 mod 32); Vt/P 40 (b32 20).
#define FQH 200
#define FVH 40
#define FPH 40
#define BR 128
#define BC 32
#define FLASH_SMEM ((BR*FQH + 2*BC*FQH + 2*DV*FVH + BR*FPH)*2)

__global__ __launch_bounds__(256, 2) void flash_h_kernel(
    const __half* __restrict__ q, const __half* __restrict__ kvh,
    const __half* __restrict__ vT, const __half* __restrict__ kpeh,
    __half* __restrict__ attn)
{
    extern __shared__ __half smh[];
    __half* Qs = smh;                     // BR x FQH
    __half* Ks = Qs + BR*FQH;             // 2 x BC x FQH
    __half* Vt = Ks + 2*BC*FQH;           // 2 x DV x FVH
    __half* Ps = Vt + 2*DV*FVH;           // BR x FPH

    const int tid  = threadIdx.x;
    const int lane = tid & 31;
    const int warp = tid >> 5;
    const int gr   = lane >> 2;
    const int tc   = lane & 3;
    const int qt = (gridDim.x - 1) - blockIdx.x;   // heavy tiles first
    const int b  = blockIdx.y >> 4;
    const int h  = blockIdx.y & 15;
    const float scale = 0.07216878364870323f; // 1/sqrt(192)

    const int qrow0 = b*S_LEN + qt*BR;
    const int wr0   = warp * 16;

    uint32_t ksm[2], vsm[2];
    ksm[0] = smem_u32(Ks);
    ksm[1] = smem_u32(Ks + BC*FQH);
    vsm[0] = smem_u32(Vt);
    vsm[1] = smem_u32(Vt + DV*FVH);

    // load Q tile (128 x 192 halves) -- plain vector copy
#pragma unroll
    for (int t = 0; t < 12; t++) {
        int idx = tid + t*256;
        int r = idx / 24, c = idx % 24;
        *(uint4*)&Qs[r*FQH + c*8] =
            *(const uint4*)(q + (size_t)(qrow0 + r)*Q_LD + h*DQ + c*8);
    }

    float m0 = -INFINITY, m1 = -INFINITY, l0 = 0.f, l1 = 0.f;
    float o[16][4];
#pragma unroll
    for (int nt = 0; nt < 16; nt++)
#pragma unroll
        for (int r = 0; r < 4; r++) o[nt][r] = 0.f;

    const int jmax = 4*qt + 3;

    auto issue_tile = [&](int j, int buf) {
        const int krow0 = b*S_LEN + j*BC;
        // K: 32 rows x 24 chunks (16B = 8 halves); 3 per thread
#pragma unroll
        for (int t = 0; t < 3; t++) {
            int idx = tid + t*256;
            int r = idx / 24, col8 = (idx % 24) * 8;
            const __half* src = (col8 < DNOPE)
                ? kvh + (size_t)(krow0 + r)*KV_LD + h*256 + col8
                : kpeh + (size_t)(krow0 + r)*DROPE + (col8 - DNOPE);
            CP_ASYNC16(ksm[buf] + (uint32_t)(r*FQH + col8)*2, src);
        }
        // Vt: 128 dv-rows x 4 chunks; 2 per thread
#pragma unroll
        for (int t = 0; t < 2; t++) {
            int idx = tid + t*256;
            int r = idx >> 2, c8 = (idx & 3) * 8;
            const __half* src = vT + (size_t)(h*DV + r)*NROWS + krow0 + c8;
            CP_ASYNC16(vsm[buf] + (uint32_t)(r*FVH + c8)*2, src);
        }
    };

    issue_tile(0, 0);
    CP_COMMIT();

    for (int j = 0; j <= jmax; j++) {
        __syncthreads();
        if (j + 1 <= jmax) issue_tile(j + 1, (j + 1) & 1);
        CP_COMMIT();
        CP_WAIT1();
        __syncthreads();

        const int off = j*BC - qt*BR;
        if (off > wr0 + 15) continue;
        const bool needMask = (off + BC - 1 > wr0);

        const __half* Ksb = Ks + (j & 1)*BC*FQH;
        const __half* Vtb = Vt + (j & 1)*DV*FVH;

        // ---- S = Q K^T (warp: 16 x 32), fp16 k16 ----
        float accS[4][4];
#pragma unroll
        for (int nt = 0; nt < 4; nt++)
#pragma unroll
            for (int r = 0; r < 4; r++) accS[nt][r] = 0.f;

#pragma unroll
        for (int k = 0; k < 12; k++) {
            const int k0 = k * 16;
            uint32_t a0 = *(const uint32_t*)(Qs + (wr0 + gr)*FQH     + k0 + 2*tc);
            uint32_t a1 = *(const uint32_t*)(Qs + (wr0 + gr + 8)*FQH + k0 + 2*tc);
            uint32_t a2 = *(const uint32_t*)(Qs + (wr0 + gr)*FQH     + k0 + 8 + 2*tc);
            uint32_t a3 = *(const uint32_t*)(Qs + (wr0 + gr + 8)*FQH + k0 + 8 + 2*tc);
#pragma unroll
            for (int nt = 0; nt < 4; nt++) {
                uint32_t b0 = *(const uint32_t*)(Ksb + (nt*8 + gr)*FQH + k0 + 2*tc);
                uint32_t b1 = *(const uint32_t*)(Ksb + (nt*8 + gr)*FQH + k0 + 8 + 2*tc);
                MMA_F16(accS[nt], a0, a1, a2, a3, b0, b1);
            }
        }

        if (needMask) {
            const int r0 = wr0 + gr, r1 = r0 + 8;
#pragma unroll
            for (int nt = 0; nt < 4; nt++) {
                const int c0 = nt*8 + 2*tc + off;
                accS[nt][0] = (c0     <= r0) ? accS[nt][0]*scale : -INFINITY;
                accS[nt][1] = (c0 + 1 <= r0) ? accS[nt][1]*scale : -INFINITY;
                accS[nt][2] = (c0     <= r1) ? accS[nt][2]*scale : -INFINITY;
                accS[nt][3] = (c0 + 1 <= r1) ? accS[nt][3]*scale : -INFINITY;
            }
        } else {
#pragma unroll
            for (int nt = 0; nt < 4; nt++)
#pragma unroll
                for (int r = 0; r < 4; r++) accS[nt][r] *= scale;
        }

        // ---- online softmax ----
        float rm0 = -INFINITY, rm1 = -INFINITY;
#pragma unroll
        for (int nt = 0; nt < 4; nt++) {
            rm0 = fmaxf(rm0, fmaxf(accS[nt][0], accS[nt][1]));
            rm1 = fmaxf(rm1, fmaxf(accS[nt][2], accS[nt][3]));
        }
        rm0 = fmaxf(rm0, __shfl_xor_sync(0xffffffffu, rm0, 1));
        rm0 = fmaxf(rm0, __shfl_xor_sync(0xffffffffu, rm0, 2));
        rm1 = fmaxf(rm1, __shfl_xor_sync(0xffffffffu, rm1, 1));
        rm1 = fmaxf(rm1, __shfl_xor_sync(0xffffffffu, rm1, 2));

        const float mn0 = fmaxf(m0, rm0), mn1 = fmaxf(m1, rm1);
        const float al0 = __expf(m0 - mn0), al1 = __expf(m1 - mn1);
        m0 = mn0; m1 = mn1;

        float rs0 = 0.f, rs1 = 0.f;
#pragma unroll
        for (int nt = 0; nt < 4; nt++) {
            float p0 = __expf(accS[nt][0] - mn0);
            float p1 = __expf(accS[nt][1] - mn0);
            float p2 = __expf(accS[nt][2] - mn1);
            float p3 = __expf(accS[nt][3] - mn1);
            rs0 += p0 + p1; rs1 += p2 + p3;
            const int c0 = nt*8 + 2*tc;
            *(__half2*)&Ps[(wr0 + gr)*FPH + c0]     = __floats2half2_rn(p0, p1);
            *(__half2*)&Ps[(wr0 + gr + 8)*FPH + c0] = __floats2half2_rn(p2, p3);
        }
        rs0 += __shfl_xor_sync(0xffffffffu, rs0, 1);
        rs0 += __shfl_xor_sync(0xffffffffu, rs0, 2);
        rs1 += __shfl_xor_sync(0xffffffffu, rs1, 1);
        rs1 += __shfl_xor_sync(0xffffffffu, rs1, 2);
        l0 = l0*al0 + rs0;
        l1 = l1*al1 + rs1;

#pragma unroll
        for (int nt = 0; nt < 16; nt++) {
            o[nt][0] *= al0; o[nt][1] *= al0;
            o[nt][2] *= al1; o[nt][3] *= al1;
        }
        __syncwarp();

        // ---- O += P V (warp: 16 x 128), fp16 k16 x 2 ----
#pragma unroll
        for (int k = 0; k < 2; k++) {
            const int k0 = k * 16;
            uint32_t a0 = *(const uint32_t*)(Ps + (wr0 + gr)*FPH     + k0 + 2*tc);
            uint32_t a1 = *(const uint32_t*)(Ps + (wr0 + gr + 8)*FPH + k0 + 2*tc);
            uint32_t a2 = *(const uint32_t*)(Ps + (wr0 + gr)*FPH     + k0 + 8 + 2*tc);
            uint32_t a3 = *(const uint32_t*)(Ps + (wr0 + gr + 8)*FPH + k0 + 8 + 2*tc);
#pragma unroll
            for (int nt = 0; nt < 16; nt++) {
                uint32_t b0 = *(const uint32_t*)(Vtb + (nt*8 + gr)*FVH + k0 + 2*tc);
                uint32_t b1 = *(const uint32_t*)(Vtb + (nt*8 + gr)*FVH + k0 + 8 + 2*tc);
                MMA_F16(o[nt], a0, a1, a2, a3, b0, b1);
            }
        }
    }

    // epilogue: half output feeds the fp16 output GEMM
    const float il0 = 1.0f / l0, il1 = 1.0f / l1;
    const int row0 = qrow0 + wr0 + gr;
#pragma unroll
    for (int nt = 0; nt < 16; nt++) {
        const int col = h*DV + nt*8 + 2*tc;
        *(__half2*)&attn[(size_t)row0*ATTN_LD + col] =
            __floats2half2_rn(o[nt][0]*il0, o[nt][1]*il0);
        *(__half2*)&attn[(size_t)(row0 + 8)*ATTN_LD + col] =
            __floats2half2_rn(o[nt][2]*il1, o[nt][3]*il1);
    }
}

// ---------------- launch ----------------
extern "C" void kernel_launch(void* const* d_in, const int* in_sizes, int n_in,
                              void* d_out, int out_size)
{
    const float* hid    = (const float*)d_in[0];
    const float* w_dq   = (const float*)d_in[1];
    const float* q_ln   = (const float*)d_in[2];
    const float* w_uq   = (const float*)d_in[3];
    const float* kv_a_w = (const float*)d_in[4];
    const float* kv_ln  = (const float*)d_in[5];
    const float* kv_b_w = (const float*)d_in[6];
    const float* o_w    = (const float*)d_in[7];
    float* out = (float*)d_out;

    float *qa, *ckv;
    __half *hidh, *qah, *ckvh, *qh, *kvh, *vTh, *kpeh, *attnh;
    __half *wdqT, *wuqT, *kvaT, *kvbT, *owT;
    cudaGetSymbolAddress((void**)&qa,   g_qa);
    cudaGetSymbolAddress((void**)&ckv,  g_ckv);
    cudaGetSymbolAddress((void**)&hidh, g_hidh);
    cudaGetSymbolAddress((void**)&qah,  g_qah);
    cudaGetSymbolAddress((void**)&ckvh, g_ckvh);
    cudaGetSymbolAddress((void**)&qh,   g_qh);
    cudaGetSymbolAddress((void**)&kvh,  g_kvh);
    cudaGetSymbolAddress((void**)&vTh,  g_vTh);
    cudaGetSymbolAddress((void**)&kpeh, g_kpeh);
    cudaGetSymbolAddress((void**)&attnh,g_attnh);
    cudaGetSymbolAddress((void**)&wdqT, g_wdqT);
    cudaGetSymbolAddress((void**)&wuqT, g_wuqT);
    cudaGetSymbolAddress((void**)&kvaT, g_kvaT);
    cudaGetSymbolAddress((void**)&kvbT, g_kvbT);
    cudaGetSymbolAddress((void**)&owT,  g_owT);

    cudaFuncSetAttribute(flash_h_kernel, cudaFuncAttributeMaxDynamicSharedMemorySize, FLASH_SMEM);
    cudaFuncSetAttribute(h16_gemm<float>, cudaFuncAttributeMaxDynamicSharedMemorySize, H_SMEM);
    cudaFuncSetAttribute(h16_gemm<__half>, cudaFuncAttributeMaxDynamicSharedMemorySize, H_SMEM);

    // pre-pass
    f2h_kernel<<<(NROWS*HIDDEN/4 + 255)/256, 256>>>(hid, hidh, NROWS*HIDDEN/4);
    dim3 tb(32, 8);
    transpose_h_kernel<<<dim3(QLORA/32,  HIDDEN/32), tb>>>(w_dq,   wdqT, HIDDEN, QLORA);
    transpose_h_kernel<<<dim3(CKV_LD/32, HIDDEN/32), tb>>>(kv_a_w, kvaT, HIDDEN, CKV_LD);
    transpose_h_kernel<<<dim3(Q_LD/32,   QLORA/32),  tb>>>(w_uq,   wuqT, QLORA,  Q_LD);
    transpose_h_kernel<<<dim3(KV_LD/32,  KVLORA/32), tb>>>(kv_b_w, kvbT, KVLORA, KV_LD);
    transpose_h_kernel<<<dim3(HIDDEN/32, ATTN_LD/32),tb>>>(o_w,    owT,  ATTN_LD, HIDDEN);

    // q_a = hidden @ w_dq        [4096,1536] k=2048 (fp32 out)
    h16_gemm<float><<<dim3(QLORA/128, NROWS/128), 256, H_SMEM>>>(hidh, wdqT, qa,
        NROWS, QLORA, HIDDEN, QLORA);
    // ckv_pe = hidden @ kv_a_w   [4096,576]  k=2048 (fp32 out)
    h16_gemm<float><<<dim3((CKV_LD+127)/128, NROWS/128), 256, H_SMEM>>>(hidh, kvaT, ckv,
        NROWS, CKV_LD, HIDDEN, CKV_LD);
    // RMSNorms -> half operands
    rmsnorm_h_kernel<<<NROWS, 256>>>(qa,  q_ln,  qah,  QLORA,  QLORA);
    rmsnorm_h_kernel<<<NROWS, 256>>>(ckv, kv_ln, ckvh, KVLORA, CKV_LD);
    // RoPE k_pe: ckv fp32 -> kpeh half
    rope_k_h_kernel<<<NROWS, 32>>>(ckv, kpeh);
    // q = q_a_ln @ w_uq          [4096,3072] k=1536 (half out)
    h16_gemm<__half><<<dim3(Q_LD/128, NROWS/128), 256, H_SMEM>>>(qah, wuqT, qh,
        NROWS, Q_LD, QLORA, Q_LD);
    // RoPE q_pe in place on half q
    rope_q_h_kernel<<<NROWS, 512>>>(qh);
    // kv = ckv_ln @ kv_b_w       [4096,4096] k=512 (half out)
    h16_gemm<__half><<<dim3(KV_LD/128, NROWS/128), 256, H_SMEM>>>(ckvh, kvbT, kvh,
        NROWS, KV_LD, KVLORA, KV_LD);
    // V transpose: kvh -> vT[h][dv][row]
    vtrans_kernel<<<dim3(NROWS/32, NH*4), tb>>>(kvh, vTh);
    // all-fp16 causal flash attention -> attnh
    flash_h_kernel<<<dim3(S_LEN/BR, BATCH*NH), 256, FLASH_SMEM>>>(qh, kvh, vTh, kpeh, attnh);
    // out = attn @ o_w           [4096,2048] k=2048 (fp32 out)
    h16_gemm<float><<<dim3(HIDDEN/128, NROWS/128), 256, H_SMEM>>>(attnh, owT, out,
        NROWS, HIDDEN, ATTN_LD, HIDDEN);
}

// round 11
// speedup vs baseline: 8.0426x; 1.0383x over previous
#include <cuda_runtime.h>
#include <cuda_fp16.h>
#include <math.h>
#include <stdint.h>

// ---------------- problem constants ----------------
#define S_LEN   2048
#define BATCH   2
#define HIDDEN  2048
#define NH      16
#define QLORA   1536
#define KVLORA  512
#define DNOPE   128
#define DROPE   64
#define DV      128
#define DQ      192           // DNOPE + DROPE
#define NROWS   (BATCH*S_LEN) // 4096
#define CKV_LD  (KVLORA + DROPE) // 576
#define KV_LD   (NH*(DNOPE+DV))  // 4096
#define Q_LD    (NH*DQ)          // 3072
#define ATTN_LD (NH*DV)          // 2048
#define NFUSE   (QLORA + CKV_LD) // 2112

// ---------------- scratch (device globals; no runtime alloc) ----------------
__device__ __half g_hidh  [(size_t)NROWS*HIDDEN];
__device__ __half g_qaraw [(size_t)NROWS*QLORA];    // pre-norm q_a (half)
__device__ __half g_ckvall[(size_t)NROWS*CKV_LD];   // pre-norm ckv + pe (half)
__device__ __half g_qah   [(size_t)NROWS*QLORA];    // normed
__device__ __half g_ckvh  [(size_t)NROWS*KVLORA];   // normed
__device__ __half g_qh    [(size_t)NROWS*Q_LD];     // q (half, rope in place)
__device__ __half g_kvh   [(size_t)NROWS*KV_LD];    // kv (half)
__device__ __half g_vTh   [(size_t)NH*DV*NROWS];    // V transposed [h][dv][row]
__device__ __half g_kpeh  [(size_t)NROWS*DROPE];    // roped k_pe (half)
__device__ __half g_attnh [(size_t)NROWS*ATTN_LD];
__device__ __half g_wAT   [(size_t)NFUSE*HIDDEN];   // [wdq^T ; kva^T] : [2112][2048]
__device__ __half g_wuqT  [(size_t)Q_LD*QLORA];
__device__ __half g_kvbT  [(size_t)KV_LD*KVLORA];
__device__ __half g_owT   [(size_t)HIDDEN*ATTN_LD];

// ---------------- helpers ----------------
#define MMA_F16(acc, a0,a1,a2,a3, b0,b1)                                        \
    asm volatile(                                                               \
        "mma.sync.aligned.m16n8k16.row.col.f32.f16.f16.f32 "                    \
        "{%0,%1,%2,%3}, {%4,%5,%6,%7}, {%8,%9}, {%0,%1,%2,%3};"                 \
        : "+f"(acc[0]), "+f"(acc[1]), "+f"(acc[2]), "+f"(acc[3])                \
        : "r"(a0), "r"(a1), "r"(a2), "r"(a3), "r"(b0), "r"(b1))

#define CP_ASYNC16(dst_u32, src_ptr)                                            \
    asm volatile("cp.async.cg.shared.global [%0], [%1], 16;"                    \
                 :: "r"(dst_u32), "l"(src_ptr))
#define CP_COMMIT() asm volatile("cp.async.commit_group;")
#define CP_WAIT1()  asm volatile("cp.async.wait_group 1;")

__device__ __forceinline__ uint32_t smem_u32(const void* p) {
    uint32_t a;
    asm("{ .reg .u64 t; cvta.to.shared.u64 t, %1; cvt.u32.u64 %0, t; }"
        : "=r"(a) : "l"(p));
    return a;
}

// ---------------- pre-pass kernels ----------------
__global__ void f2h_kernel(const float* __restrict__ src, __half* __restrict__ dst, int n4)
{
    int i = blockIdx.x * 256 + threadIdx.x;
    if (i < n4) {
        float4 v = ((const float4*)src)[i];
        ((__half2*)dst)[2*i]     = __floats2half2_rn(v.x, v.y);
        ((__half2*)dst)[2*i + 1] = __floats2half2_rn(v.z, v.w);
    }
}

// Fused transpose of all 5 weight matrices: src[R][C] fp32 -> dst[C][R] half.
// 64(R) x 32(C) tiles, half2 coalesced stores. Stride 66 (EVEN -> float2-aligned).
struct TJob { const float* src; __half* dst; int R, C, tile0; };

__global__ __launch_bounds__(256) void transpose5_kernel(TJob j0, TJob j1, TJob j2, TJob j3, TJob j4)
{
    __shared__ float t[32][66];
    const int bid = blockIdx.x;
    TJob j;
    if      (bid < j1.tile0) j = j0;
    else if (bid < j2.tile0) j = j1;
    else if (bid < j3.tile0) j = j2;
    else if (bid < j4.tile0) j = j3;
    else                     j = j4;
    const int t_local = bid - j.tile0;
    const int rtiles  = j.R >> 6;
    const int tr = t_local % rtiles;          // 64-row block in src
    const int tcb = t_local / rtiles;         // 32-col block in src
    const int rbase = tr * 64, cbase = tcb * 32;
    const int tx = threadIdx.x & 31, ty = threadIdx.x >> 5;

    // read 64 x 32 fp32 tile: t[c_local][r_local]
#pragma unroll
    for (int it = 0; it < 8; it++) {
        int r = ty + it*8;
        t[tx][r] = j.src[(size_t)(rbase + r)*j.C + cbase + tx];
    }
    __syncthreads();
    // write: dst rows = c (32 of them), each row 64 halves (32 lanes x half2)
#pragma unroll
    for (int jj = 0; jj < 4; jj++) {
        int c = ty + jj*8;
        float2 v = *(float2*)&t[c][2*tx];
        *(__half2*)&j.dst[(size_t)(cbase + c)*j.R + rbase + 2*tx] =
            __floats2half2_rn(v.x, v.y);
    }
}

// V slice of kvh -> vT[h][dv][row]
__global__ void vtrans_kernel(const __half* __restrict__ kvh, __half* __restrict__ vT)
{
    __shared__ __half t[32][33];
    const int h   = blockIdx.y >> 2;
    const int dvb = blockIdx.y & 3;
    const int row0 = blockIdx.x * 32;
#pragma unroll
    for (int i = 0; i < 4; i++) {
        int r = row0 + threadIdx.y + i*8;
        t[threadIdx.y + i*8][threadIdx.x] =
            kvh[(size_t)r*KV_LD + h*256 + DNOPE + dvb*32 + threadIdx.x];
    }
    __syncthreads();
#pragma unroll
    for (int i = 0; i < 4; i++) {
        int dv = dvb*32 + threadIdx.y + i*8;
        vT[(size_t)(h*DV + dv)*NROWS + row0 + threadIdx.x] = t[threadIdx.x][threadIdx.y + i*8];
    }
}

// ---------------- fp16 tensor-core GEMM (templated output, split epilogue) ----------------
#define HS 3
#define HBK 64
#define HSTR 72
#define H_TILE_BYTES (128*HSTR*2)
#define H_SMEM (2*HS*H_TILE_BYTES)

template <typename TOut>
__global__ __launch_bounds__(256, 2) void h16_gemm(
    const __half* __restrict__ A, const __half* __restrict__ Bt,
    TOut* __restrict__ C, int M, int N, int K, int ldc,
    TOut* __restrict__ C2, int ldc2, int nsplit)
{
    extern __shared__ char hsm[];
    const uint32_t smb = smem_u32(hsm);
    const __half* As_h = (const __half*)hsm;
    const __half* Bs_h = (const __half*)(hsm + HS*H_TILE_BYTES);

    const int tid  = threadIdx.x;
    const int lane = tid & 31;
    const int warp = tid >> 5;
    const int wm0  = (warp >> 2) * 64;
    const int wn0  = (warp & 3) * 32;
    const int gr   = lane >> 2;
    const int tc   = lane & 3;

    const int bm = blockIdx.y * 128;
    const int bn = blockIdx.x * 128;

    float acc[4][4][4];
#pragma unroll
    for (int mt = 0; mt < 4; mt++)
#pragma unroll
        for (int nt = 0; nt < 4; nt++)
#pragma unroll
            for (int r = 0; r < 4; r++) acc[mt][nt][r] = 0.0f;

    const int r0 = tid >> 3;
    const int ch = tid & 7;
    const __half* Asrc[4]; const __half* Bsrc[4];
    uint32_t soff[4];
#pragma unroll
    for (int i = 0; i < 4; i++) {
        const int rr = r0 + 32*i;
        Asrc[i] = A + (size_t)(bm + rr)*K + ch*8;
        int nr = bn + rr; if (nr > N-1) nr = N-1;
        Bsrc[i] = Bt + (size_t)nr*K + ch*8;
        soff[i] = (uint32_t)(rr*144 + ch*16);
    }
    const uint32_t a_base = smb;
    const uint32_t b_base = smb + HS*H_TILE_BYTES;

    const int ntiles = K >> 6;

    auto issue_stage = [&](int t) {
        const int kg = t * HBK;
        const uint32_t as = a_base + (t % HS) * H_TILE_BYTES;
        const uint32_t bs = b_base + (t % HS) * H_TILE_BYTES;
#pragma unroll
        for (int i = 0; i < 4; i++) CP_ASYNC16(as + soff[i], Asrc[i] + kg);
#pragma unroll
        for (int i = 0; i < 4; i++) CP_ASYNC16(bs + soff[i], Bsrc[i] + kg);
    };

    issue_stage(0); CP_COMMIT();
    issue_stage(1); CP_COMMIT();

    for (int kt = 0; kt < ntiles; kt++) {
        CP_WAIT1();
        __syncthreads();
        if (kt + 2 < ntiles) issue_stage(kt + 2);
        CP_COMMIT();

        const __half* At  = As_h + (kt % HS) * (128*HSTR);
        const __half* Bts = Bs_h + (kt % HS) * (128*HSTR);
#pragma unroll
        for (int ks = 0; ks < 4; ks++) {
            const int k0 = ks * 16;
            uint32_t af[4][4], bf[4][2];
#pragma unroll
            for (int mt = 0; mt < 4; mt++) {
                const int row = wm0 + mt*16 + gr;
                af[mt][0] = *(const uint32_t*)(At + row*HSTR     + k0 + 2*tc);
                af[mt][1] = *(const uint32_t*)(At + (row+8)*HSTR + k0 + 2*tc);
                af[mt][2] = *(const uint32_t*)(At + row*HSTR     + k0 + 8 + 2*tc);
                af[mt][3] = *(const uint32_t*)(At + (row+8)*HSTR + k0 + 8 + 2*tc);
            }
#pragma unroll
            for (int nt = 0; nt < 4; nt++) {
                const int cr = wn0 + nt*8 + gr;
                bf[nt][0] = *(const uint32_t*)(Bts + cr*HSTR + k0 + 2*tc);
                bf[nt][1] = *(const uint32_t*)(Bts + cr*HSTR + k0 + 8 + 2*tc);
            }
#pragma unroll
            for (int mt = 0; mt < 4; mt++)
#pragma unroll
                for (int nt = 0; nt < 4; nt++)
                    MMA_F16(acc[mt][nt], af[mt][0], af[mt][1], af[mt][2], af[mt][3],
                            bf[nt][0], bf[nt][1]);
        }
    }

#pragma unroll
    for (int mt = 0; mt < 4; mt++) {
        const int row0 = bm + wm0 + mt * 16 + gr;
#pragma unroll
        for (int nt = 0; nt < 4; nt++) {
            const int col = bn + wn0 + nt * 8 + tc * 2;
            if (col >= N) continue;
            TOut* dst;
            size_t idx;
            int ld;
            if (col < nsplit) { dst = C;  ld = ldc;  idx = (size_t)row0*ldc  + col; }
            else              { dst = C2; ld = ldc2; idx = (size_t)row0*ldc2 + (col - nsplit); }
            const size_t idx2 = idx + (size_t)8 * ld;
            if constexpr (sizeof(TOut) == 4) {
                *(float2*)&((float*)dst)[idx]  = make_float2(acc[mt][nt][0], acc[mt][nt][1]);
                *(float2*)&((float*)dst)[idx2] = make_float2(acc[mt][nt][2], acc[mt][nt][3]);
            } else {
                *(__half2*)&((__half*)dst)[idx]  = __floats2half2_rn(acc[mt][nt][0], acc[mt][nt][1]);
                *(__half2*)&((__half*)dst)[idx2] = __floats2half2_rn(acc[mt][nt][2], acc[mt][nt][3]);
            }
        }
    }
}

// ---------------- RMSNorm: half in -> half out (fp32 accumulation) ----------------
__global__ void rmsnorm_hh_kernel(const __half* __restrict__ x, const float* __restrict__ w,
                                  __half* __restrict__ dst, int W, int ldin)
{
    __shared__ float red[256];
    const int row = blockIdx.x;
    const __half* p = x + (size_t)row*ldin;
    float ss = 0.f;
    for (int c = threadIdx.x; c < W/2; c += 256) {
        float2 v = __half22float2(((const __half2*)p)[c]);
        ss += v.x*v.x + v.y*v.y;
    }
    red[threadIdx.x] = ss;
    __syncthreads();
    for (int s = 128; s; s >>= 1) {
        if (threadIdx.x < s) red[threadIdx.x] += red[threadIdx.x + s];
        __syncthreads();
    }
    const float scale = rsqrtf(red[0] / (float)W + 1e-6f);
    __half* d = dst + (size_t)row*W;
    for (int c = threadIdx.x; c < W; c += 256)
        d[c] = __float2half_rn(__half2float(p[c]) * scale * w[c]);
}

// ---------------- RoPE ----------------
__global__ void rope_k_h_kernel(const __half* __restrict__ ckvall, __half* __restrict__ kpeh)
{
    const int row = blockIdx.x;
    const int lane = threadIdx.x & 31;
    const __half* base = ckvall + (size_t)row*CKV_LD + KVLORA;
    float xe = __half2float(base[2*lane]), xo = __half2float(base[2*lane + 1]);
    float inv = 1.0f / powf(10000.0f, (2.0f * (float)lane) / 64.0f);
    float ph = (float)(row % S_LEN) * inv;
    float sn, cs;
    sincosf(ph, &sn, &cs);
    kpeh[(size_t)row*DROPE + lane]      = __float2half_rn(xe*cs - xo*sn);
    kpeh[(size_t)row*DROPE + lane + 32] = __float2half_rn(xo*cs + xe*sn);
}

__global__ void rope_q_h_kernel(__half* __restrict__ q)
{
    const int row = blockIdx.x;
    const int h = threadIdx.x >> 5, lane = threadIdx.x & 31;
    __half* base = q + (size_t)row*Q_LD + h*DQ + DNOPE;
    float xe = __half2float(base[2*lane]), xo = __half2float(base[2*lane + 1]);
    float inv = 1.0f / powf(10000.0f, (2.0f * (float)lane) / 64.0f);
    float ph = (float)(row % S_LEN) * inv;
    float sn, cs;
    sincosf(ph, &sn, &cs);
    __syncwarp();
    base[lane]      = __float2half_rn(xe*cs - xo*sn);
    base[lane + 32] = __float2half_rn(xo*cs + xe*sn);
}

// ---------------- all-fp16 tensor-core causal flash attention ----------------
#define FQH 200
#define FVH 40
#define FPH 40
#define BR 128
#define BC 32
#define FLASH_SMEM ((BR*FQH + 2*BC*FQH + 2*DV*FVH + BR*FPH)*2)

__global__ __launch_bounds__(256, 2) void flash_h_kernel(
    const __half* __restrict__ q, const __half* __restrict__ kvh,
    const __half* __restrict__ vT, const __half* __restrict__ kpeh,
    __half* __restrict__ attn)
{
    extern __shared__ __half smh[];
    __half* Qs = smh;                     // BR x FQH
    __half* Ks = Qs + BR*FQH;             // 2 x BC x FQH
    __half* Vt = Ks + 2*BC*FQH;           // 2 x DV x FVH
    __half* Ps = Vt + 2*DV*FVH;           // BR x FPH

    const int tid  = threadIdx.x;
    const int lane = tid & 31;
    const int warp = tid >> 5;
    const int gr   = lane >> 2;
    const int tc   = lane & 3;
    const int qt = (gridDim.x - 1) - blockIdx.x;
    const int b  = blockIdx.y >> 4;
    const int h  = blockIdx.y & 15;
    const float scale = 0.07216878364870323f; // 1/sqrt(192)

    const int qrow0 = b*S_LEN + qt*BR;
    const int wr0   = warp * 16;

    uint32_t ksm[2], vsm[2];
    ksm[0] = smem_u32(Ks);
    ksm[1] = smem_u32(Ks + BC*FQH);
    vsm[0] = smem_u32(Vt);
    vsm[1] = smem_u32(Vt + DV*FVH);

#pragma unroll
    for (int t = 0; t < 12; t++) {
        int idx = tid + t*256;
        int r = idx / 24, c = idx % 24;
        *(uint4*)&Qs[r*FQH + c*8] =
            *(const uint4*)(q + (size_t)(qrow0 + r)*Q_LD + h*DQ + c*8);
    }

    float m0 = -INFINITY, m1 = -INFINITY, l0 = 0.f, l1 = 0.f;
    float o[16][4];
#pragma unroll
    for (int nt = 0; nt < 16; nt++)
#pragma unroll
        for (int r = 0; r < 4; r++) o[nt][r] = 0.f;

    const int jmax = 4*qt + 3;

    auto issue_tile = [&](int j, int buf) {
        const int krow0 = b*S_LEN + j*BC;
#pragma unroll
        for (int t = 0; t < 3; t++) {
            int idx = tid + t*256;
            int r = idx / 24, col8 = (idx % 24) * 8;
            const __half* src = (col8 < DNOPE)
                ? kvh + (size_t)(krow0 + r)*KV_LD + h*256 + col8
                : kpeh + (size_t)(krow0 + r)*DROPE + (col8 - DNOPE);
            CP_ASYNC16(ksm[buf] + (uint32_t)(r*FQH + col8)*2, src);
        }
#pragma unroll
        for (int t = 0; t < 2; t++) {
            int idx = tid + t*256;
            int r = idx >> 2, c8 = (idx & 3) * 8;
            const __half* src = vT + (size_t)(h*DV + r)*NROWS + krow0 + c8;
            CP_ASYNC16(vsm[buf] + (uint32_t)(r*FVH + c8)*2, src);
        }
    };

    issue_tile(0, 0);
    CP_COMMIT();

    for (int j = 0; j <= jmax; j++) {
        __syncthreads();
        if (j + 1 <= jmax) issue_tile(j + 1, (j + 1) & 1);
        CP_COMMIT();
        CP_WAIT1();
        __syncthreads();

        const int off = j*BC - qt*BR;
        if (off > wr0 + 15) continue;
        const bool needMask = (off + BC - 1 > wr0);

        const __half* Ksb = Ks + (j & 1)*BC*FQH;
        const __half* Vtb = Vt + (j & 1)*DV*FVH;

        float accS[4][4];
#pragma unroll
        for (int nt = 0; nt < 4; nt++)
#pragma unroll
            for (int r = 0; r < 4; r++) accS[nt][r] = 0.f;

#pragma unroll
        for (int k = 0; k < 12; k++) {
            const int k0 = k * 16;
            uint32_t a0 = *(const uint32_t*)(Qs + (wr0 + gr)*FQH     + k0 + 2*tc);
            uint32_t a1 = *(const uint32_t*)(Qs + (wr0 + gr + 8)*FQH + k0 + 2*tc);
            uint32_t a2 = *(const uint32_t*)(Qs + (wr0 + gr)*FQH     + k0 + 8 + 2*tc);
            uint32_t a3 = *(const uint32_t*)(Qs + (wr0 + gr + 8)*FQH + k0 + 8 + 2*tc);
#pragma unroll
            for (int nt = 0; nt < 4; nt++) {
                uint32_t b0 = *(const uint32_t*)(Ksb + (nt*8 + gr)*FQH + k0 + 2*tc);
                uint32_t b1 = *(const uint32_t*)(Ksb + (nt*8 + gr)*FQH + k0 + 8 + 2*tc);
                MMA_F16(accS[nt], a0, a1, a2, a3, b0, b1);
            }
        }

        if (needMask) {
            const int r0 = wr0 + gr, r1 = r0 + 8;
#pragma unroll
            for (int nt = 0; nt < 4; nt++) {
                const int c0 = nt*8 + 2*tc + off;
                accS[nt][0] = (c0     <= r0) ? accS[nt][0]*scale : -INFINITY;
                accS[nt][1] = (c0 + 1 <= r0) ? accS[nt][1]*scale : -INFINITY;
                accS[nt][2] = (c0     <= r1) ? accS[nt][2]*scale : -INFINITY;
                accS[nt][3] = (c0 + 1 <= r1) ? accS[nt][3]*scale : -INFINITY;
            }
        } else {
#pragma unroll
            for (int nt = 0; nt < 4; nt++)
#pragma unroll
                for (int r = 0; r < 4; r++) accS[nt][r] *= scale;
        }

        float rm0 = -INFINITY, rm1 = -INFINITY;
#pragma unroll
        for (int nt = 0; nt < 4; nt++) {
            rm0 = fmaxf(rm0, fmaxf(accS[nt][0], accS[nt][1]));
            rm1 = fmaxf(rm1, fmaxf(accS[nt][2], accS[nt][3]));
        }
        rm0 = fmaxf(rm0, __shfl_xor_sync(0xffffffffu, rm0, 1));
        rm0 = fmaxf(rm0, __shfl_xor_sync(0xffffffffu, rm0, 2));
        rm1 = fmaxf(rm1, __shfl_xor_sync(0xffffffffu, rm1, 1));
        rm1 = fmaxf(rm1, __shfl_xor_sync(0xffffffffu, rm1, 2));

        const float mn0 = fmaxf(m0, rm0), mn1 = fmaxf(m1, rm1);
        const float al0 = __expf(m0 - mn0), al1 = __expf(m1 - mn1);
        m0 = mn0; m1 = mn1;

        float rs0 = 0.f, rs1 = 0.f;
#pragma unroll
        for (int nt = 0; nt < 4; nt++) {
            float p0 = __expf(accS[nt][0] - mn0);
            float p1 = __expf(accS[nt][1] - mn0);
            float p2 = __expf(accS[nt][2] - mn1);
            float p3 = __expf(accS[nt][3] - mn1);
            rs0 += p0 + p1; rs1 += p2 + p3;
            const int c0 = nt*8 + 2*tc;
            *(__half2*)&Ps[(wr0 + gr)*FPH + c0]     = __floats2half2_rn(p0, p1);
            *(__half2*)&Ps[(wr0 + gr + 8)*FPH + c0] = __floats2half2_rn(p2, p3);
        }
        rs0 += __shfl_xor_sync(0xffffffffu, rs0, 1);
        rs0 += __shfl_xor_sync(0xffffffffu, rs0, 2);
        rs1 += __shfl_xor_sync(0xffffffffu, rs1, 1);
        rs1 += __shfl_xor_sync(0xffffffffu, rs1, 2);
        l0 = l0*al0 + rs0;
        l1 = l1*al1 + rs1;

#pragma unroll
        for (int nt = 0; nt < 16; nt++) {
            o[nt][0] *= al0; o[nt][1] *= al0;
            o[nt][2] *= al1; o[nt][3] *= al1;
        }
        __syncwarp();

#pragma unroll
        for (int k = 0; k < 2; k++) {
            const int k0 = k * 16;
            uint32_t a0 = *(const uint32_t*)(Ps + (wr0 + gr)*FPH     + k0 + 2*tc);
            uint32_t a1 = *(const uint32_t*)(Ps + (wr0 + gr + 8)*FPH + k0 + 2*tc);
            uint32_t a2 = *(const uint32_t*)(Ps + (wr0 + gr)*FPH     + k0 + 8 + 2*tc);
            uint32_t a3 = *(const uint32_t*)(Ps + (wr0 + gr + 8)*FPH + k0 + 8 + 2*tc);
#pragma unroll
            for (int nt = 0; nt < 16; nt++) {
                uint32_t b0 = *(const uint32_t*)(Vtb + (nt*8 + gr)*FVH + k0 + 2*tc);
                uint32_t b1 = *(const uint32_t*)(Vtb + (nt*8 + gr)*FVH + k0 + 8 + 2*tc);
                MMA_F16(o[nt], a0, a1, a2, a3, b0, b1);
            }
        }
    }

    const float il0 = 1.0f / l0, il1 = 1.0f / l1;
    const int row0 = qrow0 + wr0 + gr;
#pragma unroll
    for (int nt = 0; nt < 16; nt++) {
        const int col = h*DV + nt*8 + 2*tc;
        *(__half2*)&attn[(size_t)row0*ATTN_LD + col] =
            __floats2half2_rn(o[nt][0]*il0, o[nt][1]*il0);
        *(__half2*)&attn[(size_t)(row0 + 8)*ATTN_LD + col] =
            __floats2half2_rn(o[nt][2]*il1, o[nt][3]*il1);
    }
}

// ---------------- launch ----------------
extern "C" void kernel_launch(void* const* d_in, const int* in_sizes, int n_in,
                              void* d_out, int out_size)
{
    const float* hid    = (const float*)d_in[0];
    const float* w_dq   = (const float*)d_in[1];
    const float* q_ln   = (const float*)d_in[2];
    const float* w_uq   = (const float*)d_in[3];
    const float* kv_a_w = (const float*)d_in[4];
    const float* kv_ln  = (const float*)d_in[5];
    const float* kv_b_w = (const float*)d_in[6];
    const float* o_w    = (const float*)d_in[7];
    float* out = (float*)d_out;

    __half *hidh, *qaraw, *ckvall, *qah, *ckvh, *qh, *kvh, *vTh, *kpeh, *attnh;
    __half *wAT, *wuqT, *kvbT, *owT;
    cudaGetSymbolAddress((void**)&hidh,  g_hidh);
    cudaGetSymbolAddress((void**)&qaraw, g_qaraw);
    cudaGetSymbolAddress((void**)&ckvall,g_ckvall);
    cudaGetSymbolAddress((void**)&qah,   g_qah);
    cudaGetSymbolAddress((void**)&ckvh,  g_ckvh);
    cudaGetSymbolAddress((void**)&qh,    g_qh);
    cudaGetSymbolAddress((void**)&kvh,   g_kvh);
    cudaGetSymbolAddress((void**)&vTh,   g_vTh);
    cudaGetSymbolAddress((void**)&kpeh,  g_kpeh);
    cudaGetSymbolAddress((void**)&attnh, g_attnh);
    cudaGetSymbolAddress((void**)&wAT,   g_wAT);
    cudaGetSymbolAddress((void**)&wuqT,  g_wuqT);
    cudaGetSymbolAddress((void**)&kvbT,  g_kvbT);
    cudaGetSymbolAddress((void**)&owT,   g_owT);

    cudaFuncSetAttribute(flash_h_kernel, cudaFuncAttributeMaxDynamicSharedMemorySize, FLASH_SMEM);
    cudaFuncSetAttribute(h16_gemm<float>, cudaFuncAttributeMaxDynamicSharedMemorySize, H_SMEM);
    cudaFuncSetAttribute(h16_gemm<__half>, cudaFuncAttributeMaxDynamicSharedMemorySize, H_SMEM);

    // pre-pass: hidden -> half; all weight transposes fused in one launch
    f2h_kernel<<<(NROWS*HIDDEN/4 + 255)/256, 256>>>(hid, hidh, NROWS*HIDDEN/4);
    {
        TJob j0 = { w_dq,   wAT,                          HIDDEN, QLORA,  0 };
        int t0 = (HIDDEN/64)*(QLORA/32);
        TJob j1 = { kv_a_w, wAT + (size_t)QLORA*HIDDEN,   HIDDEN, CKV_LD, t0 };
        int t1 = t0 + (HIDDEN/64)*(CKV_LD/32);
        TJob j2 = { w_uq,   wuqT,                         QLORA,  Q_LD,   t1 };
        int t2 = t1 + (QLORA/64)*(Q_LD/32);
        TJob j3 = { kv_b_w, kvbT,                         KVLORA, KV_LD,  t2 };
        int t3 = t2 + (KVLORA/64)*(KV_LD/32);
        TJob j4 = { o_w,    owT,                          ATTN_LD, HIDDEN, t3 };
        int t4 = t3 + (ATTN_LD/64)*(HIDDEN/32);
        transpose5_kernel<<<t4, 256>>>(j0, j1, j2, j3, j4);
    }

    // fused [q_a | ckv_pe] = hidden @ [w_dq | kv_a_w]   [4096, 2112] k=2048 (half out, split)
    h16_gemm<__half><<<dim3((NFUSE+127)/128, NROWS/128), 256, H_SMEM>>>(
        hidh, wAT, qaraw, NROWS, NFUSE, HIDDEN, QLORA, ckvall, CKV_LD, QLORA);
    // RMSNorms (half in, half out)
    rmsnorm_hh_kernel<<<NROWS, 256>>>(qaraw,  q_ln,  qah,  QLORA,  QLORA);
    rmsnorm_hh_kernel<<<NROWS, 256>>>(ckvall, kv_ln, ckvh, KVLORA, CKV_LD);
    // RoPE k_pe: ckvall half -> kpeh half
    rope_k_h_kernel<<<NROWS, 32>>>(ckvall, kpeh);
    // q = q_a_ln @ w_uq          [4096,3072] k=1536 (half out)
    h16_gemm<__half><<<dim3(Q_LD/128, NROWS/128), 256, H_SMEM>>>(
        qah, wuqT, qh, NROWS, Q_LD, QLORA, Q_LD, (__half*)nullptr, 0, 1<<30);
    // RoPE q_pe in place on half q
    rope_q_h_kernel<<<NROWS, 512>>>(qh);
    // kv = ckv_ln @ kv_b_w       [4096,4096] k=512 (half out)
    h16_gemm<__half><<<dim3(KV_LD/128, NROWS/128), 256, H_SMEM>>>(
        ckvh, kvbT, kvh, NROWS, KV_LD, KVLORA, KV_LD, (__half*)nullptr, 0, 1<<30);
    // V transpose: kvh -> vT[h][dv][row]
    vtrans_kernel<<<dim3(NROWS/32, NH*4), dim3(32,8)>>>(kvh, vTh);
    // all-fp16 causal flash attention -> attnh
    flash_h_kernel<<<dim3(S_LEN/BR, BATCH*NH), 256, FLASH_SMEM>>>(qh, kvh, vTh, kpeh, attnh);
    // out = attn @ o_w           [4096,2048] k=2048 (fp32 out)
    h16_gemm<float><<<dim3(HIDDEN/128, NROWS/128), 256, H_SMEM>>>(
        attnh, owT, out, NROWS, HIDDEN, ATTN_LD, HIDDEN, (float*)nullptr, 0, 1<<30);
}